// round 1
// baseline (speedup 1.0000x reference)
#include <cuda_runtime.h>
#include <math.h>

#define D      128
#define NROWS  200000
#define KPOW   10

#define K1_ROWS   128
#define NTHREADS  512
#define XS_STRIDE 132
#define WS_STRIDE 132
#define K2_BLOCKS 148

// ---------------- scratch (device globals; no allocation in kernel_launch) ----
__device__ float g_q [(size_t)NROWS * D];   // row-softmax(x Wq^T + bq)
__device__ float g_ek[(size_t)NROWS * D];   // exp(x Wk^T + bk) (unnormalized col softmax)
__device__ float g_Z  [D];                  // column sums of g_ek
__device__ float g_kvU[D * D];              // ek^T @ x  (unnormalized)
__device__ float g_kqU[D * D];              // ek^T @ q  (unnormalized)
__device__ float g_kv [D * D];
__device__ float g_kq [D * D];
__device__ float g_M  [D * D];              // sum_i temp[i] * kv @ kq^{i-1}
__device__ float g_bufA[D * D];
__device__ float g_bufB[D * D];

// ---------------- helpers -----------------------------------------------------
__device__ __forceinline__ void fma4(float4& a, float s, const float4 b) {
    a.x = fmaf(s, b.x, a.x);
    a.y = fmaf(s, b.y, a.y);
    a.z = fmaf(s, b.z, a.z);
    a.w = fmaf(s, b.w, a.w);
}
__device__ __forceinline__ float4 zero4() { return make_float4(0.f, 0.f, 0.f, 0.f); }

// ---------------- K0: zero the accumulators -----------------------------------
__global__ void zero_kernel() {
    int i = blockIdx.x * blockDim.x + threadIdx.x;
    if (i < D) g_Z[i] = 0.f;
    for (int k = i; k < D * D; k += gridDim.x * blockDim.x) {
        g_kvU[k] = 0.f;
        g_kqU[k] = 0.f;
    }
}

// ---------------- K1: q = softmax_row(xWq^T+bq), ek = exp(xWk^T+bk), Z = colsum(ek)
// block: 512 threads, 128 rows. thread (l = t&7, r0 = t>>3) owns rows {r0, r0+64},
// columns {l*4+32k+i : k=0..3, i=0..3}. W stored transposed in smem (stride 132).
__global__ __launch_bounds__(NTHREADS, 1)
void k1_kernel(const float* __restrict__ x,  const float* __restrict__ Wq,
               const float* __restrict__ bq, const float* __restrict__ Wk,
               const float* __restrict__ bk) {
    extern __shared__ float sm[];
    float* wqs  = sm;                          // 128 * 132
    float* wks  = wqs + D * WS_STRIDE;         // 128 * 132
    float* xs   = wks + D * WS_STRIDE;         // 128 * 132
    float* scol = xs  + K1_ROWS * XS_STRIDE;   // 128

    const int tid  = threadIdx.x;
    const int l    = tid & 7;
    const int r0   = tid >> 3;                 // 0..63
    const int lane = tid & 31;
    const int row0 = blockIdx.x * K1_ROWS;

    // load W transposed: wqs[j*132 + c] = Wq[c*128 + j]
    for (int idx = tid; idx < D * D; idx += NTHREADS) {
        int c = idx >> 7, j = idx & 127;
        wqs[j * WS_STRIDE + c] = Wq[idx];
        wks[j * WS_STRIDE + c] = Wk[idx];
    }
    // load x tile (pad stride 132), zero OOB rows
    for (int f = tid; f < K1_ROWS * (D / 4); f += NTHREADS) {
        int rr = f >> 5, cc = f & 31;
        float4 v = zero4();
        if (row0 + rr < NROWS)
            v = *(const float4*)(x + (size_t)(row0 + rr) * D + cc * 4);
        *(float4*)&xs[rr * XS_STRIDE + cc * 4] = v;
    }
    if (tid < D) scol[tid] = 0.f;
    __syncthreads();

    float4 aq[2][4], ak[2][4];
    #pragma unroll
    for (int k = 0; k < 4; k++) {
        float4 b1 = *(const float4*)(bq + l * 4 + 32 * k);
        float4 b2 = *(const float4*)(bk + l * 4 + 32 * k);
        aq[0][k] = b1; aq[1][k] = b1;
        ak[0][k] = b2; ak[1][k] = b2;
    }

    #pragma unroll 4
    for (int j = 0; j < D; j++) {
        float x0 = xs[r0 * XS_STRIDE + j];
        float x1 = xs[(r0 + 64) * XS_STRIDE + j];
        int wb = j * WS_STRIDE + l * 4;
        #pragma unroll
        for (int k = 0; k < 4; k++) {
            float4 wq = *(const float4*)&wqs[wb + 32 * k];
            float4 wk2 = *(const float4*)&wks[wb + 32 * k];
            fma4(aq[0][k], x0, wq);  fma4(aq[1][k], x1, wq);
            fma4(ak[0][k], x0, wk2); fma4(ak[1][k], x1, wk2);
        }
    }

    const unsigned FULL = 0xffffffffu;

    // ---- q: row softmax (reduce across the row's 8 lanes: xor 1,2,4) ----
    #pragma unroll
    for (int rr2 = 0; rr2 < 2; rr2++) {
        int row = row0 + r0 + rr2 * 64;
        float m = -1e30f;
        #pragma unroll
        for (int k = 0; k < 4; k++) {
            float4 v = aq[rr2][k];
            m = fmaxf(m, fmaxf(fmaxf(v.x, v.y), fmaxf(v.z, v.w)));
        }
        m = fmaxf(m, __shfl_xor_sync(FULL, m, 1));
        m = fmaxf(m, __shfl_xor_sync(FULL, m, 2));
        m = fmaxf(m, __shfl_xor_sync(FULL, m, 4));
        float4 e[4];
        float s = 0.f;
        #pragma unroll
        for (int k = 0; k < 4; k++) {
            float4 v = aq[rr2][k];
            e[k].x = __expf(v.x - m); e[k].y = __expf(v.y - m);
            e[k].z = __expf(v.z - m); e[k].w = __expf(v.w - m);
            s += e[k].x + e[k].y + e[k].z + e[k].w;
        }
        s += __shfl_xor_sync(FULL, s, 1);
        s += __shfl_xor_sync(FULL, s, 2);
        s += __shfl_xor_sync(FULL, s, 4);
        float inv = 1.f / s;
        if (row < NROWS) {
            #pragma unroll
            for (int k = 0; k < 4; k++) {
                float4 o = make_float4(e[k].x * inv, e[k].y * inv, e[k].z * inv, e[k].w * inv);
                *(float4*)(g_q + (size_t)row * D + l * 4 + 32 * k) = o;
            }
        }
    }

    // ---- ek = exp(sk) (no max subtraction; |sk| <~ 3.3), column sums ----
    float4 cs[4] = {zero4(), zero4(), zero4(), zero4()};
    #pragma unroll
    for (int rr2 = 0; rr2 < 2; rr2++) {
        int row = row0 + r0 + rr2 * 64;
        bool act = row < NROWS;
        #pragma unroll
        for (int k = 0; k < 4; k++) {
            float4 v = ak[rr2][k];
            float4 e = make_float4(__expf(v.x), __expf(v.y), __expf(v.z), __expf(v.w));
            if (act) {
                *(float4*)(g_ek + (size_t)row * D + l * 4 + 32 * k) = e;
                cs[k].x += e.x; cs[k].y += e.y; cs[k].z += e.z; cs[k].w += e.w;
            }
        }
    }
    // reduce over the warp's 4 r0-groups (xor 8, 16), lanes 0..7 commit
    #pragma unroll
    for (int k = 0; k < 4; k++) {
        float v0 = cs[k].x, v1 = cs[k].y, v2 = cs[k].z, v3 = cs[k].w;
        v0 += __shfl_xor_sync(FULL, v0, 8);  v0 += __shfl_xor_sync(FULL, v0, 16);
        v1 += __shfl_xor_sync(FULL, v1, 8);  v1 += __shfl_xor_sync(FULL, v1, 16);
        v2 += __shfl_xor_sync(FULL, v2, 8);  v2 += __shfl_xor_sync(FULL, v2, 16);
        v3 += __shfl_xor_sync(FULL, v3, 8);  v3 += __shfl_xor_sync(FULL, v3, 16);
        if (lane < 8) {
            int c = l * 4 + 32 * k;
            atomicAdd(&scol[c + 0], v0);
            atomicAdd(&scol[c + 1], v1);
            atomicAdd(&scol[c + 2], v2);
            atomicAdd(&scol[c + 3], v3);
        }
    }
    __syncthreads();
    if (tid < D) atomicAdd(&g_Z[tid], scol[tid]);
}

// ---------------- K2: kvU = ek^T @ x, kqU = ek^T @ q (split over N, atomic combine)
__global__ __launch_bounds__(NTHREADS, 1)
void k2_kernel(const float* __restrict__ x) {
    const int t = threadIdx.x;
    const int w = t >> 5, l = t & 31;
    const int d0 = w * 8;

    const size_t chunk = (NROWS + K2_BLOCKS - 1) / K2_BLOCKS;
    size_t start = (size_t)blockIdx.x * chunk;
    size_t end = start + chunk;
    if (end > (size_t)NROWS) end = NROWS;

    float4 ax[8], aq[8];
    #pragma unroll
    for (int i = 0; i < 8; i++) { ax[i] = zero4(); aq[i] = zero4(); }

    #pragma unroll 2
    for (size_t n = start; n < end; n++) {
        const float* ekp = g_ek + n * D + d0;
        float4 e0 = *(const float4*)(ekp);
        float4 e1 = *(const float4*)(ekp + 4);
        float4 xv = *(const float4*)(x   + n * D + l * 4);
        float4 qv = *(const float4*)(g_q + n * D + l * 4);
        float ee[8] = {e0.x, e0.y, e0.z, e0.w, e1.x, e1.y, e1.z, e1.w};
        #pragma unroll
        for (int i = 0; i < 8; i++) {
            fma4(ax[i], ee[i], xv);
            fma4(aq[i], ee[i], qv);
        }
    }

    #pragma unroll
    for (int i = 0; i < 8; i++) {
        int base = (d0 + i) * D + l * 4;
        atomicAdd(&g_kvU[base + 0], ax[i].x);
        atomicAdd(&g_kvU[base + 1], ax[i].y);
        atomicAdd(&g_kvU[base + 2], ax[i].z);
        atomicAdd(&g_kvU[base + 3], ax[i].w);
        atomicAdd(&g_kqU[base + 0], aq[i].x);
        atomicAdd(&g_kqU[base + 1], aq[i].y);
        atomicAdd(&g_kqU[base + 2], aq[i].z);
        atomicAdd(&g_kqU[base + 3], aq[i].w);
    }
}

// ---------------- K3: normalize by column sums --------------------------------
__global__ void norm_kernel() {
    int i = blockIdx.x * blockDim.x + threadIdx.x;
    if (i < D * D) {
        float inv = 1.f / g_Z[i >> 7];
        g_kv[i] = g_kvU[i] * inv;
        g_kq[i] = g_kqU[i] * inv;
    }
}

// ---------------- Kstep: B = A @ kq ; M (+)= temp[step] * A -------------------
__global__ void kstep_kernel(const float* __restrict__ temp, int step) {
    const float* A;
    float* B;
    if (step == 1)      { A = g_kv;   B = g_bufA; }
    else if (step & 1)  { A = g_bufB; B = g_bufA; }
    else                { A = g_bufA; B = g_bufB; }

    __shared__ float sA[D];
    int b = blockIdx.x, c = threadIdx.x;
    sA[c] = A[b * D + c];
    __syncthreads();

    float acc = 0.f;
    #pragma unroll 8
    for (int j = 0; j < D; j++) acc = fmaf(sA[j], g_kq[j * D + c], acc);
    B[b * D + c] = acc;

    float mv = temp[step] * sA[c];
    if (step == 1) g_M[b * D + c] = mv;
    else           g_M[b * D + c] += mv;
}

// ---------------- K4: out = temp[0]*x + q @ M ---------------------------------
__global__ __launch_bounds__(NTHREADS, 1)
void k4_kernel(const float* __restrict__ x, const float* __restrict__ temp,
               float* __restrict__ out) {
    extern __shared__ float sm[];
    float* Ms = sm;               // 128*128, row-major (conflict-free via interleaved chunks)
    float* qs = Ms + D * D;       // 128*132

    const int tid  = threadIdx.x;
    const int l    = tid & 7;
    const int r0   = tid >> 3;
    const int row0 = blockIdx.x * K1_ROWS;

    for (int f = tid; f < D * D / 4; f += NTHREADS)
        ((float4*)Ms)[f] = ((const float4*)g_M)[f];
    for (int f = tid; f < K1_ROWS * (D / 4); f += NTHREADS) {
        int rr = f >> 5, cc = f & 31;
        float4 v = zero4();
        if (row0 + rr < NROWS)
            v = *(const float4*)(g_q + (size_t)(row0 + rr) * D + cc * 4);
        *(float4*)&qs[rr * XS_STRIDE + cc * 4] = v;
    }
    __syncthreads();

    float4 acc[2][4];
    #pragma unroll
    for (int r = 0; r < 2; r++)
        #pragma unroll
        for (int k = 0; k < 4; k++) acc[r][k] = zero4();

    #pragma unroll 4
    for (int j = 0; j < D; j++) {
        float q0 = qs[r0 * XS_STRIDE + j];
        float q1 = qs[(r0 + 64) * XS_STRIDE + j];
        int mb = j * D + l * 4;
        #pragma unroll
        for (int k = 0; k < 4; k++) {
            float4 m4 = *(const float4*)&Ms[mb + 32 * k];
            fma4(acc[0][k], q0, m4);
            fma4(acc[1][k], q1, m4);
        }
    }

    float t0 = temp[0];
    #pragma unroll
    for (int rr2 = 0; rr2 < 2; rr2++) {
        int row = row0 + r0 + rr2 * 64;
        if (row < NROWS) {
            #pragma unroll
            for (int k = 0; k < 4; k++) {
                const float4 xv = *(const float4*)(x + (size_t)row * D + l * 4 + 32 * k);
                float4 a = acc[rr2][k];
                float4 o = make_float4(fmaf(t0, xv.x, a.x), fmaf(t0, xv.y, a.y),
                                       fmaf(t0, xv.z, a.z), fmaf(t0, xv.w, a.w));
                *(float4*)(out + (size_t)row * D + l * 4 + 32 * k) = o;
            }
        }
    }
}

// ---------------- launch -------------------------------------------------------
extern "C" void kernel_launch(void* const* d_in, const int* in_sizes, int n_in,
                              void* d_out, int out_size) {
    const float* x    = (const float*)d_in[0];
    const float* Wq   = (const float*)d_in[1];
    const float* bq   = (const float*)d_in[2];
    const float* Wk   = (const float*)d_in[3];
    const float* bk   = (const float*)d_in[4];
    const float* temp = (const float*)d_in[5];
    float* out = (float*)d_out;

    const int smem1 = (2 * D * WS_STRIDE + K1_ROWS * XS_STRIDE + D) * (int)sizeof(float);
    const int smem4 = (D * D + K1_ROWS * XS_STRIDE) * (int)sizeof(float);
    cudaFuncSetAttribute(k1_kernel, cudaFuncAttributeMaxDynamicSharedMemorySize, smem1);
    cudaFuncSetAttribute(k4_kernel, cudaFuncAttributeMaxDynamicSharedMemorySize, smem4);

    const int nblk = (NROWS + K1_ROWS - 1) / K1_ROWS;   // 1563

    zero_kernel<<<64, 256>>>();
    k1_kernel<<<nblk, NTHREADS, smem1>>>(x, Wq, bq, Wk, bk);
    k2_kernel<<<K2_BLOCKS, NTHREADS>>>(x);
    norm_kernel<<<(D * D + 511) / 512, 512>>>();
    for (int s = 1; s <= KPOW; s++)
        kstep_kernel<<<D, D>>>(temp, s);
    k4_kernel<<<nblk, NTHREADS, smem4>>>(x, temp, out);
}

// round 2
// speedup vs baseline: 1.0529x; 1.0529x over previous
#include <cuda_runtime.h>
#include <math.h>

#define D      128
#define NROWS  200000
#define KPOW   10

#define K1_ROWS   128
#define NTHREADS  512
#define XS_STRIDE 132
#define WS_STRIDE 132
#define K2_BLOCKS 148

typedef unsigned long long u64;

// ---------------- scratch (device globals; no allocation in kernel_launch) ----
__device__ float g_q [(size_t)NROWS * D];   // row-softmax(x Wq^T + bq)
__device__ float g_ek[(size_t)NROWS * D];   // exp(x Wk^T + bk) (unnormalized col softmax)
__device__ float g_Z  [D];                  // column sums of g_ek
__device__ float g_kvU[D * D];              // ek^T @ x  (unnormalized)
__device__ float g_kqU[D * D];              // ek^T @ q  (unnormalized)
__device__ float g_kv [D * D];
__device__ float g_kq [D * D];
__device__ float g_M  [D * D];              // sum_i temp[i] * kv @ kq^{i-1}
__device__ float g_bufA[D * D];
__device__ float g_bufB[D * D];

// ---------------- packed f32x2 helpers ----------------------------------------
__device__ __forceinline__ u64 pack2(float lo, float hi) {
    u64 r; asm("mov.b64 %0, {%1, %2};" : "=l"(r) : "f"(lo), "f"(hi)); return r;
}
__device__ __forceinline__ float2 up2(u64 v) {
    float2 r; asm("mov.b64 {%0, %1}, %2;" : "=f"(r.x), "=f"(r.y) : "l"(v)); return r;
}
__device__ __forceinline__ u64 fma2(u64 a, u64 b, u64 c) {
    u64 d; asm("fma.rn.f32x2 %0, %1, %2, %3;" : "=l"(d) : "l"(a), "l"(b), "l"(c)); return d;
}
__device__ __forceinline__ void fma4(float4& a, float s, const float4 b) {
    a.x = fmaf(s, b.x, a.x); a.y = fmaf(s, b.y, a.y);
    a.z = fmaf(s, b.z, a.z); a.w = fmaf(s, b.w, a.w);
}
__device__ __forceinline__ float4 zero4() { return make_float4(0.f, 0.f, 0.f, 0.f); }

// ---------------- K0: zero the accumulators -----------------------------------
__global__ void zero_kernel() {
    int i = blockIdx.x * blockDim.x + threadIdx.x;
    if (i < D) g_Z[i] = 0.f;
    for (int k = i; k < D * D; k += gridDim.x * blockDim.x) {
        g_kvU[k] = 0.f;
        g_kqU[k] = 0.f;
    }
}

// ---------------- K1: q = softmax_row(xWq^T+bq), ek = exp(xWk^T+bk), Z = colsum(ek)
// block: 512 threads, 128 rows. thread (l = t&7, r0 = t>>3) owns rows {r0, r0+64},
// columns {l*4+32k+i}. Inner product fully in packed f32x2 FMA.
__global__ __launch_bounds__(NTHREADS, 1)
void k1_kernel(const float* __restrict__ x,  const float* __restrict__ Wq,
               const float* __restrict__ bq, const float* __restrict__ Wk,
               const float* __restrict__ bk) {
    extern __shared__ float sm[];
    float* wqs  = sm;                          // 128 * 132
    float* wks  = wqs + D * WS_STRIDE;         // 128 * 132
    float* xs   = wks + D * WS_STRIDE;         // 128 * 132
    float* scol = xs  + K1_ROWS * XS_STRIDE;   // 128

    const int tid  = threadIdx.x;
    const int l    = tid & 7;
    const int r0   = tid >> 3;                 // 0..63
    const int lane = tid & 31;
    const int row0 = blockIdx.x * K1_ROWS;

    // load W transposed: wqs[j*132 + c] = Wq[c*128 + j]
    for (int idx = tid; idx < D * D; idx += NTHREADS) {
        int c = idx >> 7, j = idx & 127;
        wqs[j * WS_STRIDE + c] = Wq[idx];
        wks[j * WS_STRIDE + c] = Wk[idx];
    }
    // load x tile (pad stride 132), zero OOB rows
    for (int f = tid; f < K1_ROWS * (D / 4); f += NTHREADS) {
        int rr = f >> 5, cc = f & 31;
        float4 v = zero4();
        if (row0 + rr < NROWS)
            v = *(const float4*)(x + (size_t)(row0 + rr) * D + cc * 4);
        *(float4*)&xs[rr * XS_STRIDE + cc * 4] = v;
    }
    if (tid < D) scol[tid] = 0.f;
    __syncthreads();

    // accumulators: [row][8 packs of 2 cols] for q and k paths
    u64 aq2[2][8], ak2[2][8];
    #pragma unroll
    for (int k = 0; k < 4; k++) {
        ulonglong2 b1 = *(const ulonglong2*)(bq + l * 4 + 32 * k);
        ulonglong2 b2 = *(const ulonglong2*)(bk + l * 4 + 32 * k);
        aq2[0][2 * k] = b1.x; aq2[0][2 * k + 1] = b1.y;
        aq2[1][2 * k] = b1.x; aq2[1][2 * k + 1] = b1.y;
        ak2[0][2 * k] = b2.x; ak2[0][2 * k + 1] = b2.y;
        ak2[1][2 * k] = b2.x; ak2[1][2 * k + 1] = b2.y;
    }

    #pragma unroll 2
    for (int j = 0; j < D; j++) {
        float x0s = xs[r0 * XS_STRIDE + j];
        float x1s = xs[(r0 + 64) * XS_STRIDE + j];
        u64 x0 = pack2(x0s, x0s);
        u64 x1 = pack2(x1s, x1s);
        int wb = j * WS_STRIDE + l * 4;
        #pragma unroll
        for (int k = 0; k < 4; k++) {
            ulonglong2 wq = *(const ulonglong2*)&wqs[wb + 32 * k];
            ulonglong2 wk2 = *(const ulonglong2*)&wks[wb + 32 * k];
            aq2[0][2 * k]     = fma2(x0, wq.x,  aq2[0][2 * k]);
            aq2[0][2 * k + 1] = fma2(x0, wq.y,  aq2[0][2 * k + 1]);
            aq2[1][2 * k]     = fma2(x1, wq.x,  aq2[1][2 * k]);
            aq2[1][2 * k + 1] = fma2(x1, wq.y,  aq2[1][2 * k + 1]);
            ak2[0][2 * k]     = fma2(x0, wk2.x, ak2[0][2 * k]);
            ak2[0][2 * k + 1] = fma2(x0, wk2.y, ak2[0][2 * k + 1]);
            ak2[1][2 * k]     = fma2(x1, wk2.x, ak2[1][2 * k]);
            ak2[1][2 * k + 1] = fma2(x1, wk2.y, ak2[1][2 * k + 1]);
        }
    }

    const unsigned FULL = 0xffffffffu;

    // ---- q: row softmax; logits bounded (|.| <~ 3.5) so no max subtraction ----
    #pragma unroll
    for (int rr2 = 0; rr2 < 2; rr2++) {
        int row = row0 + r0 + rr2 * 64;
        float e[16];
        float s = 0.f;
        #pragma unroll
        for (int p = 0; p < 8; p++) {
            float2 v = up2(aq2[rr2][p]);
            e[2 * p]     = __expf(v.x);
            e[2 * p + 1] = __expf(v.y);
            s += e[2 * p] + e[2 * p + 1];
        }
        s += __shfl_xor_sync(FULL, s, 1);
        s += __shfl_xor_sync(FULL, s, 2);
        s += __shfl_xor_sync(FULL, s, 4);
        float inv = 1.f / s;
        if (row < NROWS) {
            #pragma unroll
            for (int k = 0; k < 4; k++) {
                float4 o = make_float4(e[4 * k] * inv, e[4 * k + 1] * inv,
                                       e[4 * k + 2] * inv, e[4 * k + 3] * inv);
                *(float4*)(g_q + (size_t)row * D + l * 4 + 32 * k) = o;
            }
        }
    }

    // ---- ek = exp(sk) (no max subtraction), column sums ----
    float cs[16];
    #pragma unroll
    for (int i = 0; i < 16; i++) cs[i] = 0.f;
    #pragma unroll
    for (int rr2 = 0; rr2 < 2; rr2++) {
        int row = row0 + r0 + rr2 * 64;
        bool act = row < NROWS;
        float e[16];
        #pragma unroll
        for (int p = 0; p < 8; p++) {
            float2 v = up2(ak2[rr2][p]);
            e[2 * p]     = __expf(v.x);
            e[2 * p + 1] = __expf(v.y);
        }
        if (act) {
            #pragma unroll
            for (int k = 0; k < 4; k++) {
                float4 o = make_float4(e[4 * k], e[4 * k + 1], e[4 * k + 2], e[4 * k + 3]);
                *(float4*)(g_ek + (size_t)row * D + l * 4 + 32 * k) = o;
            }
            #pragma unroll
            for (int i = 0; i < 16; i++) cs[i] += e[i];
        }
    }
    // reduce over the warp's 4 r0-groups (xor 8, 16), lanes 0..7 commit
    #pragma unroll
    for (int k = 0; k < 4; k++) {
        float v0 = cs[4 * k], v1 = cs[4 * k + 1], v2 = cs[4 * k + 2], v3 = cs[4 * k + 3];
        v0 += __shfl_xor_sync(FULL, v0, 8);  v0 += __shfl_xor_sync(FULL, v0, 16);
        v1 += __shfl_xor_sync(FULL, v1, 8);  v1 += __shfl_xor_sync(FULL, v1, 16);
        v2 += __shfl_xor_sync(FULL, v2, 8);  v2 += __shfl_xor_sync(FULL, v2, 16);
        v3 += __shfl_xor_sync(FULL, v3, 8);  v3 += __shfl_xor_sync(FULL, v3, 16);
        if (lane < 8) {
            int c = l * 4 + 32 * k;
            atomicAdd(&scol[c + 0], v0);
            atomicAdd(&scol[c + 1], v1);
            atomicAdd(&scol[c + 2], v2);
            atomicAdd(&scol[c + 3], v3);
        }
    }
    __syncthreads();
    if (tid < D) atomicAdd(&g_Z[tid], scol[tid]);
}

// ---------------- K2: kvU = ek^T @ x, kqU = ek^T @ q (split over N, atomic combine)
__global__ __launch_bounds__(NTHREADS, 1)
void k2_kernel(const float* __restrict__ x) {
    const int t = threadIdx.x;
    const int w = t >> 5, l = t & 31;
    const int d0 = w * 8;

    const size_t chunk = (NROWS + K2_BLOCKS - 1) / K2_BLOCKS;
    size_t start = (size_t)blockIdx.x * chunk;
    size_t end = start + chunk;
    if (end > (size_t)NROWS) end = NROWS;

    u64 ax2[8][2], aq2[8][2];
    #pragma unroll
    for (int i = 0; i < 8; i++) {
        ax2[i][0] = 0ull; ax2[i][1] = 0ull;
        aq2[i][0] = 0ull; aq2[i][1] = 0ull;
    }

    #pragma unroll 2
    for (size_t n = start; n < end; n++) {
        const float* ekp = g_ek + n * D + d0;
        float4 e0 = *(const float4*)(ekp);
        float4 e1 = *(const float4*)(ekp + 4);
        ulonglong2 xv = *(const ulonglong2*)(x   + n * D + l * 4);
        ulonglong2 qv = *(const ulonglong2*)(g_q + n * D + l * 4);
        float ee[8] = {e0.x, e0.y, e0.z, e0.w, e1.x, e1.y, e1.z, e1.w};
        #pragma unroll
        for (int i = 0; i < 8; i++) {
            u64 eb = pack2(ee[i], ee[i]);
            ax2[i][0] = fma2(eb, xv.x, ax2[i][0]);
            ax2[i][1] = fma2(eb, xv.y, ax2[i][1]);
            aq2[i][0] = fma2(eb, qv.x, aq2[i][0]);
            aq2[i][1] = fma2(eb, qv.y, aq2[i][1]);
        }
    }

    #pragma unroll
    for (int i = 0; i < 8; i++) {
        int base = (d0 + i) * D + l * 4;
        float2 a0 = up2(ax2[i][0]), a1 = up2(ax2[i][1]);
        float2 b0 = up2(aq2[i][0]), b1 = up2(aq2[i][1]);
        atomicAdd(&g_kvU[base + 0], a0.x);
        atomicAdd(&g_kvU[base + 1], a0.y);
        atomicAdd(&g_kvU[base + 2], a1.x);
        atomicAdd(&g_kvU[base + 3], a1.y);
        atomicAdd(&g_kqU[base + 0], b0.x);
        atomicAdd(&g_kqU[base + 1], b0.y);
        atomicAdd(&g_kqU[base + 2], b1.x);
        atomicAdd(&g_kqU[base + 3], b1.y);
    }
}

// ---------------- K3: normalize by column sums --------------------------------
__global__ void norm_kernel() {
    int i = blockIdx.x * blockDim.x + threadIdx.x;
    if (i < D * D) {
        float inv = 1.f / g_Z[i >> 7];
        g_kv[i] = g_kvU[i] * inv;
        g_kq[i] = g_kqU[i] * inv;
    }
}

// ---------------- Kstep: B = A @ kq ; M (+)= temp[step] * A -------------------
__global__ void kstep_kernel(const float* __restrict__ temp, int step) {
    const float* A;
    float* B;
    if (step == 1)      { A = g_kv;   B = g_bufA; }
    else if (step & 1)  { A = g_bufB; B = g_bufA; }
    else                { A = g_bufA; B = g_bufB; }

    __shared__ float sA[D];
    int b = blockIdx.x, c = threadIdx.x;
    sA[c] = A[b * D + c];
    __syncthreads();

    float acc = 0.f;
    #pragma unroll 8
    for (int j = 0; j < D; j++) acc = fmaf(sA[j], g_kq[j * D + c], acc);
    B[b * D + c] = acc;

    float mv = temp[step] * sA[c];
    if (step == 1) g_M[b * D + c] = mv;
    else           g_M[b * D + c] += mv;
}

// ---------------- K4: out = temp[0]*x + q @ M ---------------------------------
__global__ __launch_bounds__(NTHREADS, 1)
void k4_kernel(const float* __restrict__ x, const float* __restrict__ temp,
               float* __restrict__ out) {
    extern __shared__ float sm[];
    float* Ms = sm;               // 128*128 row-major
    float* qs = Ms + D * D;       // 128*132

    const int tid  = threadIdx.x;
    const int l    = tid & 7;
    const int r0   = tid >> 3;
    const int row0 = blockIdx.x * K1_ROWS;

    for (int f = tid; f < D * D / 4; f += NTHREADS)
        ((float4*)Ms)[f] = ((const float4*)g_M)[f];
    for (int f = tid; f < K1_ROWS * (D / 4); f += NTHREADS) {
        int rr = f >> 5, cc = f & 31;
        float4 v = zero4();
        if (row0 + rr < NROWS)
            v = *(const float4*)(g_q + (size_t)(row0 + rr) * D + cc * 4);
        *(float4*)&qs[rr * XS_STRIDE + cc * 4] = v;
    }
    __syncthreads();

    u64 acc2[2][8];
    #pragma unroll
    for (int r = 0; r < 2; r++)
        #pragma unroll
        for (int p = 0; p < 8; p++) acc2[r][p] = 0ull;

    #pragma unroll 2
    for (int j = 0; j < D; j++) {
        float q0s = qs[r0 * XS_STRIDE + j];
        float q1s = qs[(r0 + 64) * XS_STRIDE + j];
        u64 q0 = pack2(q0s, q0s);
        u64 q1 = pack2(q1s, q1s);
        int mb = j * D + l * 4;
        #pragma unroll
        for (int k = 0; k < 4; k++) {
            ulonglong2 m2 = *(const ulonglong2*)&Ms[mb + 32 * k];
            acc2[0][2 * k]     = fma2(q0, m2.x, acc2[0][2 * k]);
            acc2[0][2 * k + 1] = fma2(q0, m2.y, acc2[0][2 * k + 1]);
            acc2[1][2 * k]     = fma2(q1, m2.x, acc2[1][2 * k]);
            acc2[1][2 * k + 1] = fma2(q1, m2.y, acc2[1][2 * k + 1]);
        }
    }

    float t0 = temp[0];
    #pragma unroll
    for (int rr2 = 0; rr2 < 2; rr2++) {
        int row = row0 + r0 + rr2 * 64;
        if (row < NROWS) {
            #pragma unroll
            for (int k = 0; k < 4; k++) {
                const float4 xv = *(const float4*)(x + (size_t)row * D + l * 4 + 32 * k);
                float2 a = up2(acc2[rr2][2 * k]);
                float2 b = up2(acc2[rr2][2 * k + 1]);
                float4 o = make_float4(fmaf(t0, xv.x, a.x), fmaf(t0, xv.y, a.y),
                                       fmaf(t0, xv.z, b.x), fmaf(t0, xv.w, b.y));
                *(float4*)(out + (size_t)row * D + l * 4 + 32 * k) = o;
            }
        }
    }
}

// ---------------- launch -------------------------------------------------------
extern "C" void kernel_launch(void* const* d_in, const int* in_sizes, int n_in,
                              void* d_out, int out_size) {
    const float* x    = (const float*)d_in[0];
    const float* Wq   = (const float*)d_in[1];
    const float* bq   = (const float*)d_in[2];
    const float* Wk   = (const float*)d_in[3];
    const float* bk   = (const float*)d_in[4];
    const float* temp = (const float*)d_in[5];
    float* out = (float*)d_out;

    const int smem1 = (2 * D * WS_STRIDE + K1_ROWS * XS_STRIDE + D) * (int)sizeof(float);
    const int smem4 = (D * D + K1_ROWS * XS_STRIDE) * (int)sizeof(float);
    cudaFuncSetAttribute(k1_kernel, cudaFuncAttributeMaxDynamicSharedMemorySize, smem1);
    cudaFuncSetAttribute(k4_kernel, cudaFuncAttributeMaxDynamicSharedMemorySize, smem4);

    const int nblk = (NROWS + K1_ROWS - 1) / K1_ROWS;   // 1563

    zero_kernel<<<64, 256>>>();
    k1_kernel<<<nblk, NTHREADS, smem1>>>(x, Wq, bq, Wk, bk);
    k2_kernel<<<K2_BLOCKS, NTHREADS>>>(x);
    norm_kernel<<<(D * D + 511) / 512, 512>>>();
    for (int s = 1; s <= KPOW; s++)
        kstep_kernel<<<D, D>>>(temp, s);
    k4_kernel<<<nblk, NTHREADS, smem4>>>(x, temp, out);
}

// round 4
// speedup vs baseline: 1.4828x; 1.4083x over previous
#include <cuda_runtime.h>
#include <math.h>

#define D      128
#define NROWS  200000
#define KPOW   10

#define NTHREADS  512
#define XST 132          // x^T tile stride (K1)
#define WST 132          // W^T tile stride (K1)
#define EST 132          // K2 staging stride
#define QST 260          // q^T tile stride (K4), 256 rows + pad
#define K2_BLOCKS 148
#define K2_CHUNK  64

typedef unsigned long long u64;

// ---------------- scratch ------------------------------------------------------
__device__ float g_q [(size_t)NROWS * D];
__device__ float g_ek[(size_t)NROWS * D];
__device__ float g_Z  [D];
__device__ float g_kvU[D * D];
__device__ float g_kqU[D * D];
__device__ float g_kv [D * D];
__device__ float g_kq [D * D];
__device__ float g_M  [D * D];
__device__ float g_bufA[D * D];
__device__ float g_bufB[D * D];

// ---------------- packed f32x2 helpers ----------------------------------------
__device__ __forceinline__ u64 pack2(float lo, float hi) {
    u64 r; asm("mov.b64 %0, {%1, %2};" : "=l"(r) : "f"(lo), "f"(hi)); return r;
}
__device__ __forceinline__ float2 up2(u64 v) {
    float2 r; asm("mov.b64 {%0, %1}, %2;" : "=f"(r.x), "=f"(r.y) : "l"(v)); return r;
}
__device__ __forceinline__ u64 fma2(u64 a, u64 b, u64 c) {
    u64 d; asm("fma.rn.f32x2 %0, %1, %2, %3;" : "=l"(d) : "l"(a), "l"(b), "l"(c)); return d;
}
__device__ __forceinline__ float4 zero4() { return make_float4(0.f, 0.f, 0.f, 0.f); }

// ---------------- K0: zero the accumulators -----------------------------------
__global__ void zero_kernel() {
    int i = blockIdx.x * blockDim.x + threadIdx.x;
    if (i < D) g_Z[i] = 0.f;
    for (int k = i; k < D * D; k += gridDim.x * blockDim.x) {
        g_kvU[k] = 0.f;
        g_kqU[k] = 0.f;
    }
}

// ---------------- K1: q = softmax_row(xWq^T+bq), ek = exp(xWk^T+bk), Z += colsum
// 512 thr, 128 rows/block. warp w owns rows w*8..w*8+7; lane l owns cols l*4..l*4+3
// of BOTH the q and k outputs. All smem reads broadcast or warp-contiguous.
__global__ __launch_bounds__(NTHREADS, 1)
void k1_kernel(const float* __restrict__ x,  const float* __restrict__ Wq,
               const float* __restrict__ bq, const float* __restrict__ Wk,
               const float* __restrict__ bk) {
    extern __shared__ float sm[];
    float* wqs  = sm;                 // [j=128][WST]  (W^T)
    float* wks  = wqs + D * WST;
    float* xsT  = wks + D * WST;      // [j=128][XST]  (x^T: xsT[j][r] = x[row0+r][j])
    float* scol = xsT + D * XST;      // [128]

    const int tid  = threadIdx.x;
    const int w    = tid >> 5;
    const int lane = tid & 31;
    const int row0 = blockIdx.x * 128;

    // weights: read Wq[c*128+j] coalesced, write transposed
    for (int idx = tid; idx < D * D; idx += NTHREADS) {
        int c = idx >> 7, j = idx & 127;
        wqs[j * WST + c] = Wq[idx];
        wks[j * WST + c] = Wk[idx];
    }
    // x tile transposed; zero OOB rows
    for (int idx = tid; idx < 128 * 32; idx += NTHREADS) {
        int r = idx >> 5, c4 = (idx & 31) * 4;
        float4 v = zero4();
        if (row0 + r < NROWS)
            v = *(const float4*)(x + (size_t)(row0 + r) * D + c4);
        xsT[(c4 + 0) * XST + r] = v.x;
        xsT[(c4 + 1) * XST + r] = v.y;
        xsT[(c4 + 2) * XST + r] = v.z;
        xsT[(c4 + 3) * XST + r] = v.w;
    }
    if (tid < D) scol[tid] = 0.f;
    __syncthreads();

    // accumulators: 8 rows x (2 packed q + 2 packed k)
    u64 aq[8][2], ak[8][2];
    {
        float4 b1 = *(const float4*)(bq + lane * 4);
        float4 b2 = *(const float4*)(bk + lane * 4);
        u64 q0 = pack2(b1.x, b1.y), q1 = pack2(b1.z, b1.w);
        u64 k0 = pack2(b2.x, b2.y), k1v = pack2(b2.z, b2.w);
        #pragma unroll
        for (int r = 0; r < 8; r++) {
            aq[r][0] = q0; aq[r][1] = q1;
            ak[r][0] = k0; ak[r][1] = k1v;
        }
    }

    #pragma unroll 4
    for (int j = 0; j < D; j++) {
        float4 xa = *(const float4*)&xsT[j * XST + w * 8];      // broadcast
        float4 xb = *(const float4*)&xsT[j * XST + w * 8 + 4];  // broadcast
        ulonglong2 wq2 = *(const ulonglong2*)&wqs[j * WST + lane * 4];
        ulonglong2 wk2 = *(const ulonglong2*)&wks[j * WST + lane * 4];
        float xr[8] = {xa.x, xa.y, xa.z, xa.w, xb.x, xb.y, xb.z, xb.w};
        #pragma unroll
        for (int r = 0; r < 8; r++) {
            u64 xd = pack2(xr[r], xr[r]);
            aq[r][0] = fma2(xd, wq2.x, aq[r][0]);
            aq[r][1] = fma2(xd, wq2.y, aq[r][1]);
            ak[r][0] = fma2(xd, wk2.x, ak[r][0]);
            ak[r][1] = fma2(xd, wk2.y, ak[r][1]);
        }
    }

    const unsigned FULL = 0xffffffffu;

    // ---- q rows: softmax without max-subtraction (logits bounded ~|3.5|) ----
    float cs0 = 0.f, cs1 = 0.f, cs2 = 0.f, cs3 = 0.f;
    #pragma unroll
    for (int r = 0; r < 8; r++) {
        int row = row0 + w * 8 + r;
        bool act = row < NROWS;

        float2 v0 = up2(aq[r][0]), v1 = up2(aq[r][1]);
        float e0 = __expf(v0.x), e1 = __expf(v0.y);
        float e2 = __expf(v1.x), e3 = __expf(v1.y);
        float s = e0 + e1 + e2 + e3;
        s += __shfl_xor_sync(FULL, s, 1);
        s += __shfl_xor_sync(FULL, s, 2);
        s += __shfl_xor_sync(FULL, s, 4);
        s += __shfl_xor_sync(FULL, s, 8);
        s += __shfl_xor_sync(FULL, s, 16);
        float inv = 1.f / s;
        if (act)
            *(float4*)(g_q + (size_t)row * D + lane * 4) =
                make_float4(e0 * inv, e1 * inv, e2 * inv, e3 * inv);

        float2 u0 = up2(ak[r][0]), u1 = up2(ak[r][1]);
        float f0 = __expf(u0.x), f1 = __expf(u0.y);
        float f2 = __expf(u1.x), f3 = __expf(u1.y);
        if (act) {
            *(float4*)(g_ek + (size_t)row * D + lane * 4) = make_float4(f0, f1, f2, f3);
            cs0 += f0; cs1 += f1; cs2 += f2; cs3 += f3;
        }
    }
    atomicAdd(&scol[lane * 4 + 0], cs0);
    atomicAdd(&scol[lane * 4 + 1], cs1);
    atomicAdd(&scol[lane * 4 + 2], cs2);
    atomicAdd(&scol[lane * 4 + 3], cs3);
    __syncthreads();
    if (tid < D) atomicAdd(&g_Z[tid], scol[tid]);
}

// ---------------- K2: kvU = ek^T @ x, kqU = ek^T @ q  (tiled outer product) ---
// warp w owns d-rows w*8..+7; lane l owns cols l*4..+3 of BOTH outputs.
__global__ __launch_bounds__(NTHREADS, 1)
void k2_kernel(const float* __restrict__ x) {
    extern __shared__ float sm[];
    float* eks = sm;                     // [K2_CHUNK][EST]
    float* xs  = eks + K2_CHUNK * EST;
    float* qs  = xs  + K2_CHUNK * EST;

    const int tid  = threadIdx.x;
    const int w    = tid >> 5;
    const int lane = tid & 31;

    const int chunkN = (NROWS + K2_BLOCKS - 1) / K2_BLOCKS;
    int start = blockIdx.x * chunkN;
    int end = start + chunkN;
    if (end > NROWS) end = NROWS;

    u64 av[8][2], aq[8][2];
    #pragma unroll
    for (int i = 0; i < 8; i++) {
        av[i][0] = 0ull; av[i][1] = 0ull;
        aq[i][0] = 0ull; aq[i][1] = 0ull;
    }

    for (int n0 = start; n0 < end; n0 += K2_CHUNK) {
        int count = end - n0; if (count > K2_CHUNK) count = K2_CHUNK;
        for (int idx = tid; idx < K2_CHUNK * 32; idx += NTHREADS) {
            int r = idx >> 5, c4 = (idx & 31) * 4;
            float4 e = zero4(), xv = zero4(), qv = zero4();
            if (r < count) {
                size_t base = (size_t)(n0 + r) * D + c4;
                e  = *(const float4*)(g_ek + base);
                xv = *(const float4*)(x    + base);
                qv = *(const float4*)(g_q  + base);
            }
            *(float4*)&eks[r * EST + c4] = e;
            *(float4*)&xs [r * EST + c4] = xv;
            *(float4*)&qs [r * EST + c4] = qv;
        }
        __syncthreads();

        #pragma unroll 4
        for (int nl = 0; nl < K2_CHUNK; nl++) {
            float4 ea = *(const float4*)&eks[nl * EST + w * 8];      // broadcast
            float4 eb = *(const float4*)&eks[nl * EST + w * 8 + 4];  // broadcast
            ulonglong2 xv = *(const ulonglong2*)&xs[nl * EST + lane * 4];
            ulonglong2 qv = *(const ulonglong2*)&qs[nl * EST + lane * 4];
            float ee[8] = {ea.x, ea.y, ea.z, ea.w, eb.x, eb.y, eb.z, eb.w};
            #pragma unroll
            for (int i = 0; i < 8; i++) {
                u64 ed = pack2(ee[i], ee[i]);
                av[i][0] = fma2(ed, xv.x, av[i][0]);
                av[i][1] = fma2(ed, xv.y, av[i][1]);
                aq[i][0] = fma2(ed, qv.x, aq[i][0]);
                aq[i][1] = fma2(ed, qv.y, aq[i][1]);
            }
        }
        __syncthreads();
    }

    #pragma unroll
    for (int i = 0; i < 8; i++) {
        int base = (w * 8 + i) * D + lane * 4;
        float2 a0 = up2(av[i][0]), a1 = up2(av[i][1]);
        float2 b0 = up2(aq[i][0]), b1 = up2(aq[i][1]);
        atomicAdd(&g_kvU[base + 0], a0.x);
        atomicAdd(&g_kvU[base + 1], a0.y);
        atomicAdd(&g_kvU[base + 2], a1.x);
        atomicAdd(&g_kvU[base + 3], a1.y);
        atomicAdd(&g_kqU[base + 0], b0.x);
        atomicAdd(&g_kqU[base + 1], b0.y);
        atomicAdd(&g_kqU[base + 2], b1.x);
        atomicAdd(&g_kqU[base + 3], b1.y);
    }
}

// ---------------- K3: normalize by column sums --------------------------------
__global__ void norm_kernel() {
    int i = blockIdx.x * blockDim.x + threadIdx.x;
    if (i < D * D) {
        float inv = 1.f / g_Z[i >> 7];
        g_kv[i] = g_kvU[i] * inv;
        g_kq[i] = g_kqU[i] * inv;
    }
}

// ---------------- Kstep: B = A @ kq ; M (+)= temp[step] * A -------------------
__global__ void kstep_kernel(const float* __restrict__ temp, int step) {
    const float* A;
    float* B;
    if (step == 1)      { A = g_kv;   B = g_bufA; }
    else if (step & 1)  { A = g_bufB; B = g_bufA; }
    else                { A = g_bufA; B = g_bufB; }

    __shared__ float sA[D];
    int b = blockIdx.x, c = threadIdx.x;
    sA[c] = A[b * D + c];
    __syncthreads();

    float acc = 0.f;
    #pragma unroll 8
    for (int j = 0; j < D; j++) acc = fmaf(sA[j], g_kq[j * D + c], acc);
    B[b * D + c] = acc;

    float mv = temp[step] * sA[c];
    if (step == 1) g_M[b * D + c] = mv;
    else           g_M[b * D + c] += mv;
}

// ---------------- K4: out = temp[0]*x + q @ M  (256 rows/block) ---------------
// warp w owns rows w*16..+15; lane l owns cols l*4..+3.
__global__ __launch_bounds__(NTHREADS, 1)
void k4_kernel(const float* __restrict__ x, const float* __restrict__ temp,
               float* __restrict__ out) {
    extern __shared__ float sm[];
    float* qsT = sm;               // [j=128][QST] : qsT[j][r] = q[row0+r][j]
    float* Ms  = qsT + D * QST;    // [j=128][128]

    const int tid  = threadIdx.x;
    const int w    = tid >> 5;
    const int lane = tid & 31;
    const int row0 = blockIdx.x * 256;

    for (int f = tid; f < D * D / 4; f += NTHREADS)
        ((float4*)Ms)[f] = ((const float4*)g_M)[f];
    for (int idx = tid; idx < 256 * 32; idx += NTHREADS) {
        int r = idx >> 5, c4 = (idx & 31) * 4;
        float4 v = zero4();
        if (row0 + r < NROWS)
            v = *(const float4*)(g_q + (size_t)(row0 + r) * D + c4);
        qsT[(c4 + 0) * QST + r] = v.x;
        qsT[(c4 + 1) * QST + r] = v.y;
        qsT[(c4 + 2) * QST + r] = v.z;
        qsT[(c4 + 3) * QST + r] = v.w;
    }
    __syncthreads();

    u64 acc[16][2];
    #pragma unroll
    for (int r = 0; r < 16; r++) { acc[r][0] = 0ull; acc[r][1] = 0ull; }

    #pragma unroll 4
    for (int j = 0; j < D; j++) {
        float4 qa = *(const float4*)&qsT[j * QST + w * 16];       // broadcast
        float4 qb = *(const float4*)&qsT[j * QST + w * 16 + 4];
        float4 qc = *(const float4*)&qsT[j * QST + w * 16 + 8];
        float4 qd = *(const float4*)&qsT[j * QST + w * 16 + 12];
        ulonglong2 m2 = *(const ulonglong2*)&Ms[j * D + lane * 4];
        float qr[16] = {qa.x, qa.y, qa.z, qa.w, qb.x, qb.y, qb.z, qb.w,
                        qc.x, qc.y, qc.z, qc.w, qd.x, qd.y, qd.z, qd.w};
        #pragma unroll
        for (int r = 0; r < 16; r++) {
            u64 qd2 = pack2(qr[r], qr[r]);
            acc[r][0] = fma2(qd2, m2.x, acc[r][0]);
            acc[r][1] = fma2(qd2, m2.y, acc[r][1]);
        }
    }

    float t0 = temp[0];
    #pragma unroll
    for (int r = 0; r < 16; r++) {
        int row = row0 + w * 16 + r;
        if (row < NROWS) {
            const float4 xv = *(const float4*)(x + (size_t)row * D + lane * 4);
            float2 a = up2(acc[r][0]);
            float2 b = up2(acc[r][1]);
            *(float4*)(out + (size_t)row * D + lane * 4) =
                make_float4(fmaf(t0, xv.x, a.x), fmaf(t0, xv.y, a.y),
                            fmaf(t0, xv.z, b.x), fmaf(t0, xv.w, b.y));
        }
    }
}

// ---------------- launch -------------------------------------------------------
extern "C" void kernel_launch(void* const* d_in, const int* in_sizes, int n_in,
                              void* d_out, int out_size) {
    const float* x    = (const float*)d_in[0];
    const float* Wq   = (const float*)d_in[1];
    const float* bq   = (const float*)d_in[2];
    const float* Wk   = (const float*)d_in[3];
    const float* bk   = (const float*)d_in[4];
    const float* temp = (const float*)d_in[5];
    float* out = (float*)d_out;

    const int smem1 = (2 * D * WST + D * XST + D) * (int)sizeof(float);        // ~203.3 KB
    const int smem2 = (3 * K2_CHUNK * EST) * (int)sizeof(float);               // ~101.4 KB
    const int smem4 = (D * QST + D * D) * (int)sizeof(float);                  // ~198.7 KB
    cudaFuncSetAttribute(k1_kernel, cudaFuncAttributeMaxDynamicSharedMemorySize, smem1);
    cudaFuncSetAttribute(k2_kernel, cudaFuncAttributeMaxDynamicSharedMemorySize, smem2);
    cudaFuncSetAttribute(k4_kernel, cudaFuncAttributeMaxDynamicSharedMemorySize, smem4);

    const int nblk1 = (NROWS + 127) / 128;   // 1563
    const int nblk4 = (NROWS + 255) / 256;   // 782

    zero_kernel<<<64, 256>>>();
    k1_kernel<<<nblk1, NTHREADS, smem1>>>(x, Wq, bq, Wk, bk);
    k2_kernel<<<K2_BLOCKS, NTHREADS, smem2>>>(x);
    norm_kernel<<<(D * D + 511) / 512, 512>>>();
    for (int s = 1; s <= KPOW; s++)
        kstep_kernel<<<D, D>>>(temp, s);
    k4_kernel<<<nblk4, NTHREADS, smem4>>>(x, temp, out);
}

// round 5
// speedup vs baseline: 1.4831x; 1.0002x over previous
#include <cuda_runtime.h>
#include <math.h>

#define D      128
#define NROWS  200000
#define KPOW   10

#define NTHREADS  512
#define XST 132          // x^T tile stride (K1)
#define WST 132          // W^T tile stride (K1)
#define EST 132          // K2 staging stride
#define QST 260          // q^T tile stride (K4), 256 rows + pad
#define K2_BLOCKS 148
#define K2_CHUNK  64

typedef unsigned long long u64;

// ---------------- scratch ------------------------------------------------------
__device__ float g_q [(size_t)NROWS * D];
__device__ float g_ek[(size_t)NROWS * D];
__device__ float g_Z  [D];
__device__ float g_kvU[D * D];
__device__ float g_kqU[D * D];
__device__ float g_kv [D * D];
__device__ float g_kq [D * D];
__device__ float g_M  [D * D];
__device__ float g_bufA[D * D];
__device__ float g_bufB[D * D];

// ---------------- packed f32x2 helpers ----------------------------------------
__device__ __forceinline__ u64 pack2(float lo, float hi) {
    u64 r; asm("mov.b64 %0, {%1, %2};" : "=l"(r) : "f"(lo), "f"(hi)); return r;
}
__device__ __forceinline__ float2 up2(u64 v) {
    float2 r; asm("mov.b64 {%0, %1}, %2;" : "=f"(r.x), "=f"(r.y) : "l"(v)); return r;
}
__device__ __forceinline__ u64 fma2(u64 a, u64 b, u64 c) {
    u64 d; asm("fma.rn.f32x2 %0, %1, %2, %3;" : "=l"(d) : "l"(a), "l"(b), "l"(c)); return d;
}
__device__ __forceinline__ float4 zero4() { return make_float4(0.f, 0.f, 0.f, 0.f); }

// ---------------- K0: zero the accumulators -----------------------------------
__global__ void zero_kernel() {
    int i = blockIdx.x * blockDim.x + threadIdx.x;
    if (i < D) g_Z[i] = 0.f;
    for (int k = i; k < D * D; k += gridDim.x * blockDim.x) {
        g_kvU[k] = 0.f;
        g_kqU[k] = 0.f;
    }
}

// ---------------- K1: q = softmax_row(xWq^T+bq), ek = exp(xWk^T+bk), Z += colsum
// 512 thr, 128 rows/block. warp w owns rows w*8..w*8+7; lane l owns cols l*4..l*4+3
// of BOTH the q and k outputs. All smem reads broadcast or warp-contiguous.
__global__ __launch_bounds__(NTHREADS, 1)
void k1_kernel(const float* __restrict__ x,  const float* __restrict__ Wq,
               const float* __restrict__ bq, const float* __restrict__ Wk,
               const float* __restrict__ bk) {
    extern __shared__ float sm[];
    float* wqs  = sm;                 // [j=128][WST]  (W^T)
    float* wks  = wqs + D * WST;
    float* xsT  = wks + D * WST;      // [j=128][XST]  (x^T: xsT[j][r] = x[row0+r][j])
    float* scol = xsT + D * XST;      // [128]

    const int tid  = threadIdx.x;
    const int w    = tid >> 5;
    const int lane = tid & 31;
    const int row0 = blockIdx.x * 128;

    // weights: read Wq[c*128+j] coalesced, write transposed
    for (int idx = tid; idx < D * D; idx += NTHREADS) {
        int c = idx >> 7, j = idx & 127;
        wqs[j * WST + c] = Wq[idx];
        wks[j * WST + c] = Wk[idx];
    }
    // x tile transposed; zero OOB rows
    for (int idx = tid; idx < 128 * 32; idx += NTHREADS) {
        int r = idx >> 5, c4 = (idx & 31) * 4;
        float4 v = zero4();
        if (row0 + r < NROWS)
            v = *(const float4*)(x + (size_t)(row0 + r) * D + c4);
        xsT[(c4 + 0) * XST + r] = v.x;
        xsT[(c4 + 1) * XST + r] = v.y;
        xsT[(c4 + 2) * XST + r] = v.z;
        xsT[(c4 + 3) * XST + r] = v.w;
    }
    if (tid < D) scol[tid] = 0.f;
    __syncthreads();

    // accumulators: 8 rows x (2 packed q + 2 packed k)
    u64 aq[8][2], ak[8][2];
    {
        float4 b1 = *(const float4*)(bq + lane * 4);
        float4 b2 = *(const float4*)(bk + lane * 4);
        u64 q0 = pack2(b1.x, b1.y), q1 = pack2(b1.z, b1.w);
        u64 k0 = pack2(b2.x, b2.y), k1v = pack2(b2.z, b2.w);
        #pragma unroll
        for (int r = 0; r < 8; r++) {
            aq[r][0] = q0; aq[r][1] = q1;
            ak[r][0] = k0; ak[r][1] = k1v;
        }
    }

    #pragma unroll 4
    for (int j = 0; j < D; j++) {
        float4 xa = *(const float4*)&xsT[j * XST + w * 8];      // broadcast
        float4 xb = *(const float4*)&xsT[j * XST + w * 8 + 4];  // broadcast
        ulonglong2 wq2 = *(const ulonglong2*)&wqs[j * WST + lane * 4];
        ulonglong2 wk2 = *(const ulonglong2*)&wks[j * WST + lane * 4];
        float xr[8] = {xa.x, xa.y, xa.z, xa.w, xb.x, xb.y, xb.z, xb.w};
        #pragma unroll
        for (int r = 0; r < 8; r++) {
            u64 xd = pack2(xr[r], xr[r]);
            aq[r][0] = fma2(xd, wq2.x, aq[r][0]);
            aq[r][1] = fma2(xd, wq2.y, aq[r][1]);
            ak[r][0] = fma2(xd, wk2.x, ak[r][0]);
            ak[r][1] = fma2(xd, wk2.y, ak[r][1]);
        }
    }

    const unsigned FULL = 0xffffffffu;

    // ---- q rows: softmax without max-subtraction (logits bounded ~|3.5|) ----
    float cs0 = 0.f, cs1 = 0.f, cs2 = 0.f, cs3 = 0.f;
    #pragma unroll
    for (int r = 0; r < 8; r++) {
        int row = row0 + w * 8 + r;
        bool act = row < NROWS;

        float2 v0 = up2(aq[r][0]), v1 = up2(aq[r][1]);
        float e0 = __expf(v0.x), e1 = __expf(v0.y);
        float e2 = __expf(v1.x), e3 = __expf(v1.y);
        float s = e0 + e1 + e2 + e3;
        s += __shfl_xor_sync(FULL, s, 1);
        s += __shfl_xor_sync(FULL, s, 2);
        s += __shfl_xor_sync(FULL, s, 4);
        s += __shfl_xor_sync(FULL, s, 8);
        s += __shfl_xor_sync(FULL, s, 16);
        float inv = 1.f / s;
        if (act)
            *(float4*)(g_q + (size_t)row * D + lane * 4) =
                make_float4(e0 * inv, e1 * inv, e2 * inv, e3 * inv);

        float2 u0 = up2(ak[r][0]), u1 = up2(ak[r][1]);
        float f0 = __expf(u0.x), f1 = __expf(u0.y);
        float f2 = __expf(u1.x), f3 = __expf(u1.y);
        if (act) {
            *(float4*)(g_ek + (size_t)row * D + lane * 4) = make_float4(f0, f1, f2, f3);
            cs0 += f0; cs1 += f1; cs2 += f2; cs3 += f3;
        }
    }
    atomicAdd(&scol[lane * 4 + 0], cs0);
    atomicAdd(&scol[lane * 4 + 1], cs1);
    atomicAdd(&scol[lane * 4 + 2], cs2);
    atomicAdd(&scol[lane * 4 + 3], cs3);
    __syncthreads();
    if (tid < D) atomicAdd(&g_Z[tid], scol[tid]);
}

// ---------------- K2: kvU = ek^T @ x, kqU = ek^T @ q  (tiled outer product) ---
// warp w owns d-rows w*8..+7; lane l owns cols l*4..+3 of BOTH outputs.
__global__ __launch_bounds__(NTHREADS, 1)
void k2_kernel(const float* __restrict__ x) {
    extern __shared__ float sm[];
    float* eks = sm;                     // [K2_CHUNK][EST]
    float* xs  = eks + K2_CHUNK * EST;
    float* qs  = xs  + K2_CHUNK * EST;

    const int tid  = threadIdx.x;
    const int w    = tid >> 5;
    const int lane = tid & 31;

    const int chunkN = (NROWS + K2_BLOCKS - 1) / K2_BLOCKS;
    int start = blockIdx.x * chunkN;
    int end = start + chunkN;
    if (end > NROWS) end = NROWS;

    u64 av[8][2], aq[8][2];
    #pragma unroll
    for (int i = 0; i < 8; i++) {
        av[i][0] = 0ull; av[i][1] = 0ull;
        aq[i][0] = 0ull; aq[i][1] = 0ull;
    }

    for (int n0 = start; n0 < end; n0 += K2_CHUNK) {
        int count = end - n0; if (count > K2_CHUNK) count = K2_CHUNK;
        for (int idx = tid; idx < K2_CHUNK * 32; idx += NTHREADS) {
            int r = idx >> 5, c4 = (idx & 31) * 4;
            float4 e = zero4(), xv = zero4(), qv = zero4();
            if (r < count) {
                size_t base = (size_t)(n0 + r) * D + c4;
                e  = *(const float4*)(g_ek + base);
                xv = *(const float4*)(x    + base);
                qv = *(const float4*)(g_q  + base);
            }
            *(float4*)&eks[r * EST + c4] = e;
            *(float4*)&xs [r * EST + c4] = xv;
            *(float4*)&qs [r * EST + c4] = qv;
        }
        __syncthreads();

        #pragma unroll 4
        for (int nl = 0; nl < K2_CHUNK; nl++) {
            float4 ea = *(const float4*)&eks[nl * EST + w * 8];      // broadcast
            float4 eb = *(const float4*)&eks[nl * EST + w * 8 + 4];  // broadcast
            ulonglong2 xv = *(const ulonglong2*)&xs[nl * EST + lane * 4];
            ulonglong2 qv = *(const ulonglong2*)&qs[nl * EST + lane * 4];
            float ee[8] = {ea.x, ea.y, ea.z, ea.w, eb.x, eb.y, eb.z, eb.w};
            #pragma unroll
            for (int i = 0; i < 8; i++) {
                u64 ed = pack2(ee[i], ee[i]);
                av[i][0] = fma2(ed, xv.x, av[i][0]);
                av[i][1] = fma2(ed, xv.y, av[i][1]);
                aq[i][0] = fma2(ed, qv.x, aq[i][0]);
                aq[i][1] = fma2(ed, qv.y, aq[i][1]);
            }
        }
        __syncthreads();
    }

    #pragma unroll
    for (int i = 0; i < 8; i++) {
        int base = (w * 8 + i) * D + lane * 4;
        float2 a0 = up2(av[i][0]), a1 = up2(av[i][1]);
        float2 b0 = up2(aq[i][0]), b1 = up2(aq[i][1]);
        atomicAdd(&g_kvU[base + 0], a0.x);
        atomicAdd(&g_kvU[base + 1], a0.y);
        atomicAdd(&g_kvU[base + 2], a1.x);
        atomicAdd(&g_kvU[base + 3], a1.y);
        atomicAdd(&g_kqU[base + 0], b0.x);
        atomicAdd(&g_kqU[base + 1], b0.y);
        atomicAdd(&g_kqU[base + 2], b1.x);
        atomicAdd(&g_kqU[base + 3], b1.y);
    }
}

// ---------------- K3: normalize by column sums --------------------------------
__global__ void norm_kernel() {
    int i = blockIdx.x * blockDim.x + threadIdx.x;
    if (i < D * D) {
        float inv = 1.f / g_Z[i >> 7];
        g_kv[i] = g_kvU[i] * inv;
        g_kq[i] = g_kqU[i] * inv;
    }
}

// ---------------- Kstep: B = A @ kq ; M (+)= temp[step] * A -------------------
__global__ void kstep_kernel(const float* __restrict__ temp, int step) {
    const float* A;
    float* B;
    if (step == 1)      { A = g_kv;   B = g_bufA; }
    else if (step & 1)  { A = g_bufB; B = g_bufA; }
    else                { A = g_bufA; B = g_bufB; }

    __shared__ float sA[D];
    int b = blockIdx.x, c = threadIdx.x;
    sA[c] = A[b * D + c];
    __syncthreads();

    float acc = 0.f;
    #pragma unroll 8
    for (int j = 0; j < D; j++) acc = fmaf(sA[j], g_kq[j * D + c], acc);
    B[b * D + c] = acc;

    float mv = temp[step] * sA[c];
    if (step == 1) g_M[b * D + c] = mv;
    else           g_M[b * D + c] += mv;
}

// ---------------- K4: out = temp[0]*x + q @ M  (256 rows/block) ---------------
// warp w owns rows w*16..+15; lane l owns cols l*4..+3.
__global__ __launch_bounds__(NTHREADS, 1)
void k4_kernel(const float* __restrict__ x, const float* __restrict__ temp,
               float* __restrict__ out) {
    extern __shared__ float sm[];
    float* qsT = sm;               // [j=128][QST] : qsT[j][r] = q[row0+r][j]
    float* Ms  = qsT + D * QST;    // [j=128][128]

    const int tid  = threadIdx.x;
    const int w    = tid >> 5;
    const int lane = tid & 31;
    const int row0 = blockIdx.x * 256;

    for (int f = tid; f < D * D / 4; f += NTHREADS)
        ((float4*)Ms)[f] = ((const float4*)g_M)[f];
    for (int idx = tid; idx < 256 * 32; idx += NTHREADS) {
        int r = idx >> 5, c4 = (idx & 31) * 4;
        float4 v = zero4();
        if (row0 + r < NROWS)
            v = *(const float4*)(g_q + (size_t)(row0 + r) * D + c4);
        qsT[(c4 + 0) * QST + r] = v.x;
        qsT[(c4 + 1) * QST + r] = v.y;
        qsT[(c4 + 2) * QST + r] = v.z;
        qsT[(c4 + 3) * QST + r] = v.w;
    }
    __syncthreads();

    u64 acc[16][2];
    #pragma unroll
    for (int r = 0; r < 16; r++) { acc[r][0] = 0ull; acc[r][1] = 0ull; }

    #pragma unroll 4
    for (int j = 0; j < D; j++) {
        float4 qa = *(const float4*)&qsT[j * QST + w * 16];       // broadcast
        float4 qb = *(const float4*)&qsT[j * QST + w * 16 + 4];
        float4 qc = *(const float4*)&qsT[j * QST + w * 16 + 8];
        float4 qd = *(const float4*)&qsT[j * QST + w * 16 + 12];
        ulonglong2 m2 = *(const ulonglong2*)&Ms[j * D + lane * 4];
        float qr[16] = {qa.x, qa.y, qa.z, qa.w, qb.x, qb.y, qb.z, qb.w,
                        qc.x, qc.y, qc.z, qc.w, qd.x, qd.y, qd.z, qd.w};
        #pragma unroll
        for (int r = 0; r < 16; r++) {
            u64 qd2 = pack2(qr[r], qr[r]);
            acc[r][0] = fma2(qd2, m2.x, acc[r][0]);
            acc[r][1] = fma2(qd2, m2.y, acc[r][1]);
        }
    }

    float t0 = temp[0];
    #pragma unroll
    for (int r = 0; r < 16; r++) {
        int row = row0 + w * 16 + r;
        if (row < NROWS) {
            const float4 xv = *(const float4*)(x + (size_t)row * D + lane * 4);
            float2 a = up2(acc[r][0]);
            float2 b = up2(acc[r][1]);
            *(float4*)(out + (size_t)row * D + lane * 4) =
                make_float4(fmaf(t0, xv.x, a.x), fmaf(t0, xv.y, a.y),
                            fmaf(t0, xv.z, b.x), fmaf(t0, xv.w, b.y));
        }
    }
}

// ---------------- launch -------------------------------------------------------
extern "C" void kernel_launch(void* const* d_in, const int* in_sizes, int n_in,
                              void* d_out, int out_size) {
    const float* x    = (const float*)d_in[0];
    const float* Wq   = (const float*)d_in[1];
    const float* bq   = (const float*)d_in[2];
    const float* Wk   = (const float*)d_in[3];
    const float* bk   = (const float*)d_in[4];
    const float* temp = (const float*)d_in[5];
    float* out = (float*)d_out;

    const int smem1 = (2 * D * WST + D * XST + D) * (int)sizeof(float);        // ~203.3 KB
    const int smem2 = (3 * K2_CHUNK * EST) * (int)sizeof(float);               // ~101.4 KB
    const int smem4 = (D * QST + D * D) * (int)sizeof(float);                  // ~198.7 KB
    cudaFuncSetAttribute(k1_kernel, cudaFuncAttributeMaxDynamicSharedMemorySize, smem1);
    cudaFuncSetAttribute(k2_kernel, cudaFuncAttributeMaxDynamicSharedMemorySize, smem2);
    cudaFuncSetAttribute(k4_kernel, cudaFuncAttributeMaxDynamicSharedMemorySize, smem4);

    const int nblk1 = (NROWS + 127) / 128;   // 1563
    const int nblk4 = (NROWS + 255) / 256;   // 782

    zero_kernel<<<64, 256>>>();
    k1_kernel<<<nblk1, NTHREADS, smem1>>>(x, Wq, bq, Wk, bk);
    k2_kernel<<<K2_BLOCKS, NTHREADS, smem2>>>(x);
    norm_kernel<<<(D * D + 511) / 512, 512>>>();
    for (int s = 1; s <= KPOW; s++)
        kstep_kernel<<<D, D>>>(temp, s);
    k4_kernel<<<nblk4, NTHREADS, smem4>>>(x, temp, out);
}

// round 8
// speedup vs baseline: 2.9077x; 1.9605x over previous
#include <cuda_runtime.h>

#define D      128
#define NROWS  200000
#define KPOW   10
#define S      136          // bf16 tile row stride (272B: conflict-free ldmatrix)
typedef unsigned int u32;

// ---------------- scratch ------------------------------------------------------
__device__ float g_q [(size_t)NROWS * D];
__device__ float g_ek[(size_t)NROWS * D];
__device__ float g_Z  [D];
__device__ float g_kvU[D * D];
__device__ float g_kqU[D * D];
__device__ float g_kv [D * D];
__device__ float g_kq [D * D];
__device__ float g_MT [D * D];          // M^T: g_MT[c*D+b] = M[b][c]
__device__ float g_bufA[D * D];
__device__ float g_bufB[D * D];

// ---------------- helpers ------------------------------------------------------
__device__ __forceinline__ u32 smem_u32(const void* p) {
    u32 a;
    asm("{ .reg .u64 t; cvta.to.shared.u64 t, %1; cvt.u32.u64 %0, t; }" : "=r"(a) : "l"(p));
    return a;
}
// float4 -> bf16 hi pair-packs (h01,h23) and lo packs (l01,l23); memory order lo-half first
__device__ __forceinline__ void split4(float4 v, u32& h01, u32& h23, u32& l01, u32& l23) {
    asm("cvt.rn.bf16x2.f32 %0, %1, %2;" : "=r"(h01) : "f"(v.y), "f"(v.x));
    asm("cvt.rn.bf16x2.f32 %0, %1, %2;" : "=r"(h23) : "f"(v.w), "f"(v.z));
    float r0 = v.x - __uint_as_float(h01 << 16);
    float r1 = v.y - __uint_as_float(h01 & 0xffff0000u);
    float r2 = v.z - __uint_as_float(h23 << 16);
    float r3 = v.w - __uint_as_float(h23 & 0xffff0000u);
    asm("cvt.rn.bf16x2.f32 %0, %1, %2;" : "=r"(l01) : "f"(r1), "f"(r0));
    asm("cvt.rn.bf16x2.f32 %0, %1, %2;" : "=r"(l23) : "f"(r3), "f"(r2));
}

#define LDSM4(r, a)  asm volatile("ldmatrix.sync.aligned.m8n8.x4.shared.b16 {%0,%1,%2,%3}, [%4];" \
    : "=r"((r)[0]), "=r"((r)[1]), "=r"((r)[2]), "=r"((r)[3]) : "r"(a))
#define LDSM4T(r, a) asm volatile("ldmatrix.sync.aligned.m8n8.x4.trans.shared.b16 {%0,%1,%2,%3}, [%4];" \
    : "=r"((r)[0]), "=r"((r)[1]), "=r"((r)[2]), "=r"((r)[3]) : "r"(a))
#define LDSM2(r0, r1, a)  asm volatile("ldmatrix.sync.aligned.m8n8.x2.shared.b16 {%0,%1}, [%2];" \
    : "=r"(r0), "=r"(r1) : "r"(a))
#define LDSM2T(r0, r1, a) asm volatile("ldmatrix.sync.aligned.m8n8.x2.trans.shared.b16 {%0,%1}, [%2];" \
    : "=r"(r0), "=r"(r1) : "r"(a))
#define MMA(c, a, b0, b1) asm volatile( \
    "mma.sync.aligned.m16n8k16.row.col.f32.bf16.bf16.f32 " \
    "{%0,%1,%2,%3}, {%4,%5,%6,%7}, {%8,%9}, {%0,%1,%2,%3};" \
    : "+f"((c)[0]), "+f"((c)[1]), "+f"((c)[2]), "+f"((c)[3]) \
    : "r"((a)[0]), "r"((a)[1]), "r"((a)[2]), "r"((a)[3]), "r"(b0), "r"(b1))

// ---------------- K0 -----------------------------------------------------------
__global__ void zero_kernel() {
    int i = blockIdx.x * blockDim.x + threadIdx.x;
    if (i < D) g_Z[i] = 0.f;
    for (int k = i; k < D * D; k += gridDim.x * blockDim.x) { g_kvU[k] = 0.f; g_kqU[k] = 0.f; }
}

// ---------------- K1: q = softmax_row(xWq^T+bq), ek = exp(xWk^T+bk), Z += colsum
#define O1BQ 0
#define O1BK 512
#define O1SI 1024
#define O1AH 2048
#define O1AL (O1AH + 34816)
#define O1BH (O1AL + 34816)
#define O1BL (O1BH + 69632)
#define SMEM1 (O1BL + 69632)            // 210944
__global__ __launch_bounds__(512, 1) void k1b(const float* __restrict__ x,
        const float* __restrict__ Wq, const float* __restrict__ bq,
        const float* __restrict__ Wk, const float* __restrict__ bk) {
    extern __shared__ __align__(16) char sm[];
    const int tid = threadIdx.x, lane = tid & 31, wid = tid >> 5;
    const int row0 = blockIdx.x * 128;
    u32 sb = smem_u32(sm);
    float* sbq = (float*)(sm + O1BQ);
    float* sbk = (float*)(sm + O1BK);
    float* sinv = (float*)(sm + O1SI);
    if (tid < 128) { sbq[tid] = bq[tid]; sbk[tid] = bk[tid]; }

    #pragma unroll
    for (int i = 0; i < 8; i++) {                       // stage x -> A tiles
        int idx = tid + 512 * i, r = idx >> 5, c4 = (idx & 31) << 2;
        float4 v = make_float4(0.f, 0.f, 0.f, 0.f);
        if (row0 + r < NROWS) v = *(const float4*)(x + (size_t)(row0 + r) * D + c4);
        u32 h01, h23, l01, l23; split4(v, h01, h23, l01, l23);
        u32 off = (u32)(r * S + c4) * 2;
        *(uint2*)(sm + O1AH + off) = make_uint2(h01, h23);
        *(uint2*)(sm + O1AL + off) = make_uint2(l01, l23);
    }
    #pragma unroll
    for (int i = 0; i < 8; i++) {                       // stage Wq(0-127)|Wk(128-255) -> B
        int idx = tid + 512 * i, r = idx >> 5, c4 = (idx & 31) << 2;
        u32 h01, h23, l01, l23;
        float4 v1 = *(const float4*)(Wq + r * D + c4);
        split4(v1, h01, h23, l01, l23);
        u32 off = (u32)(r * S + c4) * 2;
        *(uint2*)(sm + O1BH + off) = make_uint2(h01, h23);
        *(uint2*)(sm + O1BL + off) = make_uint2(l01, l23);
        float4 v2 = *(const float4*)(Wk + r * D + c4);
        split4(v2, h01, h23, l01, l23);
        off = (u32)((r + 128) * S + c4) * 2;
        *(uint2*)(sm + O1BH + off) = make_uint2(h01, h23);
        *(uint2*)(sm + O1BL + off) = make_uint2(l01, l23);
    }
    __syncthreads();

    const int m0 = (wid >> 2) * 32, n0 = (wid & 3) * 64;
    float c[2][8][4];
    #pragma unroll
    for (int a = 0; a < 2; a++)
        #pragma unroll
        for (int b = 0; b < 8; b++)
            #pragma unroll
            for (int e = 0; e < 4; e++) c[a][b][e] = 0.f;

    const int arow = (lane & 7) + ((lane >> 3) & 1) * 8, acol = ((lane >> 4) & 1) * 8;
    const int brow = lane & 7,                           bcol = ((lane >> 3) & 1) * 8;

    for (int s = 0; s < 8; s++) {
        int k0 = s * 16;
        u32 ah[2][4], al[2][4];
        #pragma unroll
        for (int mt = 0; mt < 2; mt++) {
            u32 ad = sb + O1AH + (u32)((m0 + 16 * mt + arow) * S + k0 + acol) * 2;
            LDSM4(ah[mt], ad);
            ad = sb + O1AL + (u32)((m0 + 16 * mt + arow) * S + k0 + acol) * 2;
            LDSM4(al[mt], ad);
        }
        #pragma unroll
        for (int nt = 0; nt < 8; nt++) {
            u32 bh0, bh1, bl0, bl1;
            u32 bd = sb + O1BH + (u32)((n0 + 8 * nt + brow) * S + k0 + bcol) * 2;
            LDSM2(bh0, bh1, bd);
            bd = sb + O1BL + (u32)((n0 + 8 * nt + brow) * S + k0 + bcol) * 2;
            LDSM2(bl0, bl1, bd);
            #pragma unroll
            for (int mt = 0; mt < 2; mt++) {
                MMA(c[mt][nt], ah[mt], bh0, bh1);
                MMA(c[mt][nt], al[mt], bh0, bh1);
                MMA(c[mt][nt], ah[mt], bl0, bl1);
            }
        }
    }
    __syncthreads();

    float* qs = (float*)(sm + O1BH);                    // [128][132] overlay (B dead)
    float* es = (float*)(sm + O1BH + 67584);
    const int g = lane >> 2, t2 = (lane & 3) * 2;
    const bool isq = n0 < 128;
    #pragma unroll
    for (int mt = 0; mt < 2; mt++)
        #pragma unroll
        for (int nt = 0; nt < 8; nt++) {
            int col = n0 + nt * 8 + t2;
            int r1 = m0 + mt * 16 + g, r2 = r1 + 8;
            float bi0 = isq ? sbq[col] : sbk[col - 128];
            float bi1 = isq ? sbq[col + 1] : sbk[col - 127];
            float e00 = __expf(c[mt][nt][0] + bi0), e01 = __expf(c[mt][nt][1] + bi1);
            float e10 = __expf(c[mt][nt][2] + bi0), e11 = __expf(c[mt][nt][3] + bi1);
            if (isq) {
                qs[r1 * 132 + col] = e00;  qs[r1 * 132 + col + 1] = e01;
                qs[r2 * 132 + col] = e10;  qs[r2 * 132 + col + 1] = e11;
            } else {
                int cl = col - 128;
                bool a1 = (row0 + r1) < NROWS, a2 = (row0 + r2) < NROWS;
                es[r1 * 132 + cl] = a1 ? e00 : 0.f;  es[r1 * 132 + cl + 1] = a1 ? e01 : 0.f;
                es[r2 * 132 + cl] = a2 ? e10 : 0.f;  es[r2 * 132 + cl + 1] = a2 ? e11 : 0.f;
            }
        }
    __syncthreads();
    if (tid < 128) {
        float ssum = 0.f;
        #pragma unroll 8
        for (int j = 0; j < 128; j++) ssum += qs[tid * 132 + j];
        sinv[tid] = 1.f / ssum;
    }
    __syncthreads();
    #pragma unroll
    for (int i = 0; i < 8; i++) {
        int idx = tid + 512 * i, r = idx >> 5, c4 = (idx & 31) << 2;
        if (row0 + r < NROWS) {
            float iv = sinv[r];
            float4 q4 = *(float4*)&qs[r * 132 + c4];
            q4.x *= iv; q4.y *= iv; q4.z *= iv; q4.w *= iv;
            *(float4*)(g_q  + (size_t)(row0 + r) * D + c4) = q4;
            *(float4*)(g_ek + (size_t)(row0 + r) * D + c4) = *(float4*)&es[r * 132 + c4];
        }
    }
    if (tid < 128) {
        float ssum = 0.f;
        #pragma unroll 8
        for (int r = 0; r < 128; r++) ssum += es[r * 132 + tid];
        atomicAdd(&g_Z[tid], ssum);
    }
}

// ---------------- K2: kvU = ek^T @ x, kqU = ek^T @ q ---------------------------
#define O2T 1024
#define TS2 17408                       // [64][136] bf16 tile
#define SMEM2 (O2T + 6 * TS2)           // 105472
__global__ __launch_bounds__(512, 1) void k2b(const float* __restrict__ x) {
    extern __shared__ __align__(16) char sm[];
    const int tid = threadIdx.x, lane = tid & 31, wid = tid >> 5;
    u32 sb = smem_u32(sm);
    const int per = (NROWS + 147) / 148;
    int start = blockIdx.x * per;
    int end = start + per; if (end > NROWS) end = NROWS;

    const int d0 = (wid >> 2) * 32, cw = wid & 3;
    const bool isx = cw < 2;
    const int c0 = (cw & 1) * 64;
    float c[2][8][4];
    #pragma unroll
    for (int a = 0; a < 2; a++)
        #pragma unroll
        for (int b = 0; b < 8; b++)
            #pragma unroll
            for (int e = 0; e < 4; e++) c[a][b][e] = 0.f;

    const int tarow = (lane & 7) + ((lane >> 4) & 1) * 8, tacol = ((lane >> 3) & 1) * 8;
    const int tbrow = (lane & 7) + ((lane >> 3) & 1) * 8;
    const u32 obh = isx ? (O2T + 2 * TS2) : (O2T + 4 * TS2);

    for (int n0 = start; n0 < end; n0 += 64) {
        #pragma unroll
        for (int it = 0; it < 12; it++) {
            int a = it >> 2;
            int idx = tid + 512 * (it & 3), r = idx >> 5, c4 = (idx & 31) << 2;
            const float* src = (a == 0) ? g_ek : ((a == 1) ? x : g_q);
            float4 v = make_float4(0.f, 0.f, 0.f, 0.f);
            if (n0 + r < end) v = *(const float4*)(src + (size_t)(n0 + r) * D + c4);
            u32 h01, h23, l01, l23; split4(v, h01, h23, l01, l23);
            u32 off = (u32)(r * S + c4) * 2;
            *(uint2*)(sm + O2T + a * 2 * TS2 + off)       = make_uint2(h01, h23);
            *(uint2*)(sm + O2T + a * 2 * TS2 + TS2 + off) = make_uint2(l01, l23);
        }
        __syncthreads();
        #pragma unroll
        for (int s = 0; s < 4; s++) {
            int k0 = s * 16;
            u32 ah[2][4], al[2][4];
            #pragma unroll
            for (int mt = 0; mt < 2; mt++) {
                u32 ad = sb + O2T + (u32)((k0 + tarow) * S + d0 + 16 * mt + tacol) * 2;
                LDSM4T(ah[mt], ad);
                ad = sb + O2T + TS2 + (u32)((k0 + tarow) * S + d0 + 16 * mt + tacol) * 2;
                LDSM4T(al[mt], ad);
            }
            #pragma unroll
            for (int nt = 0; nt < 8; nt++) {
                int cc = c0 + 8 * nt;
                u32 bh0, bh1, bl0, bl1;
                u32 bd = sb + obh + (u32)((k0 + tbrow) * S + cc) * 2;
                LDSM2T(bh0, bh1, bd);
                bd = sb + obh + TS2 + (u32)((k0 + tbrow) * S + cc) * 2;
                LDSM2T(bl0, bl1, bd);
                #pragma unroll
                for (int mt = 0; mt < 2; mt++) {
                    MMA(c[mt][nt], ah[mt], bh0, bh1);
                    MMA(c[mt][nt], al[mt], bh0, bh1);
                    MMA(c[mt][nt], ah[mt], bl0, bl1);
                }
            }
        }
        __syncthreads();
    }
    float* dst = isx ? g_kvU : g_kqU;
    const int g = lane >> 2, t2 = (lane & 3) * 2;
    #pragma unroll
    for (int mt = 0; mt < 2; mt++)
        #pragma unroll
        for (int nt = 0; nt < 8; nt++) {
            int col = c0 + 8 * nt + t2;
            int r1 = d0 + 16 * mt + g, r2 = r1 + 8;
            atomicAdd(&dst[r1 * D + col],     c[mt][nt][0]);
            atomicAdd(&dst[r1 * D + col + 1], c[mt][nt][1]);
            atomicAdd(&dst[r2 * D + col],     c[mt][nt][2]);
            atomicAdd(&dst[r2 * D + col + 1], c[mt][nt][3]);
        }
}

// ---------------- K3 -----------------------------------------------------------
__global__ void norm_kernel() {
    int i = blockIdx.x * blockDim.x + threadIdx.x;
    if (i < D * D) {
        float inv = 1.f / g_Z[i >> 7];
        g_kv[i] = g_kvU[i] * inv;
        g_kq[i] = g_kqU[i] * inv;
    }
}

// ---------------- Kstep: B = A @ kq ; MT (+)= temp[step] * A^T ------------------
__global__ void kstep_kernel(const float* __restrict__ temp, int step) {
    const float* A; float* B;
    if (step == 1)     { A = g_kv;   B = g_bufA; }
    else if (step & 1) { A = g_bufB; B = g_bufA; }
    else               { A = g_bufA; B = g_bufB; }
    __shared__ float sA[D];
    int b = blockIdx.x, cc = threadIdx.x;
    sA[cc] = A[b * D + cc];
    __syncthreads();
    float acc = 0.f;
    #pragma unroll 8
    for (int j = 0; j < D; j++) acc = fmaf(sA[j], g_kq[j * D + cc], acc);
    B[b * D + cc] = acc;
    float mv = temp[step] * sA[cc];
    if (step == 1) g_MT[cc * D + b] = mv;
    else           g_MT[cc * D + b] += mv;
}

// ---------------- K4: out = temp[0]*x + q @ M ----------------------------------
#define O4AH 1024
#define O4AL (O4AH + 34816)
#define O4BH (O4AL + 34816)
#define O4BL (O4BH + 34816)
#define SMEM4 (O4BL + 34816)            // 140288
__global__ __launch_bounds__(512, 1) void k4b(const float* __restrict__ x,
        const float* __restrict__ temp, float* __restrict__ out) {
    extern __shared__ __align__(16) char sm[];
    const int tid = threadIdx.x, lane = tid & 31, wid = tid >> 5;
    const int row0 = blockIdx.x * 128;
    u32 sb = smem_u32(sm);

    #pragma unroll
    for (int i = 0; i < 8; i++) {                       // stage q -> A, MT -> B
        int idx = tid + 512 * i, r = idx >> 5, c4 = (idx & 31) << 2;
        float4 v = make_float4(0.f, 0.f, 0.f, 0.f);
        if (row0 + r < NROWS) v = *(const float4*)(g_q + (size_t)(row0 + r) * D + c4);
        u32 h01, h23, l01, l23; split4(v, h01, h23, l01, l23);
        u32 off = (u32)(r * S + c4) * 2;
        *(uint2*)(sm + O4AH + off) = make_uint2(h01, h23);
        *(uint2*)(sm + O4AL + off) = make_uint2(l01, l23);
        float4 m4 = *(const float4*)(g_MT + r * D + c4);
        split4(m4, h01, h23, l01, l23);
        *(uint2*)(sm + O4BH + off) = make_uint2(h01, h23);
        *(uint2*)(sm + O4BL + off) = make_uint2(l01, l23);
    }
    __syncthreads();

    const int m0 = (wid >> 2) * 32, n0 = (wid & 3) * 32;
    float c[2][4][4];
    #pragma unroll
    for (int a = 0; a < 2; a++)
        #pragma unroll
        for (int b = 0; b < 4; b++)
            #pragma unroll
            for (int e = 0; e < 4; e++) c[a][b][e] = 0.f;

    const int arow = (lane & 7) + ((lane >> 3) & 1) * 8, acol = ((lane >> 4) & 1) * 8;
    const int brow = lane & 7,                           bcol = ((lane >> 3) & 1) * 8;

    for (int s = 0; s < 8; s++) {
        int k0 = s * 16;
        u32 ah[2][4], al[2][4];
        #pragma unroll
        for (int mt = 0; mt < 2; mt++) {
            u32 ad = sb + O4AH + (u32)((m0 + 16 * mt + arow) * S + k0 + acol) * 2;
            LDSM4(ah[mt], ad);
            ad = sb + O4AL + (u32)((m0 + 16 * mt + arow) * S + k0 + acol) * 2;
            LDSM4(al[mt], ad);
        }
        #pragma unroll
        for (int nt = 0; nt < 4; nt++) {
            u32 bh0, bh1, bl0, bl1;
            u32 bd = sb + O4BH + (u32)((n0 + 8 * nt + brow) * S + k0 + bcol) * 2;
            LDSM2(bh0, bh1, bd);
            bd = sb + O4BL + (u32)((n0 + 8 * nt + brow) * S + k0 + bcol) * 2;
            LDSM2(bl0, bl1, bd);
            #pragma unroll
            for (int mt = 0; mt < 2; mt++) {
                MMA(c[mt][nt], ah[mt], bh0, bh1);
                MMA(c[mt][nt], al[mt], bh0, bh1);
                MMA(c[mt][nt], ah[mt], bl0, bl1);
            }
        }
    }
    __syncthreads();

    float* os = (float*)(sm + O4BH);                    // [128][132] overlay (B dead)
    const int g = lane >> 2, t2 = (lane & 3) * 2;
    #pragma unroll
    for (int mt = 0; mt < 2; mt++)
        #pragma unroll
        for (int nt = 0; nt < 4; nt++) {
            int col = n0 + nt * 8 + t2;
            int r1 = m0 + mt * 16 + g, r2 = r1 + 8;
            os[r1 * 132 + col] = c[mt][nt][0];  os[r1 * 132 + col + 1] = c[mt][nt][1];
            os[r2 * 132 + col] = c[mt][nt][2];  os[r2 * 132 + col + 1] = c[mt][nt][3];
        }
    __syncthreads();
    float t0 = temp[0];
    #pragma unroll
    for (int i = 0; i < 8; i++) {
        int idx = tid + 512 * i, r = idx >> 5, c4 = (idx & 31) << 2;
        if (row0 + r < NROWS) {
            float4 xv = *(const float4*)(x + (size_t)(row0 + r) * D + c4);
            float4 a = *(float4*)&os[r * 132 + c4];
            *(float4*)(out + (size_t)(row0 + r) * D + c4) =
                make_float4(fmaf(t0, xv.x, a.x), fmaf(t0, xv.y, a.y),
                            fmaf(t0, xv.z, a.z), fmaf(t0, xv.w, a.w));
        }
    }
}

// ---------------- launch -------------------------------------------------------
extern "C" void kernel_launch(void* const* d_in, const int* in_sizes, int n_in,
                              void* d_out, int out_size) {
    const float* x    = (const float*)d_in[0];
    const float* Wq   = (const float*)d_in[1];
    const float* bq   = (const float*)d_in[2];
    const float* Wk   = (const float*)d_in[3];
    const float* bk   = (const float*)d_in[4];
    const float* temp = (const float*)d_in[5];
    float* out = (float*)d_out;

    cudaFuncSetAttribute(k1b, cudaFuncAttributeMaxDynamicSharedMemorySize, SMEM1);
    cudaFuncSetAttribute(k2b, cudaFuncAttributeMaxDynamicSharedMemorySize, SMEM2);
    cudaFuncSetAttribute(k4b, cudaFuncAttributeMaxDynamicSharedMemorySize, SMEM4);

    const int nblk = (NROWS + 127) / 128;   // 1563

    zero_kernel<<<64, 256>>>();
    k1b<<<nblk, 512, SMEM1>>>(x, Wq, bq, Wk, bk);
    k2b<<<148, 512, SMEM2>>>(x);
    norm_kernel<<<(D * D + 511) / 512, 512>>>();
    for (int s = 1; s <= KPOW; s++)
        kstep_kernel<<<D, D>>>(temp, s);
    k4b<<<nblk, 512, SMEM4>>>(x, temp, out);
}

// round 9
// speedup vs baseline: 4.4537x; 1.5317x over previous
#include <cuda_runtime.h>
#include <cuda_bf16.h>

#define D      128
#define NROWS  200000
#define KPOW   10
#define S      136
typedef unsigned int u32;
typedef unsigned short u16;

// ---------------- scratch ------------------------------------------------------
__device__ __align__(16) u32 g_xh[(size_t)NROWS * 64];   // x  bf16 plane (packed x2)
__device__ __align__(16) u32 g_qh[(size_t)NROWS * 64];   // q  bf16 plane
__device__ __align__(16) u32 g_eh[(size_t)NROWS * 64];   // ek bf16 plane
__device__ __align__(16) u32 g_wh[256 * 64];             // Wq|Wk bf16 plane
__device__ __align__(16) u32 g_mh[D * D / 2];            // MT bf16 plane
__device__ float g_Z  [D];
__device__ float g_kvU[D * D];
__device__ float g_kqU[D * D];
__device__ float g_kv [D * D];
__device__ float g_kq [D * D];
__device__ float g_MT [D * D];
__device__ float g_bufA[D * D];
__device__ float g_bufB[D * D];

// ---------------- helpers ------------------------------------------------------
__device__ __forceinline__ u32 smem_u32(const void* p) {
    u32 a;
    asm("{ .reg .u64 t; cvta.to.shared.u64 t, %1; cvt.u32.u64 %0, t; }" : "=r"(a) : "l"(p));
    return a;
}
__device__ __forceinline__ u32 pbf2(float hi, float lo) {       // [hi:lo] packed bf16x2
    u32 r; asm("cvt.rn.bf16x2.f32 %0, %1, %2;" : "=r"(r) : "f"(hi), "f"(lo)); return r;
}
__device__ __forceinline__ float bflo(u32 w) { return __uint_as_float(w << 16); }
__device__ __forceinline__ float bfhi(u32 w) { return __uint_as_float(w & 0xffff0000u); }

#define CPA(dst, src, pb) asm volatile("cp.async.ca.shared.global [%0], [%1], 16, %2;" \
    :: "r"(dst), "l"(src), "r"(pb))
#define CPCOMMIT() asm volatile("cp.async.commit_group;" ::: "memory")
#define CPWAIT0()  asm volatile("cp.async.wait_group 0;" ::: "memory")
#define CPWAIT1()  asm volatile("cp.async.wait_group 1;" ::: "memory")

#define LDSM4(r, a)  asm volatile("ldmatrix.sync.aligned.m8n8.x4.shared.b16 {%0,%1,%2,%3}, [%4];" \
    : "=r"((r)[0]), "=r"((r)[1]), "=r"((r)[2]), "=r"((r)[3]) : "r"(a))
#define LDSM4T(r, a) asm volatile("ldmatrix.sync.aligned.m8n8.x4.trans.shared.b16 {%0,%1,%2,%3}, [%4];" \
    : "=r"((r)[0]), "=r"((r)[1]), "=r"((r)[2]), "=r"((r)[3]) : "r"(a))
#define LDSM2(r0, r1, a)  asm volatile("ldmatrix.sync.aligned.m8n8.x2.shared.b16 {%0,%1}, [%2];" \
    : "=r"(r0), "=r"(r1) : "r"(a))
#define LDSM2T(r0, r1, a) asm volatile("ldmatrix.sync.aligned.m8n8.x2.trans.shared.b16 {%0,%1}, [%2];" \
    : "=r"(r0), "=r"(r1) : "r"(a))
#define MMA(c, a, b0, b1) asm volatile( \
    "mma.sync.aligned.m16n8k16.row.col.f32.bf16.bf16.f32 " \
    "{%0,%1,%2,%3}, {%4,%5,%6,%7}, {%8,%9}, {%0,%1,%2,%3};" \
    : "+f"((c)[0]), "+f"((c)[1]), "+f"((c)[2]), "+f"((c)[3]) \
    : "r"((a)[0]), "r"((a)[1]), "r"((a)[2]), "r"((a)[3]), "r"(b0), "r"(b1))

// ---------------- prep: x->bf16 plane; W->plane; zero accumulators --------------
__global__ void prep_kernel(const float* __restrict__ x,
                            const float* __restrict__ Wq, const float* __restrict__ Wk) {
    const int tid = threadIdx.x, b = blockIdx.x;
    if (b < (NROWS + 127) / 128) {
        for (int i = tid; i < 8192; i += 256) {
            int n = b * 128 + (i >> 6), j = i & 63;
            if (n < NROWS) {
                float2 v = *(const float2*)(x + (size_t)n * D + j * 2);
                g_xh[(size_t)n * 64 + j] = pbf2(v.y, v.x);
            }
        }
    } else {
        if (tid < 128) g_Z[tid] = 0.f;
        for (int i = tid; i < D * D; i += 256) { g_kvU[i] = 0.f; g_kqU[i] = 0.f; }
        for (int i = tid; i < 8192; i += 256) {
            int r = i >> 6, j = i & 63;
            float2 v1 = *(const float2*)(Wq + r * D + j * 2);
            g_wh[r * 64 + j] = pbf2(v1.y, v1.x);
            float2 v2 = *(const float2*)(Wk + r * D + j * 2);
            g_wh[(r + 128) * 64 + j] = pbf2(v2.y, v2.x);
        }
    }
}

// ---------------- K1: q = softmax_row(xWq^T+bq), ek = exp(xWk^T+bk), Z += colsum
#define O1A 2048
#define O1B (O1A + 34816)
#define SMEM1 (O1B + 69632)             // 106496
__global__ __launch_bounds__(512, 1) void k1b(const float* __restrict__ bq,
                                              const float* __restrict__ bk) {
    extern __shared__ __align__(16) char sm[];
    const int tid = threadIdx.x, lane = tid & 31, wid = tid >> 5;
    const int row0 = blockIdx.x * 128;
    u32 sb = smem_u32(sm);
    float* sbq  = (float*)(sm);
    float* sbk  = (float*)(sm + 512);
    float* sinv = (float*)(sm + 1024);
    if (tid < 128) { sbq[tid] = bq[tid]; sbk[tid] = bk[tid]; }

    // stage A (x plane tile) + B (W plane) via cp.async
    #pragma unroll
    for (int i = 0; i < 4; i++) {                       // A: 128 rows x 16 chunks
        int idx = tid + 512 * i, r = idx >> 4, ch = idx & 15;
        int pb = (row0 + r < NROWS) ? 16 : 0;
        CPA(sb + O1A + (u32)(r * 272 + ch * 16),
            (const char*)(g_xh + (size_t)(row0 + r) * 64) + ch * 16, pb);
    }
    #pragma unroll
    for (int i = 0; i < 8; i++) {                       // B: 256 rows x 16 chunks
        int idx = tid + 512 * i, r = idx >> 4, ch = idx & 15;
        CPA(sb + O1B + (u32)(r * 272 + ch * 16),
            (const char*)(g_wh + r * 64) + ch * 16, 16);
    }
    CPCOMMIT(); CPWAIT0();
    __syncthreads();

    const int m0 = (wid >> 2) * 32, n0 = (wid & 3) * 64;
    float c[2][8][4];
    #pragma unroll
    for (int a = 0; a < 2; a++)
        #pragma unroll
        for (int b = 0; b < 8; b++)
            #pragma unroll
            for (int e = 0; e < 4; e++) c[a][b][e] = 0.f;

    const int arow = (lane & 7) + ((lane >> 3) & 1) * 8, acol = ((lane >> 4) & 1) * 8;
    const int brow = lane & 7,                           bcol = ((lane >> 3) & 1) * 8;

    #pragma unroll
    for (int s = 0; s < 8; s++) {
        int k0 = s * 16;
        u32 a[2][4];
        #pragma unroll
        for (int mt = 0; mt < 2; mt++)
            LDSM4(a[mt], sb + O1A + (u32)((m0 + 16 * mt + arow) * S + k0 + acol) * 2);
        #pragma unroll
        for (int nt = 0; nt < 8; nt++) {
            u32 b0, b1;
            LDSM2(b0, b1, sb + O1B + (u32)((n0 + 8 * nt + brow) * S + k0 + bcol) * 2);
            MMA(c[0][nt], a[0], b0, b1);
            MMA(c[1][nt], a[1], b0, b1);
        }
    }
    __syncthreads();

    // epilogue: exp(+bias) -> bf16 tiles in smem (overlay B region)
    char* qx = sm + O1B;                                // [128][136] bf16
    char* ex = sm + O1B + 34816;
    const int g = lane >> 2, t2 = (lane & 3) * 2;
    const bool isq = n0 < 128;
    #pragma unroll
    for (int mt = 0; mt < 2; mt++)
        #pragma unroll
        for (int nt = 0; nt < 8; nt++) {
            int col = n0 + nt * 8 + t2;
            int r1 = m0 + mt * 16 + g, r2 = r1 + 8;
            float bi0 = isq ? sbq[col] : sbk[col - 128];
            float bi1 = isq ? sbq[col + 1] : sbk[col - 127];
            float e00 = __expf(c[mt][nt][0] + bi0), e01 = __expf(c[mt][nt][1] + bi1);
            float e10 = __expf(c[mt][nt][2] + bi0), e11 = __expf(c[mt][nt][3] + bi1);
            if (isq) {
                *(u32*)(qx + r1 * 272 + col * 2) = pbf2(e01, e00);
                *(u32*)(qx + r2 * 272 + col * 2) = pbf2(e11, e10);
            } else {
                int cl = col - 128;
                bool a1 = (row0 + r1) < NROWS, a2 = (row0 + r2) < NROWS;
                *(u32*)(ex + r1 * 272 + cl * 2) = a1 ? pbf2(e01, e00) : 0u;
                *(u32*)(ex + r2 * 272 + cl * 2) = a2 ? pbf2(e11, e10) : 0u;
            }
        }
    __syncthreads();
    if (tid < 128) {                                    // q row sums
        const u32* qp = (const u32*)(qx + tid * 272);
        float s = 0.f;
        #pragma unroll 16
        for (int w = 0; w < 64; w++) { u32 v = qp[w]; s += bflo(v) + bfhi(v); }
        sinv[tid] = 1.f / s;
    } else if (tid < 256) {                             // ek column sums -> Z
        int cc = tid - 128;
        const u16* ep = (const u16*)ex;
        float s = 0.f;
        #pragma unroll 8
        for (int r = 0; r < 128; r++) s += __uint_as_float((u32)ep[r * 136 + cc] << 16);
        atomicAdd(&g_Z[cc], s);
    }
    __syncthreads();
    #pragma unroll
    for (int i = 0; i < 16; i++) {                      // write q/ek planes
        int idx = tid + 512 * i, r = idx >> 6, w = idx & 63;
        if (row0 + r < NROWS) {
            float iv = sinv[r];
            u32 qv = *(const u32*)(qx + r * 272 + w * 4);
            g_qh[(size_t)(row0 + r) * 64 + w] = pbf2(bfhi(qv) * iv, bflo(qv) * iv);
            g_eh[(size_t)(row0 + r) * 64 + w] = *(const u32*)(ex + r * 272 + w * 4);
        }
    }
}

// ---------------- K2: kvU = ek^T @ x, kqU = ek^T @ q (double-buffered) ---------
#define TS2 17408                       // [64][136] bf16 tile
#define BUF2 (3 * TS2)                  // 52224
#define SMEM2 (1024 + 2 * BUF2)         // 105472
__global__ __launch_bounds__(512, 1) void k2b() {
    extern __shared__ __align__(16) char sm[];
    const int tid = threadIdx.x, lane = tid & 31, wid = tid >> 5;
    u32 sb = smem_u32(sm);
    const int per = (NROWS + 295) / 296;
    int start = blockIdx.x * per;
    int end = start + per; if (end > NROWS) end = NROWS;
    int nch = (end - start + 63) / 64;

    const int d0 = (wid >> 2) * 32, cw = wid & 3;
    const bool isx = cw < 2;
    const int c0 = (cw & 1) * 64;
    float c[2][8][4];
    #pragma unroll
    for (int a = 0; a < 2; a++)
        #pragma unroll
        for (int b = 0; b < 8; b++)
            #pragma unroll
            for (int e = 0; e < 4; e++) c[a][b][e] = 0.f;

    const int tarow = (lane & 7) + ((lane >> 4) & 1) * 8, tacol = ((lane >> 3) & 1) * 8;
    const int tbrow = (lane & 7) + ((lane >> 3) & 1) * 8;

    // stage one chunk (ek, x, q planes) into buffer `bi`
    auto stage = [&](int ci, int bi) {
        u32 base = sb + 1024 + bi * BUF2;
        int n0 = start + ci * 64;
        #pragma unroll
        for (int i = 0; i < 6; i++) {
            int idx = tid + 512 * i;                    // 3072 = 3 tiles x 64 rows x 16
            int t = idx >> 10, rr = (idx >> 4) & 63, ch = idx & 15;
            const u32* src = (t == 0) ? g_eh : ((t == 1) ? g_xh : g_qh);
            int pb = (n0 + rr < end) ? 16 : 0;
            CPA(base + (u32)(t * TS2 + rr * 272 + ch * 16),
                (const char*)(src + (size_t)(n0 + rr) * 64) + ch * 16, pb);
        }
        CPCOMMIT();
    };

    stage(0, 0);
    for (int ci = 0; ci < nch; ci++) {
        if (ci + 1 < nch) { stage(ci + 1, (ci + 1) & 1); CPWAIT1(); }
        else               CPWAIT0();
        __syncthreads();
        u32 base = sb + 1024 + (ci & 1) * BUF2;
        u32 bA = base;                                  // ek tile
        u32 bB = base + (isx ? TS2 : 2 * TS2);          // x or q tile
        #pragma unroll
        for (int s = 0; s < 4; s++) {
            int k0 = s * 16;
            u32 a[2][4];
            #pragma unroll
            for (int mt = 0; mt < 2; mt++)
                LDSM4T(a[mt], bA + (u32)((k0 + tarow) * S + d0 + 16 * mt + tacol) * 2);
            #pragma unroll
            for (int nt = 0; nt < 8; nt++) {
                u32 b0, b1;
                LDSM2T(b0, b1, bB + (u32)((k0 + tbrow) * S + c0 + 8 * nt) * 2);
                MMA(c[0][nt], a[0], b0, b1);
                MMA(c[1][nt], a[1], b0, b1);
            }
        }
        __syncthreads();
    }
    float* dst = isx ? g_kvU : g_kqU;
    const int g = lane >> 2, t2 = (lane & 3) * 2;
    #pragma unroll
    for (int mt = 0; mt < 2; mt++)
        #pragma unroll
        for (int nt = 0; nt < 8; nt++) {
            int col = c0 + 8 * nt + t2;
            int r1 = d0 + 16 * mt + g, r2 = r1 + 8;
            atomicAdd(&dst[r1 * D + col],     c[mt][nt][0]);
            atomicAdd(&dst[r1 * D + col + 1], c[mt][nt][1]);
            atomicAdd(&dst[r2 * D + col],     c[mt][nt][2]);
            atomicAdd(&dst[r2 * D + col + 1], c[mt][nt][3]);
        }
}

// ---------------- K3 -----------------------------------------------------------
__global__ void norm_kernel() {
    int i = blockIdx.x * blockDim.x + threadIdx.x;
    if (i < D * D) {
        float inv = 1.f / g_Z[i >> 7];
        g_kv[i] = g_kvU[i] * inv;
        g_kq[i] = g_kqU[i] * inv;
    }
}

// ---------------- Kstep: B = A @ kq ; MT (+)= temp[step]*A^T; last -> bf16 -----
__global__ void kstep_kernel(const float* __restrict__ temp, int step) {
    const float* A; float* B;
    if (step == 1)     { A = g_kv;   B = g_bufA; }
    else if (step & 1) { A = g_bufB; B = g_bufA; }
    else               { A = g_bufA; B = g_bufB; }
    __shared__ float sA[D];
    int b = blockIdx.x, cc = threadIdx.x;
    sA[cc] = A[b * D + cc];
    __syncthreads();
    float acc = 0.f;
    #pragma unroll 8
    for (int j = 0; j < D; j++) acc = fmaf(sA[j], g_kq[j * D + cc], acc);
    B[b * D + cc] = acc;
    float mv = temp[step] * sA[cc];
    float nv = (step == 1) ? mv : (g_MT[cc * D + b] + mv);
    g_MT[cc * D + b] = nv;
    if (step == KPOW) {
        u16 h; asm("cvt.rn.bf16.f32 %0, %1;" : "=h"(h) : "f"(nv));
        ((u16*)g_mh)[cc * D + b] = h;
    }
}

// ---------------- K4: out = temp[0]*x + q @ M ----------------------------------
#define O4A 1024
#define O4B (O4A + 34816)
#define SMEM4 (O4B + 34816)             // 70656
__global__ __launch_bounds__(512, 1) void k4b(const float* __restrict__ x,
        const float* __restrict__ temp, float* __restrict__ out) {
    extern __shared__ __align__(16) char sm[];
    const int tid = threadIdx.x, lane = tid & 31, wid = tid >> 5;
    const int row0 = blockIdx.x * 128;
    u32 sb = smem_u32(sm);

    #pragma unroll
    for (int i = 0; i < 4; i++) {                       // A: q plane tile
        int idx = tid + 512 * i, r = idx >> 4, ch = idx & 15;
        int pb = (row0 + r < NROWS) ? 16 : 0;
        CPA(sb + O4A + (u32)(r * 272 + ch * 16),
            (const char*)(g_qh + (size_t)(row0 + r) * 64) + ch * 16, pb);
    }
    #pragma unroll
    for (int i = 0; i < 4; i++) {                       // B: MT plane
        int idx = tid + 512 * i, r = idx >> 4, ch = idx & 15;
        CPA(sb + O4B + (u32)(r * 272 + ch * 16), (const char*)g_mh + r * 256 + ch * 16, 16);
    }
    CPCOMMIT(); CPWAIT0();
    __syncthreads();

    const int m0 = (wid >> 2) * 32, n0 = (wid & 3) * 32;
    float c[2][4][4];
    #pragma unroll
    for (int a = 0; a < 2; a++)
        #pragma unroll
        for (int b = 0; b < 4; b++)
            #pragma unroll
            for (int e = 0; e < 4; e++) c[a][b][e] = 0.f;

    const int arow = (lane & 7) + ((lane >> 3) & 1) * 8, acol = ((lane >> 4) & 1) * 8;
    const int brow = lane & 7,                           bcol = ((lane >> 3) & 1) * 8;

    #pragma unroll
    for (int s = 0; s < 8; s++) {
        int k0 = s * 16;
        u32 a[2][4];
        #pragma unroll
        for (int mt = 0; mt < 2; mt++)
            LDSM4(a[mt], sb + O4A + (u32)((m0 + 16 * mt + arow) * S + k0 + acol) * 2);
        #pragma unroll
        for (int nt = 0; nt < 4; nt++) {
            u32 b0, b1;
            LDSM2(b0, b1, sb + O4B + (u32)((n0 + 8 * nt + brow) * S + k0 + bcol) * 2);
            MMA(c[0][nt], a[0], b0, b1);
            MMA(c[1][nt], a[1], b0, b1);
        }
    }
    __syncthreads();

    float* os = (float*)(sm + O4A);                     // [128][132] overlay
    const int g = lane >> 2, t2 = (lane & 3) * 2;
    #pragma unroll
    for (int mt = 0; mt < 2; mt++)
        #pragma unroll
        for (int nt = 0; nt < 4; nt++) {
            int col = n0 + nt * 8 + t2;
            int r1 = m0 + mt * 16 + g, r2 = r1 + 8;
            os[r1 * 132 + col] = c[mt][nt][0];  os[r1 * 132 + col + 1] = c[mt][nt][1];
            os[r2 * 132 + col] = c[mt][nt][2];  os[r2 * 132 + col + 1] = c[mt][nt][3];
        }
    __syncthreads();
    float t0 = temp[0];
    #pragma unroll
    for (int i = 0; i < 8; i++) {
        int idx = tid + 512 * i, r = idx >> 5, c4 = (idx & 31) << 2;
        if (row0 + r < NROWS) {
            float4 xv = *(const float4*)(x + (size_t)(row0 + r) * D + c4);
            float4 a = *(float4*)&os[r * 132 + c4];
            *(float4*)(out + (size_t)(row0 + r) * D + c4) =
                make_float4(fmaf(t0, xv.x, a.x), fmaf(t0, xv.y, a.y),
                            fmaf(t0, xv.z, a.z), fmaf(t0, xv.w, a.w));
        }
    }
}

// ---------------- launch -------------------------------------------------------
extern "C" void kernel_launch(void* const* d_in, const int* in_sizes, int n_in,
                              void* d_out, int out_size) {
    const float* x    = (const float*)d_in[0];
    const float* Wq   = (const float*)d_in[1];
    const float* bq   = (const float*)d_in[2];
    const float* Wk   = (const float*)d_in[3];
    const float* bk   = (const float*)d_in[4];
    const float* temp = (const float*)d_in[5];
    float* out = (float*)d_out;

    cudaFuncSetAttribute(k1b, cudaFuncAttributeMaxDynamicSharedMemorySize, SMEM1);
    cudaFuncSetAttribute(k2b, cudaFuncAttributeMaxDynamicSharedMemorySize, SMEM2);
    cudaFuncSetAttribute(k4b, cudaFuncAttributeMaxDynamicSharedMemorySize, SMEM4);

    const int nblk = (NROWS + 127) / 128;   // 1563

    prep_kernel<<<nblk + 1, 256>>>(x, Wq, Wk);
    k1b<<<nblk, 512, SMEM1>>>(bq, bk);
    k2b<<<296, 512, SMEM2>>>();
    norm_kernel<<<(D * D + 511) / 512, 512>>>();
    for (int s = 1; s <= KPOW; s++)
        kstep_kernel<<<D, D>>>(temp, s);
    k4b<<<nblk, 512, SMEM4>>>(x, temp, out);
}

// round 11
// speedup vs baseline: 4.7990x; 1.0775x over previous
#include <cuda_runtime.h>
#include <cuda_bf16.h>

#define D      128
#define NROWS  200000
#define KPOW   10
#define S      136
typedef unsigned int u32;
typedef unsigned short u16;

// ---------------- scratch ------------------------------------------------------
__device__ __align__(16) u32 g_xh[(size_t)NROWS * 64];   // x  bf16 plane (packed x2)
__device__ __align__(16) u32 g_qh[(size_t)NROWS * 64];   // q  bf16 plane
__device__ __align__(16) u32 g_eh[(size_t)NROWS * 64];   // ek bf16 plane
__device__ __align__(16) u32 g_wh[256 * 64];             // Wq|Wk bf16 plane
__device__ __align__(16) u32 g_mh[D * 64];               // MT bf16 plane
__device__ float g_Z  [D];
__device__ float g_kvU[D * D];
__device__ float g_kqU[D * D];

// ---------------- helpers ------------------------------------------------------
__device__ __forceinline__ u32 smem_u32(const void* p) {
    u32 a;
    asm("{ .reg .u64 t; cvta.to.shared.u64 t, %1; cvt.u32.u64 %0, t; }" : "=r"(a) : "l"(p));
    return a;
}
__device__ __forceinline__ u32 pbf2(float hi, float lo) {       // [hi:lo] packed bf16x2
    u32 r; asm("cvt.rn.bf16x2.f32 %0, %1, %2;" : "=r"(r) : "f"(hi), "f"(lo)); return r;
}
__device__ __forceinline__ float bflo(u32 w) { return __uint_as_float(w << 16); }
__device__ __forceinline__ float bfhi(u32 w) { return __uint_as_float(w & 0xffff0000u); }

#define CPA(dst, src, pb) asm volatile("cp.async.ca.shared.global [%0], [%1], 16, %2;" \
    :: "r"(dst), "l"(src), "r"(pb))
#define CPCOMMIT() asm volatile("cp.async.commit_group;" ::: "memory")
#define CPWAIT0()  asm volatile("cp.async.wait_group 0;" ::: "memory")
#define CPWAIT1()  asm volatile("cp.async.wait_group 1;" ::: "memory")

#define LDSM4(r, a)  asm volatile("ldmatrix.sync.aligned.m8n8.x4.shared.b16 {%0,%1,%2,%3}, [%4];" \
    : "=r"((r)[0]), "=r"((r)[1]), "=r"((r)[2]), "=r"((r)[3]) : "r"(a))
#define LDSM4T(r, a) asm volatile("ldmatrix.sync.aligned.m8n8.x4.trans.shared.b16 {%0,%1,%2,%3}, [%4];" \
    : "=r"((r)[0]), "=r"((r)[1]), "=r"((r)[2]), "=r"((r)[3]) : "r"(a))
#define LDSM2(r0, r1, a)  asm volatile("ldmatrix.sync.aligned.m8n8.x2.shared.b16 {%0,%1}, [%2];" \
    : "=r"(r0), "=r"(r1) : "r"(a))
#define LDSM2T(r0, r1, a) asm volatile("ldmatrix.sync.aligned.m8n8.x2.trans.shared.b16 {%0,%1}, [%2];" \
    : "=r"(r0), "=r"(r1) : "r"(a))
#define MMA(c, a, b0, b1) asm volatile( \
    "mma.sync.aligned.m16n8k16.row.col.f32.bf16.bf16.f32 " \
    "{%0,%1,%2,%3}, {%4,%5,%6,%7}, {%8,%9}, {%0,%1,%2,%3};" \
    : "+f"((c)[0]), "+f"((c)[1]), "+f"((c)[2]), "+f"((c)[3]) \
    : "r"((a)[0]), "r"((a)[1]), "r"((a)[2]), "r"((a)[3]), "r"(b0), "r"(b1))

// ---------------- prep: W->bf16 plane; zero accumulators (9 small blocks) ------
__global__ void prep_kernel(const float* __restrict__ Wq, const float* __restrict__ Wk) {
    const int tid = threadIdx.x, b = blockIdx.x;
    if (b == 0) {
        for (int i = tid; i < 8192; i += 256) {
            int r = i >> 6, j = i & 63;
            float2 v1 = *(const float2*)(Wq + r * D + j * 2);
            g_wh[r * 64 + j] = pbf2(v1.y, v1.x);
            float2 v2 = *(const float2*)(Wk + r * D + j * 2);
            g_wh[(r + 128) * 64 + j] = pbf2(v2.y, v2.x);
        }
    } else {
        int base = (b - 1) * 2048;
        for (int i = tid; i < 2048; i += 256) { g_kvU[base + i] = 0.f; g_kqU[base + i] = 0.f; }
        if (b == 1 && tid < 128) g_Z[tid] = 0.f;
    }
}

// ---------------- K1: q = softmax_row(xWq^T+bq), ek = exp(xWk^T+bk), Z += colsum
// also emits the x bf16 plane (g_xh) for K2.
#define O1A 2048
#define O1B (O1A + 34816)
#define SMEM1 (O1B + 69632)             // 106496
__global__ __launch_bounds__(512, 1) void k1b(const float* __restrict__ x,
        const float* __restrict__ bq, const float* __restrict__ bk) {
    extern __shared__ __align__(16) char sm[];
    const int tid = threadIdx.x, lane = tid & 31, wid = tid >> 5;
    const int row0 = blockIdx.x * 128;
    u32 sb = smem_u32(sm);
    float* sbq  = (float*)(sm);
    float* sbk  = (float*)(sm + 512);
    float* sinv = (float*)(sm + 1024);
    if (tid < 128) { sbq[tid] = bq[tid]; sbk[tid] = bk[tid]; }

    #pragma unroll
    for (int i = 0; i < 8; i++) {                       // B: W plane via cp.async
        int idx = tid + 512 * i, r = idx >> 4, ch = idx & 15;
        CPA(sb + O1B + (u32)(r * 272 + ch * 16),
            (const char*)(g_wh + r * 64) + ch * 16, 16);
    }
    CPCOMMIT();
    #pragma unroll
    for (int i = 0; i < 16; i++) {                      // A: x fp32 -> bf16 + plane (8192 u32)
        int idx = tid + 512 * i, r = idx >> 6, j2 = idx & 63;
        u32 p = 0u;
        if (row0 + r < NROWS) {
            float2 v = *(const float2*)(x + (size_t)(row0 + r) * D + j2 * 2);
            p = pbf2(v.y, v.x);
            g_xh[(size_t)(row0 + r) * 64 + j2] = p;
        }
        *(u32*)(sm + O1A + (u32)(r * 272 + j2 * 4)) = p;
    }
    CPWAIT0();
    __syncthreads();

    const int m0 = (wid >> 2) * 32, n0 = (wid & 3) * 64;
    float c[2][8][4];
    #pragma unroll
    for (int a = 0; a < 2; a++)
        #pragma unroll
        for (int b = 0; b < 8; b++)
            #pragma unroll
            for (int e = 0; e < 4; e++) c[a][b][e] = 0.f;

    const int arow = (lane & 7) + ((lane >> 3) & 1) * 8, acol = ((lane >> 4) & 1) * 8;
    const int brow = lane & 7,                           bcol = ((lane >> 3) & 1) * 8;

    #pragma unroll
    for (int s = 0; s < 8; s++) {
        int k0 = s * 16;
        u32 a[2][4];
        #pragma unroll
        for (int mt = 0; mt < 2; mt++)
            LDSM4(a[mt], sb + O1A + (u32)((m0 + 16 * mt + arow) * S + k0 + acol) * 2);
        #pragma unroll
        for (int nt = 0; nt < 8; nt++) {
            u32 b0, b1;
            LDSM2(b0, b1, sb + O1B + (u32)((n0 + 8 * nt + brow) * S + k0 + bcol) * 2);
            MMA(c[0][nt], a[0], b0, b1);
            MMA(c[1][nt], a[1], b0, b1);
        }
    }
    __syncthreads();

    char* qx = sm + O1B;                                // [128][136] bf16 overlay
    char* ex = sm + O1B + 34816;
    const int g = lane >> 2, t2 = (lane & 3) * 2;
    const bool isq = n0 < 128;
    #pragma unroll
    for (int mt = 0; mt < 2; mt++)
        #pragma unroll
        for (int nt = 0; nt < 8; nt++) {
            int col = n0 + nt * 8 + t2;
            int r1 = m0 + mt * 16 + g, r2 = r1 + 8;
            float bi0 = isq ? sbq[col] : sbk[col - 128];
            float bi1 = isq ? sbq[col + 1] : sbk[col - 127];
            float e00 = __expf(c[mt][nt][0] + bi0), e01 = __expf(c[mt][nt][1] + bi1);
            float e10 = __expf(c[mt][nt][2] + bi0), e11 = __expf(c[mt][nt][3] + bi1);
            if (isq) {
                *(u32*)(qx + r1 * 272 + col * 2) = pbf2(e01, e00);
                *(u32*)(qx + r2 * 272 + col * 2) = pbf2(e11, e10);
            } else {
                int cl = col - 128;
                bool a1 = (row0 + r1) < NROWS, a2 = (row0 + r2) < NROWS;
                *(u32*)(ex + r1 * 272 + cl * 2) = a1 ? pbf2(e01, e00) : 0u;
                *(u32*)(ex + r2 * 272 + cl * 2) = a2 ? pbf2(e11, e10) : 0u;
            }
        }
    __syncthreads();
    if (tid < 128) {                                    // q row sums
        const u32* qp = (const u32*)(qx + tid * 272);
        float s = 0.f;
        #pragma unroll 16
        for (int w = 0; w < 64; w++) { u32 v = qp[w]; s += bflo(v) + bfhi(v); }
        sinv[tid] = 1.f / s;
    } else if (tid < 256) {                             // ek column sums -> Z
        int cc = tid - 128;
        const u16* ep = (const u16*)ex;
        float s = 0.f;
        #pragma unroll 8
        for (int r = 0; r < 128; r++) s += __uint_as_float((u32)ep[r * 136 + cc] << 16);
        atomicAdd(&g_Z[cc], s);
    }
    __syncthreads();
    #pragma unroll
    for (int i = 0; i < 16; i++) {                      // write q/ek planes
        int idx = tid + 512 * i, r = idx >> 6, w = idx & 63;
        if (row0 + r < NROWS) {
            float iv = sinv[r];
            u32 qv = *(const u32*)(qx + r * 272 + w * 4);
            g_qh[(size_t)(row0 + r) * 64 + w] = pbf2(bfhi(qv) * iv, bflo(qv) * iv);
            g_eh[(size_t)(row0 + r) * 64 + w] = *(const u32*)(ex + r * 272 + w * 4);
        }
    }
}

// ---------------- K2: kvU = ek^T @ x, kqU = ek^T @ q (double-buffered) ---------
#define TS2 17408                       // [64][136] bf16 tile
#define BUF2 (3 * TS2)                  // 52224
#define SMEM2 (1024 + 2 * BUF2)         // 105472
__global__ __launch_bounds__(512, 1) void k2b() {
    extern __shared__ __align__(16) char sm[];
    const int tid = threadIdx.x, lane = tid & 31, wid = tid >> 5;
    u32 sb = smem_u32(sm);
    const int per = (NROWS + 295) / 296;
    int start = blockIdx.x * per;
    int end = start + per; if (end > NROWS) end = NROWS;
    int nch = (end - start + 63) / 64;

    const int d0 = (wid >> 2) * 32, cw = wid & 3;
    const bool isx = cw < 2;
    const int c0 = (cw & 1) * 64;
    float c[2][8][4];
    #pragma unroll
    for (int a = 0; a < 2; a++)
        #pragma unroll
        for (int b = 0; b < 8; b++)
            #pragma unroll
            for (int e = 0; e < 4; e++) c[a][b][e] = 0.f;

    const int tarow = (lane & 7) + ((lane >> 4) & 1) * 8, tacol = ((lane >> 3) & 1) * 8;
    const int tbrow = (lane & 7) + ((lane >> 3) & 1) * 8;

    auto stage = [&](int ci, int bi) {
        u32 base = sb + 1024 + bi * BUF2;
        int n0 = start + ci * 64;
        #pragma unroll
        for (int i = 0; i < 6; i++) {
            int idx = tid + 512 * i;
            int t = idx >> 10, rr = (idx >> 4) & 63, ch = idx & 15;
            const u32* src = (t == 0) ? g_eh : ((t == 1) ? g_xh : g_qh);
            int pb = (n0 + rr < end) ? 16 : 0;
            CPA(base + (u32)(t * TS2 + rr * 272 + ch * 16),
                (const char*)(src + (size_t)(n0 + rr) * 64) + ch * 16, pb);
        }
        CPCOMMIT();
    };

    stage(0, 0);
    for (int ci = 0; ci < nch; ci++) {
        if (ci + 1 < nch) { stage(ci + 1, (ci + 1) & 1); CPWAIT1(); }
        else               CPWAIT0();
        __syncthreads();
        u32 base = sb + 1024 + (ci & 1) * BUF2;
        u32 bA = base;
        u32 bB = base + (isx ? TS2 : 2 * TS2);
        #pragma unroll
        for (int s = 0; s < 4; s++) {
            int k0 = s * 16;
            u32 a[2][4];
            #pragma unroll
            for (int mt = 0; mt < 2; mt++)
                LDSM4T(a[mt], bA + (u32)((k0 + tarow) * S + d0 + 16 * mt + tacol) * 2);
            #pragma unroll
            for (int nt = 0; nt < 8; nt++) {
                u32 b0, b1;
                LDSM2T(b0, b1, bB + (u32)((k0 + tbrow) * S + c0 + 8 * nt) * 2);
                MMA(c[0][nt], a[0], b0, b1);
                MMA(c[1][nt], a[1], b0, b1);
            }
        }
        __syncthreads();
    }
    float* dst = isx ? g_kvU : g_kqU;
    const int g = lane >> 2, t2 = (lane & 3) * 2;
    #pragma unroll
    for (int mt = 0; mt < 2; mt++)
        #pragma unroll
        for (int nt = 0; nt < 8; nt++) {
            int col = c0 + 8 * nt + t2;
            int r1 = d0 + 16 * mt + g, r2 = r1 + 8;
            atomicAdd(&dst[r1 * D + col],     c[mt][nt][0]);
            atomicAdd(&dst[r1 * D + col + 1], c[mt][nt][1]);
            atomicAdd(&dst[r2 * D + col],     c[mt][nt][2]);
            atomicAdd(&dst[r2 * D + col + 1], c[mt][nt][3]);
        }
}

// ---------------- chain: normalize + K-step Horner chain + MT plane (1 block) --
#define CH_IZ  0
#define CH_TMP 512
#define CH_KQ  1024
#define CH_A0  (CH_KQ + 34816)
#define CH_A1  (CH_A0 + 34816)
#define CH_M   (CH_A1 + 34816)
#define SMEMC  (CH_M + 65536)           // 171008
__global__ __launch_bounds__(512, 1) void chaink(const float* __restrict__ temp) {
    extern __shared__ __align__(16) char sm[];
    const int tid = threadIdx.x, lane = tid & 31, wid = tid >> 5;
    u32 sb = smem_u32(sm);
    float* izv = (float*)(sm + CH_IZ);
    float* tmp = (float*)(sm + CH_TMP);
    float* Mf  = (float*)(sm + CH_M);
    if (tid < 128) izv[tid] = 1.f / g_Z[tid];
    if (tid < KPOW + 1) tmp[tid] = temp[tid];
    __syncthreads();
    #pragma unroll
    for (int i = 0; i < 16; i++) {                      // kq,kv -> bf16 tiles; M = 0
        int idx = tid + 512 * i, r = idx >> 6, n2 = idx & 63;
        float iv = izv[r];
        float2 vq = *(const float2*)(g_kqU + r * D + n2 * 2);
        *(u32*)(sm + CH_KQ + r * 272 + n2 * 4) = pbf2(vq.y * iv, vq.x * iv);
        float2 vv = *(const float2*)(g_kvU + r * D + n2 * 2);
        *(u32*)(sm + CH_A0 + r * 272 + n2 * 4) = pbf2(vv.y * iv, vv.x * iv);
        Mf[idx] = 0.f; Mf[idx + 8192] = 0.f;
    }
    __syncthreads();

    const int m0 = (wid >> 2) * 32, n0 = (wid & 3) * 32;
    const int arow = (lane & 7) + ((lane >> 3) & 1) * 8, acol = ((lane >> 4) & 1) * 8;
    const int tbrow = (lane & 7) + ((lane >> 3) & 1) * 8;
    const int g = lane >> 2, t2 = (lane & 3) * 2;

    int cur = 0;
    for (int s = 1; s <= KPOW; s++) {
        u32 aoff = cur ? CH_A1 : CH_A0;
        float t = tmp[s];
        #pragma unroll
        for (int i = 0; i < 16; i++) {                  // M += temp[s] * A
            int idx = tid + 512 * i, m = idx >> 6, n2 = idx & 63;
            u32 v = *(u32*)(sm + aoff + m * 272 + n2 * 4);
            Mf[m * 128 + n2 * 2]     += t * bflo(v);
            Mf[m * 128 + n2 * 2 + 1] += t * bfhi(v);
        }
        if (s == KPOW) break;
        float c[2][4][4];
        #pragma unroll
        for (int a = 0; a < 2; a++)
            #pragma unroll
            for (int b = 0; b < 4; b++)
                #pragma unroll
                for (int e = 0; e < 4; e++) c[a][b][e] = 0.f;
        #pragma unroll
        for (int s8 = 0; s8 < 8; s8++) {                // Anew = A @ kq
            int k0 = s8 * 16;
            u32 a[2][4];
            #pragma unroll
            for (int mt = 0; mt < 2; mt++)
                LDSM4(a[mt], sb + aoff + (u32)((m0 + 16 * mt + arow) * S + k0 + acol) * 2);
            #pragma unroll
            for (int nt = 0; nt < 4; nt++) {
                u32 b0, b1;
                LDSM2T(b0, b1, sb + CH_KQ + (u32)((k0 + tbrow) * S + n0 + 8 * nt) * 2);
                MMA(c[0][nt], a[0], b0, b1);
                MMA(c[1][nt], a[1], b0, b1);
            }
        }
        u32 noff = cur ? CH_A0 : CH_A1;
        #pragma unroll
        for (int mt = 0; mt < 2; mt++)
            #pragma unroll
            for (int nt = 0; nt < 4; nt++) {
                int col = n0 + nt * 8 + t2;
                int r1 = m0 + mt * 16 + g, r2 = r1 + 8;
                *(u32*)(sm + noff + r1 * 272 + col * 2) = pbf2(c[mt][nt][1], c[mt][nt][0]);
                *(u32*)(sm + noff + r2 * 272 + col * 2) = pbf2(c[mt][nt][3], c[mt][nt][2]);
            }
        __syncthreads();
        cur ^= 1;
    }
    __syncthreads();
    #pragma unroll
    for (int i = 0; i < 16; i++) {                      // g_mh[n][k] = bf16(M[k][n])
        int idx = tid + 512 * i, n = idx & 127, kk = idx >> 7;
        g_mh[n * 64 + kk] = pbf2(Mf[(2 * kk + 1) * 128 + n], Mf[2 * kk * 128 + n]);
    }
}

// ---------------- K4: out = temp[0]*x + q @ M ----------------------------------
#define O4A 1024
#define O4B (O4A + 34816)
#define SMEM4 (O4B + 34816)             // 70656
__global__ __launch_bounds__(512, 1) void k4b(const float* __restrict__ x,
        const float* __restrict__ temp, float* __restrict__ out) {
    extern __shared__ __align__(16) char sm[];
    const int tid = threadIdx.x, lane = tid & 31, wid = tid >> 5;
    const int row0 = blockIdx.x * 128;
    u32 sb = smem_u32(sm);

    #pragma unroll
    for (int i = 0; i < 4; i++) {                       // A: q plane tile
        int idx = tid + 512 * i, r = idx >> 4, ch = idx & 15;
        int pb = (row0 + r < NROWS) ? 16 : 0;
        CPA(sb + O4A + (u32)(r * 272 + ch * 16),
            (const char*)(g_qh + (size_t)(row0 + r) * 64) + ch * 16, pb);
    }
    #pragma unroll
    for (int i = 0; i < 4; i++) {                       // B: MT plane
        int idx = tid + 512 * i, r = idx >> 4, ch = idx & 15;
        CPA(sb + O4B + (u32)(r * 272 + ch * 16), (const char*)g_mh + r * 256 + ch * 16, 16);
    }
    CPCOMMIT(); CPWAIT0();
    __syncthreads();

    const int m0 = (wid >> 2) * 32, n0 = (wid & 3) * 32;
    float c[2][4][4];
    #pragma unroll
    for (int a = 0; a < 2; a++)
        #pragma unroll
        for (int b = 0; b < 4; b++)
            #pragma unroll
            for (int e = 0; e < 4; e++) c[a][b][e] = 0.f;

    const int arow = (lane & 7) + ((lane >> 3) & 1) * 8, acol = ((lane >> 4) & 1) * 8;
    const int brow = lane & 7,                           bcol = ((lane >> 3) & 1) * 8;

    #pragma unroll
    for (int s = 0; s < 8; s++) {
        int k0 = s * 16;
        u32 a[2][4];
        #pragma unroll
        for (int mt = 0; mt < 2; mt++)
            LDSM4(a[mt], sb + O4A + (u32)((m0 + 16 * mt + arow) * S + k0 + acol) * 2);
        #pragma unroll
        for (int nt = 0; nt < 4; nt++) {
            u32 b0, b1;
            LDSM2(b0, b1, sb + O4B + (u32)((n0 + 8 * nt + brow) * S + k0 + bcol) * 2);
            MMA(c[0][nt], a[0], b0, b1);
            MMA(c[1][nt], a[1], b0, b1);
        }
    }
    __syncthreads();

    float* os = (float*)(sm + O4A);                     // [128][132] overlay
    const int g = lane >> 2, t2 = (lane & 3) * 2;
    #pragma unroll
    for (int mt = 0; mt < 2; mt++)
        #pragma unroll
        for (int nt = 0; nt < 4; nt++) {
            int col = n0 + nt * 8 + t2;
            int r1 = m0 + mt * 16 + g, r2 = r1 + 8;
            os[r1 * 132 + col] = c[mt][nt][0];  os[r1 * 132 + col + 1] = c[mt][nt][1];
            os[r2 * 132 + col] = c[mt][nt][2];  os[r2 * 132 + col + 1] = c[mt][nt][3];
        }
    __syncthreads();
    float t0 = temp[0];
    #pragma unroll
    for (int i = 0; i < 8; i++) {
        int idx = tid + 512 * i, r = idx >> 5, c4 = (idx & 31) << 2;
        if (row0 + r < NROWS) {
            float4 xv = *(const float4*)(x + (size_t)(row0 + r) * D + c4);
            float4 a = *(float4*)&os[r * 132 + c4];
            *(float4*)(out + (size_t)(row0 + r) * D + c4) =
                make_float4(fmaf(t0, xv.x, a.x), fmaf(t0, xv.y, a.y),
                            fmaf(t0, xv.z, a.z), fmaf(t0, xv.w, a.w));
        }
    }
}

// ---------------- launch -------------------------------------------------------
extern "C" void kernel_launch(void* const* d_in, const int* in_sizes, int n_in,
                              void* d_out, int out_size) {
    const float* x    = (const float*)d_in[0];
    const float* Wq   = (const float*)d_in[1];
    const float* bq   = (const float*)d_in[2];
    const float* Wk   = (const float*)d_in[3];
    const float* bk   = (const float*)d_in[4];
    const float* temp = (const float*)d_in[5];
    float* out = (float*)d_out;

    cudaFuncSetAttribute(k1b,    cudaFuncAttributeMaxDynamicSharedMemorySize, SMEM1);
    cudaFuncSetAttribute(k2b,    cudaFuncAttributeMaxDynamicSharedMemorySize, SMEM2);
    cudaFuncSetAttribute(chaink, cudaFuncAttributeMaxDynamicSharedMemorySize, SMEMC);
    cudaFuncSetAttribute(k4b,    cudaFuncAttributeMaxDynamicSharedMemorySize, SMEM4);

    const int nblk = (NROWS + 127) / 128;   // 1563

    prep_kernel<<<9, 256>>>(Wq, Wk);
    k1b<<<nblk, 512, SMEM1>>>(x, bq, bk);
    k2b<<<296, 512, SMEM2>>>();
    chaink<<<1, 512, SMEMC>>>(temp);
    k4b<<<nblk, 512, SMEM4>>>(x, temp, out);
}

// round 13
// speedup vs baseline: 5.0815x; 1.0589x over previous
#include <cuda_runtime.h>
#include <cuda_bf16.h>

#define D      128
#define NROWS  200000
#define KPOW   10
#define S      136
#define NTILES 1563
typedef unsigned int u32;
typedef unsigned short u16;

// ---------------- scratch ------------------------------------------------------
__device__ __align__(16) u32 g_xh[(size_t)NROWS * 64];   // x  bf16 plane (packed x2)
__device__ __align__(16) u32 g_qh[(size_t)NROWS * 64];   // q  bf16 plane
__device__ __align__(16) u32 g_eh[(size_t)NROWS * 64];   // ek bf16 plane
__device__ __align__(16) u32 g_wh[256 * 64];             // Wq|Wk bf16 plane
__device__ __align__(16) u32 g_mh[D * 64];               // MT bf16 plane
__device__ float g_Z  [D];
__device__ float g_kvU[D * D];
__device__ float g_kqU[D * D];

// ---------------- helpers ------------------------------------------------------
__device__ __forceinline__ u32 smem_u32(const void* p) {
    u32 a;
    asm("{ .reg .u64 t; cvta.to.shared.u64 t, %1; cvt.u32.u64 %0, t; }" : "=r"(a) : "l"(p));
    return a;
}
__device__ __forceinline__ u32 pbf2(float hi, float lo) {
    u32 r; asm("cvt.rn.bf16x2.f32 %0, %1, %2;" : "=r"(r) : "f"(hi), "f"(lo)); return r;
}
__device__ __forceinline__ float bflo(u32 w) { return __uint_as_float(w << 16); }
__device__ __forceinline__ float bfhi(u32 w) { return __uint_as_float(w & 0xffff0000u); }

#define CPA(dst, src, pb) asm volatile("cp.async.ca.shared.global [%0], [%1], 16, %2;" \
    :: "r"(dst), "l"(src), "r"(pb))
#define CPCOMMIT() asm volatile("cp.async.commit_group;" ::: "memory")
#define CPWAIT0()  asm volatile("cp.async.wait_group 0;" ::: "memory")
#define CPWAIT1()  asm volatile("cp.async.wait_group 1;" ::: "memory")

#define LDSM4(r, a)  asm volatile("ldmatrix.sync.aligned.m8n8.x4.shared.b16 {%0,%1,%2,%3}, [%4];" \
    : "=r"((r)[0]), "=r"((r)[1]), "=r"((r)[2]), "=r"((r)[3]) : "r"(a))
#define LDSM4T(r, a) asm volatile("ldmatrix.sync.aligned.m8n8.x4.trans.shared.b16 {%0,%1,%2,%3}, [%4];" \
    : "=r"((r)[0]), "=r"((r)[1]), "=r"((r)[2]), "=r"((r)[3]) : "r"(a))
#define LDSM2(r0, r1, a)  asm volatile("ldmatrix.sync.aligned.m8n8.x2.shared.b16 {%0,%1}, [%2];" \
    : "=r"(r0), "=r"(r1) : "r"(a))
#define LDSM2T(r0, r1, a) asm volatile("ldmatrix.sync.aligned.m8n8.x2.trans.shared.b16 {%0,%1}, [%2];" \
    : "=r"(r0), "=r"(r1) : "r"(a))
#define MMA(c, a, b0, b1) asm volatile( \
    "mma.sync.aligned.m16n8k16.row.col.f32.bf16.bf16.f32 " \
    "{%0,%1,%2,%3}, {%4,%5,%6,%7}, {%8,%9}, {%0,%1,%2,%3};" \
    : "+f"((c)[0]), "+f"((c)[1]), "+f"((c)[2]), "+f"((c)[3]) \
    : "r"((a)[0]), "r"((a)[1]), "r"((a)[2]), "r"((a)[3]), "r"(b0), "r"(b1))

// ---------------- prep: W->bf16 plane; zero accumulators -----------------------
__global__ void prep_kernel(const float* __restrict__ Wq, const float* __restrict__ Wk) {
    const int tid = threadIdx.x, b = blockIdx.x;
    if (b == 0) {
        for (int i = tid; i < 8192; i += 256) {
            int r = i >> 6, j = i & 63;
            float2 v1 = *(const float2*)(Wq + r * D + j * 2);
            g_wh[r * 64 + j] = pbf2(v1.y, v1.x);
            float2 v2 = *(const float2*)(Wk + r * D + j * 2);
            g_wh[(r + 128) * 64 + j] = pbf2(v2.y, v2.x);
        }
    } else {
        int base = (b - 1) * 2048;
        for (int i = tid; i < 2048; i += 256) { g_kvU[base + i] = 0.f; g_kqU[base + i] = 0.f; }
        if (b == 1 && tid < 128) g_Z[tid] = 0.f;
    }
}

// ---------------- K1 (persistent): q/ek logits, softmax, planes, Z -------------
#define O1B  2048
#define O1X0 (O1B + 69632)
#define O1X1 (O1X0 + 34816)
#define O1Q  (O1X1 + 34816)
#define O1E  (O1Q + 34816)
#define SMEM1 (O1E + 34816)             // 210944
__device__ __forceinline__ void k1_stage(const float* __restrict__ x, int row0,
                                         char* sm, u32 off, int tid) {
    #pragma unroll
    for (int i = 0; i < 16; i++) {
        int idx = tid + 512 * i, r = idx >> 6, j2 = idx & 63;
        u32 p = 0u;
        if (row0 + r < NROWS) {
            float2 v = *(const float2*)(x + (size_t)(row0 + r) * D + j2 * 2);
            p = pbf2(v.y, v.x);
            g_xh[(size_t)(row0 + r) * 64 + j2] = p;
        }
        *(u32*)(sm + off + (u32)(r * 272 + j2 * 4)) = p;
    }
}
__global__ __launch_bounds__(512, 1) void k1c(const float* __restrict__ x,
        const float* __restrict__ bq, const float* __restrict__ bk) {
    extern __shared__ __align__(16) char sm[];
    const int tid = threadIdx.x, lane = tid & 31, wid = tid >> 5;
    u32 sb = smem_u32(sm);
    float* sbq  = (float*)(sm);
    float* sbk  = (float*)(sm + 512);
    float* sinv = (float*)(sm + 1024);
    float* scol = (float*)(sm + 1536);
    if (tid < 128) { sbq[tid] = bq[tid]; sbk[tid] = bk[tid]; scol[tid] = 0.f; }

    const int ts = (NTILES * blockIdx.x) / 148;
    const int te = (NTILES * (blockIdx.x + 1)) / 148;

    #pragma unroll
    for (int i = 0; i < 8; i++) {                       // W plane (once per block)
        int idx = tid + 512 * i, r = idx >> 4, ch = idx & 15;
        CPA(sb + O1B + (u32)(r * 272 + ch * 16),
            (const char*)(g_wh + r * 64) + ch * 16, 16);
    }
    CPCOMMIT();
    k1_stage(x, ts * 128, sm, O1X0, tid);
    CPWAIT0();
    __syncthreads();

    const int m0 = (wid >> 2) * 32, n0 = (wid & 3) * 64;
    const int arow = (lane & 7) + ((lane >> 3) & 1) * 8, acol = ((lane >> 4) & 1) * 8;
    const int brow = lane & 7,                           bcol = ((lane >> 3) & 1) * 8;
    const int g = lane >> 2, t2 = (lane & 3) * 2;
    const bool isq = n0 < 128;

    for (int t = ts; t < te; t++) {
        const int row0 = t * 128;
        const u32 xb = sb + (((t - ts) & 1) ? O1X1 : O1X0);

        float c[2][8][4];
        #pragma unroll
        for (int a = 0; a < 2; a++)
            #pragma unroll
            for (int b = 0; b < 8; b++)
                #pragma unroll
                for (int e = 0; e < 4; e++) c[a][b][e] = 0.f;

        #pragma unroll
        for (int s = 0; s < 8; s++) {
            int k0 = s * 16;
            u32 a[2][4];
            #pragma unroll
            for (int mt = 0; mt < 2; mt++)
                LDSM4(a[mt], xb + (u32)((m0 + 16 * mt + arow) * S + k0 + acol) * 2);
            #pragma unroll
            for (int nt = 0; nt < 8; nt++) {
                u32 b0, b1;
                LDSM2(b0, b1, sb + O1B + (u32)((n0 + 8 * nt + brow) * S + k0 + bcol) * 2);
                MMA(c[0][nt], a[0], b0, b1);
                MMA(c[1][nt], a[1], b0, b1);
            }
        }

        if (t + 1 < te)                                  // overlap staging with epilogue
            k1_stage(x, (t + 1) * 128, sm, ((t - ts) & 1) ? O1X0 : O1X1, tid);

        char* qx = sm + O1Q;
        char* ex = sm + O1E;
        #pragma unroll
        for (int mt = 0; mt < 2; mt++)
            #pragma unroll
            for (int nt = 0; nt < 8; nt++) {
                int col = n0 + nt * 8 + t2;
                int r1 = m0 + mt * 16 + g, r2 = r1 + 8;
                float bi0 = isq ? sbq[col] : sbk[col - 128];
                float bi1 = isq ? sbq[col + 1] : sbk[col - 127];
                float e00 = __expf(c[mt][nt][0] + bi0), e01 = __expf(c[mt][nt][1] + bi1);
                float e10 = __expf(c[mt][nt][2] + bi0), e11 = __expf(c[mt][nt][3] + bi1);
                if (isq) {
                    *(u32*)(qx + r1 * 272 + col * 2) = pbf2(e01, e00);
                    *(u32*)(qx + r2 * 272 + col * 2) = pbf2(e11, e10);
                } else {
                    int cl = col - 128;
                    bool a1 = (row0 + r1) < NROWS, a2 = (row0 + r2) < NROWS;
                    *(u32*)(ex + r1 * 272 + cl * 2) = a1 ? pbf2(e01, e00) : 0u;
                    *(u32*)(ex + r2 * 272 + cl * 2) = a2 ? pbf2(e11, e10) : 0u;
                }
            }
        __syncthreads();
        if (tid < 128) {                                 // q row sums
            const u32* qp = (const u32*)(qx + tid * 272);
            float s = 0.f;
            #pragma unroll 16
            for (int w = 0; w < 64; w++) { u32 v = qp[w]; s += bflo(v) + bfhi(v); }
            sinv[tid] = 1.f / s;
        } else if (tid < 256) {                          // ek column sums -> scol
            int cc = tid - 128;
            const u16* ep = (const u16*)ex;
            float s = 0.f;
            #pragma unroll 8
            for (int r = 0; r < 128; r++) s += __uint_as_float((u32)ep[r * 136 + cc] << 16);
            scol[cc] += s;
        }
        __syncthreads();
        #pragma unroll
        for (int i = 0; i < 16; i++) {                   // plane writes
            int idx = tid + 512 * i, r = idx >> 6, w = idx & 63;
            if (row0 + r < NROWS) {
                float iv = sinv[r];
                u32 qv = *(const u32*)(qx + r * 272 + w * 4);
                g_qh[(size_t)(row0 + r) * 64 + w] = pbf2(bfhi(qv) * iv, bflo(qv) * iv);
                g_eh[(size_t)(row0 + r) * 64 + w] = *(const u32*)(ex + r * 272 + w * 4);
            }
        }
        __syncthreads();
    }
    if (tid < 128) atomicAdd(&g_Z[tid], scol[tid]);
}

// ---------------- K2: kvU = ek^T @ x, kqU = ek^T @ q (double-buffered) ---------
#define TS2 17408
#define BUF2 (3 * TS2)
#define SMEM2 (1024 + 2 * BUF2)         // 105472
__global__ __launch_bounds__(512, 1) void k2b() {
    extern __shared__ __align__(16) char sm[];
    const int tid = threadIdx.x, lane = tid & 31, wid = tid >> 5;
    u32 sb = smem_u32(sm);
    const int per = (NROWS + 295) / 296;
    int start = blockIdx.x * per;
    int end = start + per; if (end > NROWS) end = NROWS;
    int nch = (end - start + 63) / 64;

    const int d0 = (wid >> 2) * 32, cw = wid & 3;
    const bool isx = cw < 2;
    const int c0 = (cw & 1) * 64;
    float c[2][8][4];
    #pragma unroll
    for (int a = 0; a < 2; a++)
        #pragma unroll
        for (int b = 0; b < 8; b++)
            #pragma unroll
            for (int e = 0; e < 4; e++) c[a][b][e] = 0.f;

    const int tarow = (lane & 7) + ((lane >> 4) & 1) * 8, tacol = ((lane >> 3) & 1) * 8;
    const int tbrow = (lane & 7) + ((lane >> 3) & 1) * 8;

    auto stage = [&](int ci, int bi) {
        u32 base = sb + 1024 + bi * BUF2;
        int n0 = start + ci * 64;
        #pragma unroll
        for (int i = 0; i < 6; i++) {
            int idx = tid + 512 * i;
            int t = idx >> 10, rr = (idx >> 4) & 63, ch = idx & 15;
            const u32* src = (t == 0) ? g_eh : ((t == 1) ? g_xh : g_qh);
            int pb = (n0 + rr < end) ? 16 : 0;
            CPA(base + (u32)(t * TS2 + rr * 272 + ch * 16),
                (const char*)(src + (size_t)(n0 + rr) * 64) + ch * 16, pb);
        }
        CPCOMMIT();
    };

    stage(0, 0);
    for (int ci = 0; ci < nch; ci++) {
        if (ci + 1 < nch) { stage(ci + 1, (ci + 1) & 1); CPWAIT1(); }
        else               CPWAIT0();
        __syncthreads();
        u32 base = sb + 1024 + (ci & 1) * BUF2;
        u32 bA = base;
        u32 bB = base + (isx ? TS2 : 2 * TS2);
        #pragma unroll
        for (int s = 0; s < 4; s++) {
            int k0 = s * 16;
            u32 a[2][4];
            #pragma unroll
            for (int mt = 0; mt < 2; mt++)
                LDSM4T(a[mt], bA + (u32)((k0 + tarow) * S + d0 + 16 * mt + tacol) * 2);
            #pragma unroll
            for (int nt = 0; nt < 8; nt++) {
                u32 b0, b1;
                LDSM2T(b0, b1, bB + (u32)((k0 + tbrow) * S + c0 + 8 * nt) * 2);
                MMA(c[0][nt], a[0], b0, b1);
                MMA(c[1][nt], a[1], b0, b1);
            }
        }
        __syncthreads();
    }
    float* dst = isx ? g_kvU : g_kqU;
    const int g = lane >> 2, t2 = (lane & 3) * 2;
    #pragma unroll
    for (int mt = 0; mt < 2; mt++)
        #pragma unroll
        for (int nt = 0; nt < 8; nt++) {
            int col = c0 + 8 * nt + t2;
            int r1 = d0 + 16 * mt + g, r2 = r1 + 8;
            atomicAdd(&dst[r1 * D + col],     c[mt][nt][0]);
            atomicAdd(&dst[r1 * D + col + 1], c[mt][nt][1]);
            atomicAdd(&dst[r2 * D + col],     c[mt][nt][2]);
            atomicAdd(&dst[r2 * D + col + 1], c[mt][nt][3]);
        }
}

// ---------------- chain (256 thr, M in regs): normalize + Horner + MT plane ----
#define CH_KQ  1024
#define CH_A0  (CH_KQ + 34816)
#define CH_A1  (CH_A0 + 34816)
#define CH_M   CH_A0                    // overlay (A0 dead at finale; last read is A1)
#define SMEMC  (CH_A1 + 34816)          // 105472
__global__ __launch_bounds__(256, 1) void chainc(const float* __restrict__ temp) {
    extern __shared__ __align__(16) char sm[];
    const int tid = threadIdx.x, lane = tid & 31, wid = tid >> 5;
    u32 sb = smem_u32(sm);
    float* izv = (float*)(sm);
    float* tmp = (float*)(sm + 512);
    if (tid < 128) izv[tid] = 1.f / g_Z[tid];
    if (tid < KPOW + 1) tmp[tid] = temp[tid];
    __syncthreads();
    #pragma unroll
    for (int i = 0; i < 32; i++) {                      // kq,kv -> bf16 tiles
        int idx = tid + 256 * i, r = idx >> 6, n2 = idx & 63;
        float iv = izv[r];
        float2 vq = *(const float2*)(g_kqU + r * D + n2 * 2);
        *(u32*)(sm + CH_KQ + r * 272 + n2 * 4) = pbf2(vq.y * iv, vq.x * iv);
        float2 vv = *(const float2*)(g_kvU + r * D + n2 * 2);
        *(u32*)(sm + CH_A0 + r * 272 + n2 * 4) = pbf2(vv.y * iv, vv.x * iv);
    }
    __syncthreads();

    const int m0 = (wid >> 1) * 32, n0 = (wid & 1) * 64;
    const int arow = (lane & 7) + ((lane >> 3) & 1) * 8, acol = ((lane >> 4) & 1) * 8;
    const int tbrow = (lane & 7) + ((lane >> 3) & 1) * 8;
    const int g = lane >> 2, t2 = (lane & 3) * 2;

    float M[2][8][4];
    #pragma unroll
    for (int a = 0; a < 2; a++)
        #pragma unroll
        for (int b = 0; b < 8; b++)
            #pragma unroll
            for (int e = 0; e < 4; e++) M[a][b][e] = 0.f;

    int cur = 0;
    for (int s = 1; s <= KPOW; s++) {
        u32 aoff = sb + (cur ? CH_A1 : CH_A0);
        char* ap = sm + (cur ? CH_A1 : CH_A0);
        float t = tmp[s];
        #pragma unroll
        for (int mt = 0; mt < 2; mt++)                  // M += t * A (reg accumulate)
            #pragma unroll
            for (int nt = 0; nt < 8; nt++) {
                int col = n0 + nt * 8 + t2;
                int r1 = m0 + mt * 16 + g, r2 = r1 + 8;
                u32 v1 = *(const u32*)(ap + r1 * 272 + col * 2);
                u32 v2 = *(const u32*)(ap + r2 * 272 + col * 2);
                M[mt][nt][0] += t * bflo(v1); M[mt][nt][1] += t * bfhi(v1);
                M[mt][nt][2] += t * bflo(v2); M[mt][nt][3] += t * bfhi(v2);
            }
        if (s == KPOW) break;
        float c[2][8][4];
        #pragma unroll
        for (int a = 0; a < 2; a++)
            #pragma unroll
            for (int b = 0; b < 8; b++)
                #pragma unroll
                for (int e = 0; e < 4; e++) c[a][b][e] = 0.f;
        #pragma unroll
        for (int s8 = 0; s8 < 8; s8++) {                // Anew = A @ kq
            int k0 = s8 * 16;
            u32 a[2][4];
            #pragma unroll
            for (int mt = 0; mt < 2; mt++)
                LDSM4(a[mt], aoff + (u32)((m0 + 16 * mt + arow) * S + k0 + acol) * 2);
            #pragma unroll
            for (int nt = 0; nt < 8; nt++) {
                u32 b0, b1;
                LDSM2T(b0, b1, sb + CH_KQ + (u32)((k0 + tbrow) * S + n0 + 8 * nt) * 2);
                MMA(c[0][nt], a[0], b0, b1);
                MMA(c[1][nt], a[1], b0, b1);
            }
        }
        __syncthreads();                                // all reads of A done before overwrite
        char* np = sm + (cur ? CH_A0 : CH_A1);
        #pragma unroll
        for (int mt = 0; mt < 2; mt++)
            #pragma unroll
            for (int nt = 0; nt < 8; nt++) {
                int col = n0 + nt * 8 + t2;
                int r1 = m0 + mt * 16 + g, r2 = r1 + 8;
                *(u32*)(np + r1 * 272 + col * 2) = pbf2(c[mt][nt][1], c[mt][nt][0]);
                *(u32*)(np + r2 * 272 + col * 2) = pbf2(c[mt][nt][3], c[mt][nt][2]);
            }
        __syncthreads();
        cur ^= 1;
    }
    __syncthreads();                                    // M-updates done before overlay
    float* Mf = (float*)(sm + CH_M);
    #pragma unroll
    for (int mt = 0; mt < 2; mt++)
        #pragma unroll
        for (int nt = 0; nt < 8; nt++) {
            int col = n0 + nt * 8 + t2;
            int r1 = m0 + mt * 16 + g, r2 = r1 + 8;
            Mf[r1 * 128 + col] = M[mt][nt][0];  Mf[r1 * 128 + col + 1] = M[mt][nt][1];
            Mf[r2 * 128 + col] = M[mt][nt][2];  Mf[r2 * 128 + col + 1] = M[mt][nt][3];
        }
    __syncthreads();
    #pragma unroll
    for (int i = 0; i < 32; i++) {                      // g_mh[n][k] = bf16(M[k][n])
        int idx = tid + 256 * i, n = idx & 127, kk = idx >> 7;
        g_mh[n * 64 + kk] = pbf2(Mf[(2 * kk + 1) * 128 + n], Mf[2 * kk * 128 + n]);
    }
}

// ---------------- K4 (persistent): out = temp[0]*x + q @ M ---------------------
#define O4M  1024
#define O4Q0 (O4M + 34816)
#define O4Q1 (O4Q0 + 34816)
#define O4OS (O4Q1 + 34816)
#define SMEM4 (O4OS + 67584)            // 173056
__global__ __launch_bounds__(512, 1) void k4c(const float* __restrict__ x,
        const float* __restrict__ temp, float* __restrict__ out) {
    extern __shared__ __align__(16) char sm[];
    const int tid = threadIdx.x, lane = tid & 31, wid = tid >> 5;
    u32 sb = smem_u32(sm);
    const int ts = (NTILES * blockIdx.x) / 148;
    const int te = (NTILES * (blockIdx.x + 1)) / 148;

    auto stage_q = [&](int t, u32 off) {
        int row0 = t * 128;
        #pragma unroll
        for (int i = 0; i < 4; i++) {
            int idx = tid + 512 * i, r = idx >> 4, ch = idx & 15;
            int pb = (row0 + r < NROWS) ? 16 : 0;
            CPA(sb + off + (u32)(r * 272 + ch * 16),
                (const char*)(g_qh + (size_t)(row0 + r) * 64) + ch * 16, pb);
        }
    };

    #pragma unroll
    for (int i = 0; i < 4; i++) {                       // M plane (once per block)
        int idx = tid + 512 * i, r = idx >> 4, ch = idx & 15;
        CPA(sb + O4M + (u32)(r * 272 + ch * 16), (const char*)g_mh + r * 256 + ch * 16, 16);
    }
    stage_q(ts, O4Q0);
    CPCOMMIT();

    const int m0 = (wid >> 2) * 32, n0 = (wid & 3) * 32;
    const int arow = (lane & 7) + ((lane >> 3) & 1) * 8, acol = ((lane >> 4) & 1) * 8;
    const int brow = lane & 7,                           bcol = ((lane >> 3) & 1) * 8;
    const int g = lane >> 2, t2 = (lane & 3) * 2;
    float* os = (float*)(sm + O4OS);

    for (int t = ts; t < te; t++) {
        const int row0 = t * 128;
        const u32 qb = sb + (((t - ts) & 1) ? O4Q1 : O4Q0);
        if (t + 1 < te) { stage_q(t + 1, ((t - ts) & 1) ? O4Q0 : O4Q1); CPCOMMIT(); CPWAIT1(); }
        else            CPWAIT0();
        __syncthreads();

        float c[2][4][4];
        #pragma unroll
        for (int a = 0; a < 2; a++)
            #pragma unroll
            for (int b = 0; b < 4; b++)
                #pragma unroll
                for (int e = 0; e < 4; e++) c[a][b][e] = 0.f;

        #pragma unroll
        for (int s = 0; s < 8; s++) {
            int k0 = s * 16;
            u32 a[2][4];
            #pragma unroll
            for (int mt = 0; mt < 2; mt++)
                LDSM4(a[mt], qb + (u32)((m0 + 16 * mt + arow) * S + k0 + acol) * 2);
            #pragma unroll
            for (int nt = 0; nt < 4; nt++) {
                u32 b0, b1;
                LDSM2(b0, b1, sb + O4M + (u32)((n0 + 8 * nt + brow) * S + k0 + bcol) * 2);
                MMA(c[0][nt], a[0], b0, b1);
                MMA(c[1][nt], a[1], b0, b1);
            }
        }
        #pragma unroll
        for (int mt = 0; mt < 2; mt++)
            #pragma unroll
            for (int nt = 0; nt < 4; nt++) {
                int col = n0 + nt * 8 + t2;
                int r1 = m0 + mt * 16 + g, r2 = r1 + 8;
                os[r1 * 132 + col] = c[mt][nt][0];  os[r1 * 132 + col + 1] = c[mt][nt][1];
                os[r2 * 132 + col] = c[mt][nt][2];  os[r2 * 132 + col + 1] = c[mt][nt][3];
            }
        __syncthreads();
        float t0 = temp[0];
        #pragma unroll
        for (int i = 0; i < 8; i++) {
            int idx = tid + 512 * i, r = idx >> 5, c4 = (idx & 31) << 2;
            if (row0 + r < NROWS) {
                float4 xv = *(const float4*)(x + (size_t)(row0 + r) * D + c4);
                float4 a = *(float4*)&os[r * 132 + c4];
                *(float4*)(out + (size_t)(row0 + r) * D + c4) =
                    make_float4(fmaf(t0, xv.x, a.x), fmaf(t0, xv.y, a.y),
                                fmaf(t0, xv.z, a.z), fmaf(t0, xv.w, a.w));
            }
        }
        __syncthreads();
    }
}

// ---------------- launch -------------------------------------------------------
extern "C" void kernel_launch(void* const* d_in, const int* in_sizes, int n_in,
                              void* d_out, int out_size) {
    const float* x    = (const float*)d_in[0];
    const float* Wq   = (const float*)d_in[1];
    const float* bq   = (const float*)d_in[2];
    const float* Wk   = (const float*)d_in[3];
    const float* bk   = (const float*)d_in[4];
    const float* temp = (const float*)d_in[5];
    float* out = (float*)d_out;

    cudaFuncSetAttribute(k1c,    cudaFuncAttributeMaxDynamicSharedMemorySize, SMEM1);
    cudaFuncSetAttribute(k2b,    cudaFuncAttributeMaxDynamicSharedMemorySize, SMEM2);
    cudaFuncSetAttribute(chainc, cudaFuncAttributeMaxDynamicSharedMemorySize, SMEMC);
    cudaFuncSetAttribute(k4c,    cudaFuncAttributeMaxDynamicSharedMemorySize, SMEM4);

    prep_kernel<<<9, 256>>>(Wq, Wk);
    k1c<<<148, 512, SMEM1>>>(x, bq, bk);
    k2b<<<296, 512, SMEM2>>>();
    chainc<<<1, 256, SMEMC>>>(temp);
    k4c<<<148, 512, SMEM4>>>(x, temp, out);
}

// round 16
// speedup vs baseline: 5.1521x; 1.0139x over previous
#include <cuda_runtime.h>
#include <cuda_bf16.h>

#define D      128
#define NROWS  200000
#define KPOW   10
#define S      136
#define NTILES 1563
typedef unsigned int u32;
typedef unsigned short u16;

// ---------------- scratch ------------------------------------------------------
__device__ __align__(16) u32 g_xh[(size_t)NROWS * 64];   // x  bf16 plane (packed x2)
__device__ __align__(16) u32 g_qh[(size_t)NROWS * 64];   // q  bf16 plane
__device__ __align__(16) u32 g_eh[(size_t)NROWS * 64];   // ek bf16 plane
__device__ __align__(16) u32 g_mh[D * 64];               // MT bf16 plane
__device__ float g_Zpart[148 * 128];                     // per-block ek column sums
__device__ float g_kvU[D * D];
__device__ float g_kqU[D * D];

// ---------------- helpers ------------------------------------------------------
__device__ __forceinline__ u32 smem_u32(const void* p) {
    u32 a;
    asm("{ .reg .u64 t; cvta.to.shared.u64 t, %1; cvt.u32.u64 %0, t; }" : "=r"(a) : "l"(p));
    return a;
}
__device__ __forceinline__ u32 pbf2(float hi, float lo) {
    u32 r; asm("cvt.rn.bf16x2.f32 %0, %1, %2;" : "=r"(r) : "f"(hi), "f"(lo)); return r;
}
__device__ __forceinline__ float bflo(u32 w) { return __uint_as_float(w << 16); }
__device__ __forceinline__ float bfhi(u32 w) { return __uint_as_float(w & 0xffff0000u); }

#define CPA(dst, src, pb) asm volatile("cp.async.ca.shared.global [%0], [%1], 16, %2;" \
    :: "r"(dst), "l"(src), "r"(pb))
#define CPCOMMIT() asm volatile("cp.async.commit_group;" ::: "memory")
#define CPWAIT0()  asm volatile("cp.async.wait_group 0;" ::: "memory")
#define CPWAIT1()  asm volatile("cp.async.wait_group 1;" ::: "memory")

#define LDSM4(r, a)  asm volatile("ldmatrix.sync.aligned.m8n8.x4.shared.b16 {%0,%1,%2,%3}, [%4];" \
    : "=r"((r)[0]), "=r"((r)[1]), "=r"((r)[2]), "=r"((r)[3]) : "r"(a))
#define LDSM4T(r, a) asm volatile("ldmatrix.sync.aligned.m8n8.x4.trans.shared.b16 {%0,%1,%2,%3}, [%4];" \
    : "=r"((r)[0]), "=r"((r)[1]), "=r"((r)[2]), "=r"((r)[3]) : "r"(a))
#define LDSM2(r0, r1, a)  asm volatile("ldmatrix.sync.aligned.m8n8.x2.shared.b16 {%0,%1}, [%2];" \
    : "=r"(r0), "=r"(r1) : "r"(a))
#define LDSM2T(r0, r1, a) asm volatile("ldmatrix.sync.aligned.m8n8.x2.trans.shared.b16 {%0,%1}, [%2];" \
    : "=r"(r0), "=r"(r1) : "r"(a))
#define MMA(c, a, b0, b1) asm volatile( \
    "mma.sync.aligned.m16n8k16.row.col.f32.bf16.bf16.f32 " \
    "{%0,%1,%2,%3}, {%4,%5,%6,%7}, {%8,%9}, {%0,%1,%2,%3};" \
    : "+f"((c)[0]), "+f"((c)[1]), "+f"((c)[2]), "+f"((c)[3]) \
    : "r"((a)[0]), "r"((a)[1]), "r"((a)[2]), "r"((a)[3]), "r"(b0), "r"(b1))

// ---------------- K1 (persistent): W convert + logits + softmax + planes -------
#define O1B  2048
#define O1X0 (O1B + 69632)
#define O1X1 (O1X0 + 34816)
#define O1Q  (O1X1 + 34816)
#define O1E  (O1Q + 34816)
#define SMEM1 (O1E + 34816)             // 210944
__device__ __forceinline__ void k1_stage(const float* __restrict__ x, int row0,
                                         char* sm, u32 off, int tid) {
    #pragma unroll
    for (int i = 0; i < 16; i++) {
        int idx = tid + 512 * i, r = idx >> 6, j2 = idx & 63;
        u32 p = 0u;
        if (row0 + r < NROWS) {
            float2 v = *(const float2*)(x + (size_t)(row0 + r) * D + j2 * 2);
            p = pbf2(v.y, v.x);
            g_xh[(size_t)(row0 + r) * 64 + j2] = p;
        }
        *(u32*)(sm + off + (u32)(r * 272 + j2 * 4)) = p;
    }
}
__global__ __launch_bounds__(512, 1) void k1c(const float* __restrict__ x,
        const float* __restrict__ Wq, const float* __restrict__ bq,
        const float* __restrict__ Wk, const float* __restrict__ bk) {
    extern __shared__ __align__(16) char sm[];
    const int tid = threadIdx.x, lane = tid & 31, wid = tid >> 5;
    u32 sb = smem_u32(sm);
    float* sbq  = (float*)(sm);
    float* sbk  = (float*)(sm + 512);
    float* sinv = (float*)(sm + 1024);
    float* scol = (float*)(sm + 1536);
    if (tid < 128) { sbq[tid] = bq[tid]; sbk[tid] = bk[tid]; scol[tid] = 0.f; }

    if (blockIdx.x == 0) {                              // zero accumulators (pre-k2)
        float4 z4 = make_float4(0.f, 0.f, 0.f, 0.f);
        for (int i = tid; i < 4096; i += 512) {
            ((float4*)g_kvU)[i] = z4;
            ((float4*)g_kqU)[i] = z4;
        }
    }

    const int ts = (NTILES * blockIdx.x) / 148;
    const int te = (NTILES * (blockIdx.x + 1)) / 148;

    // W -> bf16 smem tile, direct fp32 LDG (Wq rows 0-127, Wk rows 128-255)
    #pragma unroll
    for (int i = 0; i < 32; i++) {
        int idx = tid + 512 * i, r = idx >> 6, j2 = idx & 63;
        const float* src = (r < 128) ? (Wq + r * D + j2 * 2) : (Wk + (r - 128) * D + j2 * 2);
        float2 v = *(const float2*)src;
        *(u32*)(sm + O1B + (u32)(r * 272 + j2 * 4)) = pbf2(v.y, v.x);
    }
    k1_stage(x, ts * 128, sm, O1X0, tid);
    __syncthreads();

    const int m0 = (wid >> 2) * 32, n0 = (wid & 3) * 64;
    const int arow = (lane & 7) + ((lane >> 3) & 1) * 8, acol = ((lane >> 4) & 1) * 8;
    const int brow = lane & 7,                           bcol = ((lane >> 3) & 1) * 8;
    const int g = lane >> 2, t2 = (lane & 3) * 2;
    const bool isq = n0 < 128;

    for (int t = ts; t < te; t++) {
        const int row0 = t * 128;
        const u32 xb = sb + (((t - ts) & 1) ? O1X1 : O1X0);

        float c[2][8][4];
        #pragma unroll
        for (int a = 0; a < 2; a++)
            #pragma unroll
            for (int b = 0; b < 8; b++)
                #pragma unroll
                for (int e = 0; e < 4; e++) c[a][b][e] = 0.f;

        #pragma unroll
        for (int s = 0; s < 8; s++) {
            int k0 = s * 16;
            u32 a[2][4];
            #pragma unroll
            for (int mt = 0; mt < 2; mt++)
                LDSM4(a[mt], xb + (u32)((m0 + 16 * mt + arow) * S + k0 + acol) * 2);
            #pragma unroll
            for (int nt = 0; nt < 8; nt++) {
                u32 b0, b1;
                LDSM2(b0, b1, sb + O1B + (u32)((n0 + 8 * nt + brow) * S + k0 + bcol) * 2);
                MMA(c[0][nt], a[0], b0, b1);
                MMA(c[1][nt], a[1], b0, b1);
            }
        }

        if (t + 1 < te)                                  // overlap staging with epilogue
            k1_stage(x, (t + 1) * 128, sm, ((t - ts) & 1) ? O1X0 : O1X1, tid);

        char* qx = sm + O1Q;
        char* ex = sm + O1E;
        #pragma unroll
        for (int mt = 0; mt < 2; mt++)
            #pragma unroll
            for (int nt = 0; nt < 8; nt++) {
                int col = n0 + nt * 8 + t2;
                int r1 = m0 + mt * 16 + g, r2 = r1 + 8;
                float bi0 = isq ? sbq[col] : sbk[col - 128];
                float bi1 = isq ? sbq[col + 1] : sbk[col - 127];
                float e00 = __expf(c[mt][nt][0] + bi0), e01 = __expf(c[mt][nt][1] + bi1);
                float e10 = __expf(c[mt][nt][2] + bi0), e11 = __expf(c[mt][nt][3] + bi1);
                if (isq) {
                    *(u32*)(qx + r1 * 272 + col * 2) = pbf2(e01, e00);
                    *(u32*)(qx + r2 * 272 + col * 2) = pbf2(e11, e10);
                } else {
                    int cl = col - 128;
                    bool a1 = (row0 + r1) < NROWS, a2 = (row0 + r2) < NROWS;
                    *(u32*)(ex + r1 * 272 + cl * 2) = a1 ? pbf2(e01, e00) : 0u;
                    *(u32*)(ex + r2 * 272 + cl * 2) = a2 ? pbf2(e11, e10) : 0u;
                }
            }
        __syncthreads();
        if (tid < 128) {                                 // q row sums
            const u32* qp = (const u32*)(qx + tid * 272);
            float s = 0.f;
            #pragma unroll 16
            for (int w = 0; w < 64; w++) { u32 v = qp[w]; s += bflo(v) + bfhi(v); }
            sinv[tid] = 1.f / s;
        } else if (tid < 256) {                          // ek column sums -> scol
            int cc = tid - 128;
            const u16* ep = (const u16*)ex;
            float s = 0.f;
            #pragma unroll 8
            for (int r = 0; r < 128; r++) s += __uint_as_float((u32)ep[r * 136 + cc] << 16);
            scol[cc] += s;
        }
        __syncthreads();
        #pragma unroll
        for (int i = 0; i < 16; i++) {                   // plane writes
            int idx = tid + 512 * i, r = idx >> 6, w = idx & 63;
            if (row0 + r < NROWS) {
                float iv = sinv[r];
                u32 qv = *(const u32*)(qx + r * 272 + w * 4);
                g_qh[(size_t)(row0 + r) * 64 + w] = pbf2(bfhi(qv) * iv, bflo(qv) * iv);
                g_eh[(size_t)(row0 + r) * 64 + w] = *(const u32*)(ex + r * 272 + w * 4);
            }
        }
        __syncthreads();
    }
    if (tid < 128) g_Zpart[blockIdx.x * 128 + tid] = scol[tid];
}

// ---------------- K2: kvU = ek^T @ x, kqU = ek^T @ q (double-buffered) ---------
#define TS2 17408
#define BUF2 (3 * TS2)
#define SMEM2 (1024 + 2 * BUF2)         // 105472
__global__ __launch_bounds__(512, 1) void k2b() {
    extern __shared__ __align__(16) char sm[];
    const int tid = threadIdx.x, lane = tid & 31, wid = tid >> 5;
    u32 sb = smem_u32(sm);
    const int per = (NROWS + 295) / 296;
    int start = blockIdx.x * per;
    int end = start + per; if (end > NROWS) end = NROWS;
    int nch = (end - start + 63) / 64;

    const int d0 = (wid >> 2) * 32, cw = wid & 3;
    const bool isx = cw < 2;
    const int c0 = (cw & 1) * 64;
    float c[2][8][4];
    #pragma unroll
    for (int a = 0; a < 2; a++)
        #pragma unroll
        for (int b = 0; b < 8; b++)
            #pragma unroll
            for (int e = 0; e < 4; e++) c[a][b][e] = 0.f;

    const int tarow = (lane & 7) + ((lane >> 4) & 1) * 8, tacol = ((lane >> 3) & 1) * 8;
    const int tbrow = (lane & 7) + ((lane >> 3) & 1) * 8;

    auto stage = [&](int ci, int bi) {
        u32 base = sb + 1024 + bi * BUF2;
        int n0 = start + ci * 64;
        #pragma unroll
        for (int i = 0; i < 6; i++) {
            int idx = tid + 512 * i;
            int t = idx >> 10, rr = (idx >> 4) & 63, ch = idx & 15;
            const u32* src = (t == 0) ? g_eh : ((t == 1) ? g_xh : g_qh);
            int pb = (n0 + rr < end) ? 16 : 0;
            CPA(base + (u32)(t * TS2 + rr * 272 + ch * 16),
                (const char*)(src + (size_t)(n0 + rr) * 64) + ch * 16, pb);
        }
        CPCOMMIT();
    };

    stage(0, 0);
    for (int ci = 0; ci < nch; ci++) {
        if (ci + 1 < nch) { stage(ci + 1, (ci + 1) & 1); CPWAIT1(); }
        else               CPWAIT0();
        __syncthreads();
        u32 base = sb + 1024 + (ci & 1) * BUF2;
        u32 bA = base;
        u32 bB = base + (isx ? TS2 : 2 * TS2);
        #pragma unroll
        for (int s = 0; s < 4; s++) {
            int k0 = s * 16;
            u32 a[2][4];
            #pragma unroll
            for (int mt = 0; mt < 2; mt++)
                LDSM4T(a[mt], bA + (u32)((k0 + tarow) * S + d0 + 16 * mt + tacol) * 2);
            #pragma unroll
            for (int nt = 0; nt < 8; nt++) {
                u32 b0, b1;
                LDSM2T(b0, b1, bB + (u32)((k0 + tbrow) * S + c0 + 8 * nt) * 2);
                MMA(c[0][nt], a[0], b0, b1);
                MMA(c[1][nt], a[1], b0, b1);
            }
        }
        __syncthreads();
    }
    float* dst = isx ? g_kvU : g_kqU;
    const int g = lane >> 2, t2 = (lane & 3) * 2;
    #pragma unroll
    for (int mt = 0; mt < 2; mt++)
        #pragma unroll
        for (int nt = 0; nt < 8; nt++) {
            int col = c0 + 8 * nt + t2;
            int r1 = d0 + 16 * mt + g, r2 = r1 + 8;
            atomicAdd(&dst[r1 * D + col],     c[mt][nt][0]);
            atomicAdd(&dst[r1 * D + col + 1], c[mt][nt][1]);
            atomicAdd(&dst[r2 * D + col],     c[mt][nt][2]);
            atomicAdd(&dst[r2 * D + col + 1], c[mt][nt][3]);
        }
}

// ---------------- chain (512 thr, 16 warps, M in regs) -------------------------
#define CH_KQ  3072
#define CH_A0  (CH_KQ + 34816)
#define CH_A1  (CH_A0 + 34816)
#define CH_M   CH_A0                    // fp32 overlay spans A0+A1 (both dead)
#define SMEMC  (CH_A1 + 34816)          // 107520
__global__ __launch_bounds__(512, 1) void chainc(const float* __restrict__ temp) {
    extern __shared__ __align__(16) char sm[];
    const int tid = threadIdx.x, lane = tid & 31, wid = tid >> 5;
    u32 sb = smem_u32(sm);
    float* izv   = (float*)(sm);
    float* tmp   = (float*)(sm + 512);
    float* spart = (float*)(sm + 640);
    {
        int cc = tid & 127, p = tid >> 7;
        float s = 0.f;
        for (int b = p; b < 148; b += 4) s += g_Zpart[b * 128 + cc];
        spart[p * 128 + cc] = s;
    }
    if (tid < KPOW + 1) tmp[tid] = temp[tid];
    __syncthreads();
    if (tid < 128)
        izv[tid] = 1.f / (spart[tid] + spart[128 + tid] + spart[256 + tid] + spart[384 + tid]);
    __syncthreads();
    #pragma unroll
    for (int i = 0; i < 16; i++) {                      // kq,kv -> bf16 tiles
        int idx = tid + 512 * i, r = idx >> 6, n2 = idx & 63;
        float iv = izv[r];
        float2 vq = *(const float2*)(g_kqU + r * D + n2 * 2);
        *(u32*)(sm + CH_KQ + r * 272 + n2 * 4) = pbf2(vq.y * iv, vq.x * iv);
        float2 vv = *(const float2*)(g_kvU + r * D + n2 * 2);
        *(u32*)(sm + CH_A0 + r * 272 + n2 * 4) = pbf2(vv.y * iv, vv.x * iv);
    }
    __syncthreads();

    const int m0 = (wid >> 2) * 32, n0 = (wid & 3) * 32;
    const int arow = (lane & 7) + ((lane >> 3) & 1) * 8, acol = ((lane >> 4) & 1) * 8;
    const int tbrow = (lane & 7) + ((lane >> 3) & 1) * 8;
    const int g = lane >> 2, t2 = (lane & 3) * 2;

    float M[2][4][4];
    #pragma unroll
    for (int a = 0; a < 2; a++)
        #pragma unroll
        for (int b = 0; b < 4; b++)
            #pragma unroll
            for (int e = 0; e < 4; e++) M[a][b][e] = 0.f;

    int cur = 0;
    for (int s = 1; s <= KPOW; s++) {
        u32 aoff = sb + (cur ? CH_A1 : CH_A0);
        char* ap = sm + (cur ? CH_A1 : CH_A0);
        float t = tmp[s];
        #pragma unroll
        for (int mt = 0; mt < 2; mt++)                  // M += t * A (reg accumulate)
            #pragma unroll
            for (int nt = 0; nt < 4; nt++) {
                int col = n0 + nt * 8 + t2;
                int r1 = m0 + mt * 16 + g, r2 = r1 + 8;
                u32 v1 = *(const u32*)(ap + r1 * 272 + col * 2);
                u32 v2 = *(const u32*)(ap + r2 * 272 + col * 2);
                M[mt][nt][0] += t * bflo(v1); M[mt][nt][1] += t * bfhi(v1);
                M[mt][nt][2] += t * bflo(v2); M[mt][nt][3] += t * bfhi(v2);
            }
        if (s == KPOW) break;
        float c[2][4][4];
        #pragma unroll
        for (int a = 0; a < 2; a++)
            #pragma unroll
            for (int b = 0; b < 4; b++)
                #pragma unroll
                for (int e = 0; e < 4; e++) c[a][b][e] = 0.f;
        #pragma unroll
        for (int s8 = 0; s8 < 8; s8++) {                // Anew = A @ kq
            int k0 = s8 * 16;
            u32 a[2][4];
            #pragma unroll
            for (int mt = 0; mt < 2; mt++)
                LDSM4(a[mt], aoff + (u32)((m0 + 16 * mt + arow) * S + k0 + acol) * 2);
            #pragma unroll
            for (int nt = 0; nt < 4; nt++) {
                u32 b0, b1;
                LDSM2T(b0, b1, sb + CH_KQ + (u32)((k0 + tbrow) * S + n0 + 8 * nt) * 2);
                MMA(c[0][nt], a[0], b0, b1);
                MMA(c[1][nt], a[1], b0, b1);
            }
        }
        __syncthreads();                                // reads of A done before overwrite
        char* np = sm + (cur ? CH_A0 : CH_A1);
        #pragma unroll
        for (int mt = 0; mt < 2; mt++)
            #pragma unroll
            for (int nt = 0; nt < 4; nt++) {
                int col = n0 + nt * 8 + t2;
                int r1 = m0 + mt * 16 + g, r2 = r1 + 8;
                *(u32*)(np + r1 * 272 + col * 2) = pbf2(c[mt][nt][1], c[mt][nt][0]);
                *(u32*)(np + r2 * 272 + col * 2) = pbf2(c[mt][nt][3], c[mt][nt][2]);
            }
        __syncthreads();
        cur ^= 1;
    }
    __syncthreads();                                    // M-updates done before overlay
    float* Mf = (float*)(sm + CH_M);
    #pragma unroll
    for (int mt = 0; mt < 2; mt++)
        #pragma unroll
        for (int nt = 0; nt < 4; nt++) {
            int col = n0 + nt * 8 + t2;
            int r1 = m0 + mt * 16 + g, r2 = r1 + 8;
            Mf[r1 * 128 + col] = M[mt][nt][0];  Mf[r1 * 128 + col + 1] = M[mt][nt][1];
            Mf[r2 * 128 + col] = M[mt][nt][2];  Mf[r2 * 128 + col + 1] = M[mt][nt][3];
        }
    __syncthreads();
    #pragma unroll
    for (int i = 0; i < 16; i++) {                      // g_mh[n][k] = bf16(M[k][n])
        int idx = tid + 512 * i, n = idx & 127, kk = idx >> 7;
        g_mh[n * 64 + kk] = pbf2(Mf[(2 * kk + 1) * 128 + n], Mf[2 * kk * 128 + n]);
    }
}

// ---------------- K4 (persistent): out = temp[0]*x + q @ M ---------------------
#define O4M  1024
#define O4Q0 (O4M + 34816)
#define O4Q1 (O4Q0 + 34816)
#define O4OS (O4Q1 + 34816)
#define SMEM4 (O4OS + 67584)            // 173056
__global__ __launch_bounds__(512, 1) void k4c(const float* __restrict__ x,
        const float* __restrict__ temp, float* __restrict__ out) {
    extern __shared__ __align__(16) char sm[];
    const int tid = threadIdx.x, lane = tid & 31, wid = tid >> 5;
    u32 sb = smem_u32(sm);
    const int ts = (NTILES * blockIdx.x) / 148;
    const int te = (NTILES * (blockIdx.x + 1)) / 148;

    auto stage_q = [&](int t, u32 off) {
        int row0 = t * 128;
        #pragma unroll
        for (int i = 0; i < 4; i++) {
            int idx = tid + 512 * i, r = idx >> 4, ch = idx & 15;
            int pb = (row0 + r < NROWS) ? 16 : 0;
            CPA(sb + off + (u32)(r * 272 + ch * 16),
                (const char*)(g_qh + (size_t)(row0 + r) * 64) + ch * 16, pb);
        }
    };

    #pragma unroll
    for (int i = 0; i < 4; i++) {                       // M plane (once per block)
        int idx = tid + 512 * i, r = idx >> 4, ch = idx & 15;
        CPA(sb + O4M + (u32)(r * 272 + ch * 16), (const char*)g_mh + r * 256 + ch * 16, 16);
    }
    stage_q(ts, O4Q0);
    CPCOMMIT();

    const int m0 = (wid >> 2) * 32, n0 = (wid & 3) * 32;
    const int arow = (lane & 7) + ((lane >> 3) & 1) * 8, acol = ((lane >> 4) & 1) * 8;
    const int brow = lane & 7,                           bcol = ((lane >> 3) & 1) * 8;
    const int g = lane >> 2, t2 = (lane & 3) * 2;
    float* os = (float*)(sm + O4OS);

    for (int t = ts; t < te; t++) {
        const int row0 = t * 128;
        const u32 qb = sb + (((t - ts) & 1) ? O4Q1 : O4Q0);
        if (t + 1 < te) { stage_q(t + 1, ((t - ts) & 1) ? O4Q0 : O4Q1); CPCOMMIT(); CPWAIT1(); }
        else            CPWAIT0();
        __syncthreads();

        float c[2][4][4];
        #pragma unroll
        for (int a = 0; a < 2; a++)
            #pragma unroll
            for (int b = 0; b < 4; b++)
                #pragma unroll
                for (int e = 0; e < 4; e++) c[a][b][e] = 0.f;

        #pragma unroll
        for (int s = 0; s < 8; s++) {
            int k0 = s * 16;
            u32 a[2][4];
            #pragma unroll
            for (int mt = 0; mt < 2; mt++)
                LDSM4(a[mt], qb + (u32)((m0 + 16 * mt + arow) * S + k0 + acol) * 2);
            #pragma unroll
            for (int nt = 0; nt < 4; nt++) {
                u32 b0, b1;
                LDSM2(b0, b1, sb + O4M + (u32)((n0 + 8 * nt + brow) * S + k0 + bcol) * 2);
                MMA(c[0][nt], a[0], b0, b1);
                MMA(c[1][nt], a[1], b0, b1);
            }
        }
        #pragma unroll
        for (int mt = 0; mt < 2; mt++)
            #pragma unroll
            for (int nt = 0; nt < 4; nt++) {
                int col = n0 + nt * 8 + t2;
                int r1 = m0 + mt * 16 + g, r2 = r1 + 8;
                os[r1 * 132 + col] = c[mt][nt][0];  os[r1 * 132 + col + 1] = c[mt][nt][1];
                os[r2 * 132 + col] = c[mt][nt][2];  os[r2 * 132 + col + 1] = c[mt][nt][3];
            }
        __syncthreads();
        float t0 = temp[0];
        #pragma unroll
        for (int i = 0; i < 8; i++) {
            int idx = tid + 512 * i, r = idx >> 5, c4 = (idx & 31) << 2;
            if (row0 + r < NROWS) {
                float4 xv = *(const float4*)(x + (size_t)(row0 + r) * D + c4);
                float4 a = *(float4*)&os[r * 132 + c4];
                *(float4*)(out + (size_t)(row0 + r) * D + c4) =
                    make_float4(fmaf(t0, xv.x, a.x), fmaf(t0, xv.y, a.y),
                                fmaf(t0, xv.z, a.z), fmaf(t0, xv.w, a.w));
            }
        }
        __syncthreads();
    }
}

// ---------------- launch -------------------------------------------------------
extern "C" void kernel_launch(void* const* d_in, const int* in_sizes, int n_in,
                              void* d_out, int out_size) {
    const float* x    = (const float*)d_in[0];
    const float* Wq   = (const float*)d_in[1];
    const float* bq   = (const float*)d_in[2];
    const float* Wk   = (const float*)d_in[3];
    const float* bk   = (const float*)d_in[4];
    const float* temp = (const float*)d_in[5];
    float* out = (float*)d_out;

    cudaFuncSetAttribute(k1c,    cudaFuncAttributeMaxDynamicSharedMemorySize, SMEM1);
    cudaFuncSetAttribute(k2b,    cudaFuncAttributeMaxDynamicSharedMemorySize, SMEM2);
    cudaFuncSetAttribute(chainc, cudaFuncAttributeMaxDynamicSharedMemorySize, SMEMC);
    cudaFuncSetAttribute(k4c,    cudaFuncAttributeMaxDynamicSharedMemorySize, SMEM4);

    k1c<<<148, 512, SMEM1>>>(x, Wq, bq, Wk, bk);
    k2b<<<296, 512, SMEM2>>>();
    chainc<<<1, 512, SMEMC>>>(temp);
    k4c<<<148, 512, SMEM4>>>(x, temp, out);
}

// round 17
// speedup vs baseline: 5.2559x; 1.0201x over previous
#include <cuda_runtime.h>
#include <cuda_bf16.h>

#define D      128
#define NROWS  200000
#define KPOW   10
#define S      136
#define NTILES 1563
typedef unsigned int u32;
typedef unsigned short u16;

// ---------------- scratch ------------------------------------------------------
__device__ __align__(16) u32 g_xh[(size_t)NROWS * 64];   // x  bf16 plane (packed x2)
__device__ __align__(16) u32 g_qh[(size_t)NROWS * 64];   // q  bf16 plane
__device__ __align__(16) u32 g_eh[(size_t)NROWS * 64];   // ek bf16 plane
__device__ __align__(16) u32 g_mh[D * 64];               // MT bf16 plane
__device__ float g_Zpart[148 * 128];                     // per-block ek column sums
__device__ float g_kvU[D * D];
__device__ float g_kqU[D * D];

// ---------------- helpers ------------------------------------------------------
__device__ __forceinline__ u32 smem_u32(const void* p) {
    u32 a;
    asm("{ .reg .u64 t; cvta.to.shared.u64 t, %1; cvt.u32.u64 %0, t; }" : "=r"(a) : "l"(p));
    return a;
}
__device__ __forceinline__ u32 pbf2(float hi, float lo) {
    u32 r; asm("cvt.rn.bf16x2.f32 %0, %1, %2;" : "=r"(r) : "f"(hi), "f"(lo)); return r;
}
__device__ __forceinline__ float bflo(u32 w) { return __uint_as_float(w << 16); }
__device__ __forceinline__ float bfhi(u32 w) { return __uint_as_float(w & 0xffff0000u); }

#define CPA(dst, src, pb) asm volatile("cp.async.ca.shared.global [%0], [%1], 16, %2;" \
    :: "r"(dst), "l"(src), "r"(pb))
#define CPCOMMIT() asm volatile("cp.async.commit_group;" ::: "memory")
#define CPWAIT0()  asm volatile("cp.async.wait_group 0;" ::: "memory")
#define CPWAIT1()  asm volatile("cp.async.wait_group 1;" ::: "memory")

#define LDSM4(r, a)  asm volatile("ldmatrix.sync.aligned.m8n8.x4.shared.b16 {%0,%1,%2,%3}, [%4];" \
    : "=r"((r)[0]), "=r"((r)[1]), "=r"((r)[2]), "=r"((r)[3]) : "r"(a))
#define LDSM4T(r, a) asm volatile("ldmatrix.sync.aligned.m8n8.x4.trans.shared.b16 {%0,%1,%2,%3}, [%4];" \
    : "=r"((r)[0]), "=r"((r)[1]), "=r"((r)[2]), "=r"((r)[3]) : "r"(a))
#define LDSM2(r0, r1, a)  asm volatile("ldmatrix.sync.aligned.m8n8.x2.shared.b16 {%0,%1}, [%2];" \
    : "=r"(r0), "=r"(r1) : "r"(a))
#define LDSM2T(r0, r1, a) asm volatile("ldmatrix.sync.aligned.m8n8.x2.trans.shared.b16 {%0,%1}, [%2];" \
    : "=r"(r0), "=r"(r1) : "r"(a))
#define MMA(c, a, b0, b1) asm volatile( \
    "mma.sync.aligned.m16n8k16.row.col.f32.bf16.bf16.f32 " \
    "{%0,%1,%2,%3}, {%4,%5,%6,%7}, {%8,%9}, {%0,%1,%2,%3};" \
    : "+f"((c)[0]), "+f"((c)[1]), "+f"((c)[2]), "+f"((c)[3]) \
    : "r"((a)[0]), "r"((a)[1]), "r"((a)[2]), "r"((a)[3]), "r"(b0), "r"(b1))

// ---------------- K1 (persistent): W convert + logits + softmax + planes -------
#define O1B  2048
#define O1X0 (O1B + 69632)
#define O1X1 (O1X0 + 34816)
#define O1Q  (O1X1 + 34816)
#define O1E  (O1Q + 34816)
#define SMEM1 (O1E + 34816)             // 210944
__device__ __forceinline__ void k1_stage(const float* __restrict__ x, int row0,
                                         char* sm, u32 off, int tid) {
    #pragma unroll
    for (int i = 0; i < 16; i++) {
        int idx = tid + 512 * i, r = idx >> 6, j2 = idx & 63;
        u32 p = 0u;
        if (row0 + r < NROWS) {
            float2 v = *(const float2*)(x + (size_t)(row0 + r) * D + j2 * 2);
            p = pbf2(v.y, v.x);
            g_xh[(size_t)(row0 + r) * 64 + j2] = p;
        }
        *(u32*)(sm + off + (u32)(r * 272 + j2 * 4)) = p;
    }
}
__global__ __launch_bounds__(512, 1) void k1c(const float* __restrict__ x,
        const float* __restrict__ Wq, const float* __restrict__ bq,
        const float* __restrict__ Wk, const float* __restrict__ bk) {
    extern __shared__ __align__(16) char sm[];
    const int tid = threadIdx.x, lane = tid & 31, wid = tid >> 5;
    u32 sb = smem_u32(sm);
    float* sbq  = (float*)(sm);
    float* sbk  = (float*)(sm + 512);
    float* sinv = (float*)(sm + 1024);
    float* scol = (float*)(sm + 1536);
    if (tid < 128) { sbq[tid] = bq[tid]; sbk[tid] = bk[tid]; scol[tid] = 0.f; }

    if (blockIdx.x == 0) {                              // zero accumulators (pre-k2)
        float4 z4 = make_float4(0.f, 0.f, 0.f, 0.f);
        for (int i = tid; i < 4096; i += 512) {
            ((float4*)g_kvU)[i] = z4;
            ((float4*)g_kqU)[i] = z4;
        }
    }

    const int ts = (NTILES * blockIdx.x) / 148;
    const int te = (NTILES * (blockIdx.x + 1)) / 148;

    // W -> bf16 smem tile, direct fp32 LDG (Wq rows 0-127, Wk rows 128-255)
    #pragma unroll
    for (int i = 0; i < 32; i++) {
        int idx = tid + 512 * i, r = idx >> 6, j2 = idx & 63;
        const float* src = (r < 128) ? (Wq + r * D + j2 * 2) : (Wk + (r - 128) * D + j2 * 2);
        float2 v = *(const float2*)src;
        *(u32*)(sm + O1B + (u32)(r * 272 + j2 * 4)) = pbf2(v.y, v.x);
    }
    k1_stage(x, ts * 128, sm, O1X0, tid);
    __syncthreads();

    const int m0 = (wid >> 2) * 32, n0 = (wid & 3) * 64;
    const int arow = (lane & 7) + ((lane >> 3) & 1) * 8, acol = ((lane >> 4) & 1) * 8;
    const int brow = lane & 7,                           bcol = ((lane >> 3) & 1) * 8;
    const int g = lane >> 2, t2 = (lane & 3) * 2;
    const bool isq = n0 < 128;

    for (int t = ts; t < te; t++) {
        const int row0 = t * 128;
        const u32 xb = sb + (((t - ts) & 1) ? O1X1 : O1X0);

        float c[2][8][4];
        #pragma unroll
        for (int a = 0; a < 2; a++)
            #pragma unroll
            for (int b = 0; b < 8; b++)
                #pragma unroll
                for (int e = 0; e < 4; e++) c[a][b][e] = 0.f;

        #pragma unroll
        for (int s = 0; s < 8; s++) {
            int k0 = s * 16;
            u32 a[2][4];
            #pragma unroll
            for (int mt = 0; mt < 2; mt++)
                LDSM4(a[mt], xb + (u32)((m0 + 16 * mt + arow) * S + k0 + acol) * 2);
            #pragma unroll
            for (int nt = 0; nt < 8; nt++) {
                u32 b0, b1;
                LDSM2(b0, b1, sb + O1B + (u32)((n0 + 8 * nt + brow) * S + k0 + bcol) * 2);
                MMA(c[0][nt], a[0], b0, b1);
                MMA(c[1][nt], a[1], b0, b1);
            }
        }

        if (t + 1 < te)                                  // overlap staging with epilogue
            k1_stage(x, (t + 1) * 128, sm, ((t - ts) & 1) ? O1X0 : O1X1, tid);

        char* qx = sm + O1Q;
        char* ex = sm + O1E;
        #pragma unroll
        for (int mt = 0; mt < 2; mt++)
            #pragma unroll
            for (int nt = 0; nt < 8; nt++) {
                int col = n0 + nt * 8 + t2;
                int r1 = m0 + mt * 16 + g, r2 = r1 + 8;
                float bi0 = isq ? sbq[col] : sbk[col - 128];
                float bi1 = isq ? sbq[col + 1] : sbk[col - 127];
                float e00 = __expf(c[mt][nt][0] + bi0), e01 = __expf(c[mt][nt][1] + bi1);
                float e10 = __expf(c[mt][nt][2] + bi0), e11 = __expf(c[mt][nt][3] + bi1);
                if (isq) {
                    *(u32*)(qx + r1 * 272 + col * 2) = pbf2(e01, e00);
                    *(u32*)(qx + r2 * 272 + col * 2) = pbf2(e11, e10);
                } else {
                    int cl = col - 128;
                    bool a1 = (row0 + r1) < NROWS, a2 = (row0 + r2) < NROWS;
                    *(u32*)(ex + r1 * 272 + cl * 2) = a1 ? pbf2(e01, e00) : 0u;
                    *(u32*)(ex + r2 * 272 + cl * 2) = a2 ? pbf2(e11, e10) : 0u;
                }
            }
        __syncthreads();
        if (tid < 128) {                                 // q row sums
            const u32* qp = (const u32*)(qx + tid * 272);
            float s = 0.f;
            #pragma unroll 16
            for (int w = 0; w < 64; w++) { u32 v = qp[w]; s += bflo(v) + bfhi(v); }
            sinv[tid] = 1.f / s;
        } else if (tid < 256) {                          // ek column sums -> scol
            int cc = tid - 128;
            const u16* ep = (const u16*)ex;
            float s = 0.f;
            #pragma unroll 8
            for (int r = 0; r < 128; r++) s += __uint_as_float((u32)ep[r * 136 + cc] << 16);
            scol[cc] += s;
        }
        __syncthreads();
        #pragma unroll
        for (int i = 0; i < 16; i++) {                   // plane writes
            int idx = tid + 512 * i, r = idx >> 6, w = idx & 63;
            if (row0 + r < NROWS) {
                float iv = sinv[r];
                u32 qv = *(const u32*)(qx + r * 272 + w * 4);
                g_qh[(size_t)(row0 + r) * 64 + w] = pbf2(bfhi(qv) * iv, bflo(qv) * iv);
                g_eh[(size_t)(row0 + r) * 64 + w] = *(const u32*)(ex + r * 272 + w * 4);
            }
        }
        __syncthreads();
    }
    if (tid < 128) g_Zpart[blockIdx.x * 128 + tid] = scol[tid];
}

// ---------------- K2: kvU = ek^T @ x, kqU = ek^T @ q (double-buffered) ---------
#define TS2 17408
#define BUF2 (3 * TS2)
#define SMEM2 (1024 + 2 * BUF2)         // 105472
__global__ __launch_bounds__(512, 1) void k2b() {
    extern __shared__ __align__(16) char sm[];
    const int tid = threadIdx.x, lane = tid & 31, wid = tid >> 5;
    u32 sb = smem_u32(sm);
    const int per = (NROWS + 295) / 296;
    int start = blockIdx.x * per;
    int end = start + per; if (end > NROWS) end = NROWS;
    int nch = (end - start + 63) / 64;

    const int d0 = (wid >> 2) * 32, cw = wid & 3;
    const bool isx = cw < 2;
    const int c0 = (cw & 1) * 64;
    float c[2][8][4];
    #pragma unroll
    for (int a = 0; a < 2; a++)
        #pragma unroll
        for (int b = 0; b < 8; b++)
            #pragma unroll
            for (int e = 0; e < 4; e++) c[a][b][e] = 0.f;

    const int tarow = (lane & 7) + ((lane >> 4) & 1) * 8, tacol = ((lane >> 3) & 1) * 8;
    const int tbrow = (lane & 7) + ((lane >> 3) & 1) * 8;

    auto stage = [&](int ci, int bi) {
        u32 base = sb + 1024 + bi * BUF2;
        int n0 = start + ci * 64;
        #pragma unroll
        for (int i = 0; i < 6; i++) {
            int idx = tid + 512 * i;
            int t = idx >> 10, rr = (idx >> 4) & 63, ch = idx & 15;
            const u32* src = (t == 0) ? g_eh : ((t == 1) ? g_xh : g_qh);
            int pb = (n0 + rr < end) ? 16 : 0;
            CPA(base + (u32)(t * TS2 + rr * 272 + ch * 16),
                (const char*)(src + (size_t)(n0 + rr) * 64) + ch * 16, pb);
        }
        CPCOMMIT();
    };

    stage(0, 0);
    for (int ci = 0; ci < nch; ci++) {
        if (ci + 1 < nch) { stage(ci + 1, (ci + 1) & 1); CPWAIT1(); }
        else               CPWAIT0();
        __syncthreads();
        u32 base = sb + 1024 + (ci & 1) * BUF2;
        u32 bA = base;
        u32 bB = base + (isx ? TS2 : 2 * TS2);
        #pragma unroll
        for (int s = 0; s < 4; s++) {
            int k0 = s * 16;
            u32 a[2][4];
            #pragma unroll
            for (int mt = 0; mt < 2; mt++)
                LDSM4T(a[mt], bA + (u32)((k0 + tarow) * S + d0 + 16 * mt + tacol) * 2);
            #pragma unroll
            for (int nt = 0; nt < 8; nt++) {
                u32 b0, b1;
                LDSM2T(b0, b1, bB + (u32)((k0 + tbrow) * S + c0 + 8 * nt) * 2);
                MMA(c[0][nt], a[0], b0, b1);
                MMA(c[1][nt], a[1], b0, b1);
            }
        }
        __syncthreads();
    }
    float* dst = isx ? g_kvU : g_kqU;
    const int g = lane >> 2, t2 = (lane & 3) * 2;
    #pragma unroll
    for (int mt = 0; mt < 2; mt++)
        #pragma unroll
        for (int nt = 0; nt < 8; nt++) {
            int col = c0 + 8 * nt + t2;
            int r1 = d0 + 16 * mt + g, r2 = r1 + 8;
            atomicAdd(&dst[r1 * D + col],     c[mt][nt][0]);
            atomicAdd(&dst[r1 * D + col + 1], c[mt][nt][1]);
            atomicAdd(&dst[r2 * D + col],     c[mt][nt][2]);
            atomicAdd(&dst[r2 * D + col + 1], c[mt][nt][3]);
        }
}

// ---------------- chain (Paterson-Stockmeyer, 6 matmuls) -----------------------
// M = kv * P(A),  P = C0 + B(C1 + B(C2 + B(C3 + B*C4))),  B = A^2,
// Ca = temp[2a+1]*I + temp[2a+2]*A.
#define PKV 3072
#define PA  (PKV + 34816)
#define PB  (PA + 34816)
#define PX0 (PB + 34816)
#define PX1 (PX0 + 34816)
#define SMEMC (PX1 + 34816)             // 177152
#define PMF PA                          // fp32 M overlay (A,B dead after P formed)
__device__ __forceinline__ void ps_mm(u32 aoff, u32 boff,
        int m0, int n0, int arow, int acol, int tbrow, float c[2][4][4]) {
    #pragma unroll
    for (int a = 0; a < 2; a++)
        #pragma unroll
        for (int b = 0; b < 4; b++)
            #pragma unroll
            for (int e = 0; e < 4; e++) c[a][b][e] = 0.f;
    #pragma unroll
    for (int s8 = 0; s8 < 8; s8++) {
        int k0 = s8 * 16;
        u32 a[2][4];
        #pragma unroll
        for (int mt = 0; mt < 2; mt++)
            LDSM4(a[mt], aoff + (u32)((m0 + 16 * mt + arow) * S + k0 + acol) * 2);
        #pragma unroll
        for (int nt = 0; nt < 4; nt++) {
            u32 b0, b1;
            LDSM2T(b0, b1, boff + (u32)((k0 + tbrow) * S + n0 + 8 * nt) * 2);
            MMA(c[0][nt], a[0], b0, b1);
            MMA(c[1][nt], a[1], b0, b1);
        }
    }
}
__global__ __launch_bounds__(512, 1) void chainp(const float* __restrict__ temp) {
    extern __shared__ __align__(16) char sm[];
    const int tid = threadIdx.x, lane = tid & 31, wid = tid >> 5;
    u32 sb = smem_u32(sm);
    float* izv   = (float*)(sm);
    float* tmp   = (float*)(sm + 512);
    float* spart = (float*)(sm + 640);
    {
        int cc = tid & 127, p = tid >> 7;
        float s = 0.f;
        for (int b = p; b < 148; b += 4) s += g_Zpart[b * 128 + cc];
        spart[p * 128 + cc] = s;
    }
    if (tid < KPOW + 1) tmp[tid] = temp[tid];
    __syncthreads();
    if (tid < 128)
        izv[tid] = 1.f / (spart[tid] + spart[128 + tid] + spart[256 + tid] + spart[384 + tid]);
    __syncthreads();
    #pragma unroll
    for (int i = 0; i < 16; i++) {                      // kq->A, kv->KV bf16 tiles
        int idx = tid + 512 * i, r = idx >> 6, n2 = idx & 63;
        float iv = izv[r];
        float2 vq = *(const float2*)(g_kqU + r * D + n2 * 2);
        *(u32*)(sm + PA + r * 272 + n2 * 4) = pbf2(vq.y * iv, vq.x * iv);
        float2 vv = *(const float2*)(g_kvU + r * D + n2 * 2);
        *(u32*)(sm + PKV + r * 272 + n2 * 4) = pbf2(vv.y * iv, vv.x * iv);
    }
    __syncthreads();

    const int m0 = (wid >> 2) * 32, n0 = (wid & 3) * 32;
    const int arow = (lane & 7) + ((lane >> 3) & 1) * 8, acol = ((lane >> 4) & 1) * 8;
    const int tbrow = (lane & 7) + ((lane >> 3) & 1) * 8;
    const int g = lane >> 2, t2 = (lane & 3) * 2;
    float c[2][4][4];

    // B = A*A
    ps_mm(sb + PA, sb + PA, m0, n0, arow, acol, tbrow, c);
    #pragma unroll
    for (int mt = 0; mt < 2; mt++)
        #pragma unroll
        for (int nt = 0; nt < 4; nt++) {
            int col = n0 + nt * 8 + t2;
            int r1 = m0 + mt * 16 + g, r2 = r1 + 8;
            *(u32*)(sm + PB + r1 * 272 + col * 2) = pbf2(c[mt][nt][1], c[mt][nt][0]);
            *(u32*)(sm + PB + r2 * 272 + col * 2) = pbf2(c[mt][nt][3], c[mt][nt][2]);
        }
    // X0 = C4 = tmp[9]*I + tmp[10]*A   (elementwise; reads A only)
    {
        float t9 = tmp[9], t10 = tmp[10];
        #pragma unroll
        for (int i = 0; i < 16; i++) {
            int idx = tid + 512 * i, r = idx >> 6, n2 = idx & 63;
            u32 av = *(const u32*)(sm + PA + r * 272 + n2 * 4);
            float lo = t10 * bflo(av), hi = t10 * bfhi(av);
            if (r == 2 * n2)     lo += t9;
            if (r == 2 * n2 + 1) hi += t9;
            *(u32*)(sm + PX0 + r * 272 + n2 * 4) = pbf2(hi, lo);
        }
    }
    __syncthreads();

    // Horner: for a=3..0: X' = Ca + B*X
    int cur = 0;
    #pragma unroll
    for (int a = 3; a >= 0; a--) {
        u32 xoff = cur ? PX1 : PX0, noff = cur ? PX0 : PX1;
        ps_mm(sb + PB, sb + xoff, m0, n0, arow, acol, tbrow, c);
        float t1 = tmp[2 * a + 1], t2c = tmp[2 * a + 2];
        #pragma unroll
        for (int mt = 0; mt < 2; mt++)
            #pragma unroll
            for (int nt = 0; nt < 4; nt++) {
                int col = n0 + nt * 8 + t2;
                int r1 = m0 + mt * 16 + g, r2 = r1 + 8;
                u32 a1 = *(const u32*)(sm + PA + r1 * 272 + col * 2);
                u32 a2 = *(const u32*)(sm + PA + r2 * 272 + col * 2);
                float v0 = c[mt][nt][0] + t2c * bflo(a1);
                float v1 = c[mt][nt][1] + t2c * bfhi(a1);
                float v2 = c[mt][nt][2] + t2c * bflo(a2);
                float v3 = c[mt][nt][3] + t2c * bfhi(a2);
                if (r1 == col)     v0 += t1;
                if (r1 == col + 1) v1 += t1;
                if (r2 == col)     v2 += t1;
                if (r2 == col + 1) v3 += t1;
                *(u32*)(sm + noff + r1 * 272 + col * 2) = pbf2(v1, v0);
                *(u32*)(sm + noff + r2 * 272 + col * 2) = pbf2(v3, v2);
            }
        __syncthreads();
        cur ^= 1;
    }

    // M = KV * P  (P in PX0/PX1 per cur)
    ps_mm(sb + PKV, sb + (cur ? PX1 : PX0), m0, n0, arow, acol, tbrow, c);
    float* Mf = (float*)(sm + PMF);                     // overlay A+B (dead)
    #pragma unroll
    for (int mt = 0; mt < 2; mt++)
        #pragma unroll
        for (int nt = 0; nt < 4; nt++) {
            int col = n0 + nt * 8 + t2;
            int r1 = m0 + mt * 16 + g, r2 = r1 + 8;
            Mf[r1 * 128 + col] = c[mt][nt][0];  Mf[r1 * 128 + col + 1] = c[mt][nt][1];
            Mf[r2 * 128 + col] = c[mt][nt][2];  Mf[r2 * 128 + col + 1] = c[mt][nt][3];
        }
    __syncthreads();
    #pragma unroll
    for (int i = 0; i < 16; i++) {                      // g_mh[n][k] = bf16(M[k][n])
        int idx = tid + 512 * i, n = idx & 127, kk = idx >> 7;
        g_mh[n * 64 + kk] = pbf2(Mf[(2 * kk + 1) * 128 + n], Mf[2 * kk * 128 + n]);
    }
}

// ---------------- K4 (persistent): out = temp[0]*x + q @ M, direct epilogue ----
#define O4M  1024
#define O4Q0 (O4M + 34816)
#define O4Q1 (O4Q0 + 34816)
#define SMEM4 (O4Q1 + 34816)            // 105472
__global__ __launch_bounds__(512, 1) void k4c(const float* __restrict__ x,
        const float* __restrict__ temp, float* __restrict__ out) {
    extern __shared__ __align__(16) char sm[];
    const int tid = threadIdx.x, lane = tid & 31, wid = tid >> 5;
    u32 sb = smem_u32(sm);
    const int ts = (NTILES * blockIdx.x) / 148;
    const int te = (NTILES * (blockIdx.x + 1)) / 148;
    const float t0 = temp[0];

    auto stage_q = [&](int t, u32 off) {
        int row0 = t * 128;
        #pragma unroll
        for (int i = 0; i < 4; i++) {
            int idx = tid + 512 * i, r = idx >> 4, ch = idx & 15;
            int pb = (row0 + r < NROWS) ? 16 : 0;
            CPA(sb + off + (u32)(r * 272 + ch * 16),
                (const char*)(g_qh + (size_t)(row0 + r) * 64) + ch * 16, pb);
        }
    };

    #pragma unroll
    for (int i = 0; i < 4; i++) {                       // M plane (once per block)
        int idx = tid + 512 * i, r = idx >> 4, ch = idx & 15;
        CPA(sb + O4M + (u32)(r * 272 + ch * 16), (const char*)g_mh + r * 256 + ch * 16, 16);
    }
    stage_q(ts, O4Q0);
    CPCOMMIT();

    const int m0 = (wid >> 2) * 32, n0 = (wid & 3) * 32;
    const int arow = (lane & 7) + ((lane >> 3) & 1) * 8, acol = ((lane >> 4) & 1) * 8;
    const int brow = lane & 7,                           bcol = ((lane >> 3) & 1) * 8;
    const int g = lane >> 2, t2 = (lane & 3) * 2;

    for (int t = ts; t < te; t++) {
        const int row0 = t * 128;
        const u32 qb = sb + (((t - ts) & 1) ? O4Q1 : O4Q0);
        if (t + 1 < te) { stage_q(t + 1, ((t - ts) & 1) ? O4Q0 : O4Q1); CPCOMMIT(); CPWAIT1(); }
        else            CPWAIT0();
        __syncthreads();

        float c[2][4][4];
        #pragma unroll
        for (int a = 0; a < 2; a++)
            #pragma unroll
            for (int b = 0; b < 4; b++)
                #pragma unroll
                for (int e = 0; e < 4; e++) c[a][b][e] = 0.f;

        #pragma unroll
        for (int s = 0; s < 8; s++) {
            int k0 = s * 16;
            u32 a[2][4];
            #pragma unroll
            for (int mt = 0; mt < 2; mt++)
                LDSM4(a[mt], qb + (u32)((m0 + 16 * mt + arow) * S + k0 + acol) * 2);
            #pragma unroll
            for (int nt = 0; nt < 4; nt++) {
                u32 b0, b1;
                LDSM2(b0, b1, sb + O4M + (u32)((n0 + 8 * nt + brow) * S + k0 + bcol) * 2);
                MMA(c[0][nt], a[0], b0, b1);
                MMA(c[1][nt], a[1], b0, b1);
            }
        }
        // direct epilogue: out = t0*x + frag (32B row-segments = full sectors)
        #pragma unroll
        for (int mt = 0; mt < 2; mt++)
            #pragma unroll
            for (int nt = 0; nt < 4; nt++) {
                int col = n0 + nt * 8 + t2;
                int r1 = m0 + mt * 16 + g, r2 = r1 + 8;
                if (row0 + r1 < NROWS) {
                    size_t o = (size_t)(row0 + r1) * D + col;
                    float2 xv = *(const float2*)(x + o);
                    *(float2*)(out + o) = make_float2(fmaf(t0, xv.x, c[mt][nt][0]),
                                                      fmaf(t0, xv.y, c[mt][nt][1]));
                }
                if (row0 + r2 < NROWS) {
                    size_t o = (size_t)(row0 + r2) * D + col;
                    float2 xv = *(const float2*)(x + o);
                    *(float2*)(out + o) = make_float2(fmaf(t0, xv.x, c[mt][nt][2]),
                                                      fmaf(t0, xv.y, c[mt][nt][3]));
                }
            }
        __syncthreads();                                 // protect qb before restage
    }
}

// ---------------- launch -------------------------------------------------------
extern "C" void kernel_launch(void* const* d_in, const int* in_sizes, int n_in,
                              void* d_out, int out_size) {
    const float* x    = (const float*)d_in[0];
    const float* Wq   = (const float*)d_in[1];
    const float* bq   = (const float*)d_in[2];
    const float* Wk   = (const float*)d_in[3];
    const float* bk   = (const float*)d_in[4];
    const float* temp = (const float*)d_in[5];
    float* out = (float*)d_out;

    cudaFuncSetAttribute(k1c,    cudaFuncAttributeMaxDynamicSharedMemorySize, SMEM1);
    cudaFuncSetAttribute(k2b,    cudaFuncAttributeMaxDynamicSharedMemorySize, SMEM2);
    cudaFuncSetAttribute(chainp, cudaFuncAttributeMaxDynamicSharedMemorySize, SMEMC);
    cudaFuncSetAttribute(k4c,    cudaFuncAttributeMaxDynamicSharedMemorySize, SMEM4);

    k1c<<<148, 512, SMEM1>>>(x, Wq, bq, Wk, bk);
    k2b<<<296, 512, SMEM2>>>();
    chainp<<<1, 512, SMEMC>>>(temp);
    k4c<<<148, 512, SMEM4>>>(x, temp, out);
}